// round 5
// baseline (speedup 1.0000x reference)
#include <cuda_runtime.h>
#include <cuda_bf16.h>
#include <cstdint>
#include <cstddef>

#define NSRC 4096
#define NTGT 4096
#define DIM  1024

// ---------------- scratch (__device__ globals; no allocations allowed) -----
__device__ float g_sp[(size_t)NSRC * DIM];
__device__ float g_tp[(size_t)NTGT * DIM];
__device__ float g_sqs[NSRC];
__device__ float g_sqt[NTGT];
__device__ float g_rowsum[NSRC];

__device__ __nv_bfloat16 g_srch[(size_t)NSRC * DIM], g_srcl[(size_t)NSRC * DIM];
__device__ __nv_bfloat16 g_tgth[(size_t)NTGT * DIM], g_tgtl[(size_t)NTGT * DIM];
__device__ __nv_bfloat16 g_Wsh[(size_t)DIM * DIM],   g_Wsl[(size_t)DIM * DIM];
__device__ __nv_bfloat16 g_Wth[(size_t)DIM * DIM],   g_Wtl[(size_t)DIM * DIM];
__device__ __nv_bfloat16 g_sph[(size_t)NSRC * DIM],  g_spl[(size_t)NSRC * DIM];
__device__ __nv_bfloat16 g_tph[(size_t)NTGT * DIM],  g_tpl[(size_t)NTGT * DIM];
__device__ __nv_bfloat16 g_tTh[(size_t)DIM * NTGT],  g_tTl[(size_t)DIM * NTGT];
__device__ __nv_bfloat16 g_Kh[(size_t)NSRC * NTGT],  g_Kl[(size_t)NSRC * NTGT];

// ---------------- helpers ----------------------------------------------------
__device__ __forceinline__ uint32_t smem_to_u32(const void* p) {
    uint32_t a;
    asm("{ .reg .u64 t; cvta.to.shared.u64 t, %1; cvt.u32.u64 %0, t; }" : "=r"(a) : "l"(p));
    return a;
}
__device__ __forceinline__ void cp_async16(uint32_t dst, const void* src) {
    asm volatile("cp.async.cg.shared.global [%0], [%1], 16;" :: "r"(dst), "l"(src) : "memory");
}
__device__ __forceinline__ void ldm4(uint32_t* r, uint32_t addr) {
    asm volatile("ldmatrix.sync.aligned.m8n8.x4.shared.b16 {%0,%1,%2,%3}, [%4];"
                 : "=r"(r[0]), "=r"(r[1]), "=r"(r[2]), "=r"(r[3]) : "r"(addr));
}
__device__ __forceinline__ void mma_bf16(float* c, const uint32_t* a, const uint32_t* b) {
    asm volatile(
        "mma.sync.aligned.m16n8k16.row.col.f32.bf16.bf16.f32 "
        "{%0,%1,%2,%3}, {%4,%5,%6,%7}, {%8,%9}, {%0,%1,%2,%3};"
        : "+f"(c[0]), "+f"(c[1]), "+f"(c[2]), "+f"(c[3])
        : "r"(a[0]), "r"(a[1]), "r"(a[2]), "r"(a[3]), "r"(b[0]), "r"(b[1]));
}
__device__ __forceinline__ void f32_split(float x, unsigned short& h, unsigned short& l) {
    __nv_bfloat16 bh = __float2bfloat16(x);
    float r = x - __bfloat162float(bh);
    __nv_bfloat16 bl = __float2bfloat16(r);
    h = __bfloat16_as_ushort(bh);
    l = __bfloat16_as_ushort(bl);
}

// ---------------- warp-MMA split-bf16 NT GEMM -------------------------------
// C[r,c] = sum_k A[r,k]*B[c,k]; bf16 hi/lo operands, 3 passes (hh+hl+lh).
// CTA 128x128, 4 warps (2x2), warp tile 64x64, BK=32, double-buffered cp.async,
// fragment loads via ldmatrix.x4.
#define EPI_NONE 0
#define EPI_BIAS 1
#define EPI_COST 2

#define BK 32
#define ROW_BYTES 80                        // 32 halves (64B) + 16B pad
enum { TILE_BYTES = 128 * ROW_BYTES,        // 10240
       BUF_BYTES  = 4 * TILE_BYTES,         // Ah,Al,Bh,Bl
       SMEM_DYN   = 2 * BUF_BYTES };        // 81920

template <int EPI>
__global__ void __launch_bounds__(128, 2) tc_gemm(
    const __nv_bfloat16* __restrict__ Ah, const __nv_bfloat16* __restrict__ Al,
    const __nv_bfloat16* __restrict__ Bh, const __nv_bfloat16* __restrict__ Bl,
    const float* __restrict__ bias,
    const float* __restrict__ sqa, const float* __restrict__ sqb,
    const float* __restrict__ temp,
    float* __restrict__ C,
    __nv_bfloat16* __restrict__ Chb, __nv_bfloat16* __restrict__ Clb,
    int N, int Kdim)
{
    extern __shared__ char dsm[];
    const uint32_t sm0 = smem_to_u32(dsm);
    const int tid = threadIdx.x;
    const int wid = tid >> 5, lane = tid & 31;
    const int warpRow = wid & 1;            // 2 row-warps (64 rows each)
    const int warpCol = wid >> 1;           // 2 col-warps (64 cols each)
    const int g  = lane >> 2;
    const int qp = lane & 3;
    const int rowBase = blockIdx.y * 128;
    const int colBase = blockIdx.x * 128;

    // ldmatrix lane->address offsets
    // A x4: m0 rows0-7 klo, m1 rows8-15 klo, m2 rows0-7 khi, m3 rows8-15 khi
    const uint32_t offA = (uint32_t)((warpRow * 64 + (lane & 7) + ((lane >> 3) & 1) * 8) * ROW_BYTES
                                     + ((lane >> 4) & 1) * 16);
    // B x4 (pair of nf): m0 nf rows klo, m1 nf khi, m2 nf+1 klo, m3 nf+1 khi
    const uint32_t offB = (uint32_t)(((lane & 7) + ((lane >> 4) & 1) * 8) * ROW_BYTES
                                     + ((lane >> 3) & 1) * 16);

    const __nv_bfloat16* basep[4] = {
        Ah + (size_t)rowBase * Kdim, Al + (size_t)rowBase * Kdim,
        Bh + (size_t)colBase * Kdim, Bl + (size_t)colBase * Kdim };

    float acc[4][8][4];
#pragma unroll
    for (int mf = 0; mf < 4; mf++)
#pragma unroll
        for (int nf = 0; nf < 8; nf++)
#pragma unroll
            for (int e = 0; e < 4; e++) acc[mf][nf][e] = 0.f;

    const int KC = Kdim / BK;

    auto issue = [&](int ch, int buf) {
        uint32_t sbase = sm0 + (uint32_t)buf * BUF_BYTES;
        int kt = ch * BK;
#pragma unroll
        for (int j = 0; j < 16; j++) {
            int id  = j * 128 + tid;          // 0..2047
            int t   = id >> 9;                // tile 0..3
            int c   = id & 511;
            int row = c >> 2;
            int seg = c & 3;
            const void* src = basep[t] + (size_t)row * Kdim + kt + seg * 8;
            uint32_t dst = sbase + (uint32_t)t * TILE_BYTES + row * ROW_BYTES + seg * 16;
            cp_async16(dst, src);
        }
        asm volatile("cp.async.commit_group;" ::: "memory");
    };

    issue(0, 0);
#pragma unroll 1
    for (int ch = 0; ch < KC; ch++) {
        int buf = ch & 1;
        if (ch + 1 < KC) {
            issue(ch + 1, buf ^ 1);
            asm volatile("cp.async.wait_group 1;" ::: "memory");
        } else {
            asm volatile("cp.async.wait_group 0;" ::: "memory");
        }
        __syncthreads();

        uint32_t sb = sm0 + (uint32_t)buf * BUF_BYTES;
#pragma unroll
        for (int ks = 0; ks < 2; ks++) {
            const uint32_t kof = (uint32_t)(ks * 32);
            // B fragments: all 8 nf, hi+lo (4 ldmatrix.x4 each)
            uint32_t bh[8][2], bl[8][2];
#pragma unroll
            for (int p = 0; p < 4; p++) {
                uint32_t nboff = (uint32_t)((warpCol * 64 + p * 16) * ROW_BYTES);
                uint32_t rh[4], rl[4];
                ldm4(rh, sb + 2u * TILE_BYTES + nboff + offB + kof);
                ldm4(rl, sb + 3u * TILE_BYTES + nboff + offB + kof);
                bh[p * 2][0] = rh[0]; bh[p * 2][1] = rh[1];
                bh[p * 2 + 1][0] = rh[2]; bh[p * 2 + 1][1] = rh[3];
                bl[p * 2][0] = rl[0]; bl[p * 2][1] = rl[1];
                bl[p * 2 + 1][0] = rl[2]; bl[p * 2 + 1][1] = rl[3];
            }
#pragma unroll
            for (int mf = 0; mf < 4; mf++) {
                uint32_t mof = (uint32_t)(mf * 16 * ROW_BYTES);
                uint32_t ah[4], al[4];
                ldm4(ah, sb + mof + offA + kof);
                ldm4(al, sb + TILE_BYTES + mof + offA + kof);
#pragma unroll
                for (int nf = 0; nf < 8; nf++) {
                    mma_bf16(acc[mf][nf], ah, bh[nf]);   // hh
                    mma_bf16(acc[mf][nf], ah, bl[nf]);   // hl
                    mma_bf16(acc[mf][nf], al, bh[nf]);   // lh
                }
            }
        }
        __syncthreads();
    }

    // ---- epilogue -----------------------------------------------------------
    const float invT = (EPI == EPI_COST) ? (1.0f / temp[0]) : 0.f;
#pragma unroll
    for (int mf = 0; mf < 4; mf++) {
        int r0 = rowBase + warpRow * 64 + mf * 16 + g;
#pragma unroll
        for (int half = 0; half < 2; half++) {
            int r = r0 + half * 8;
            float sa = (EPI == EPI_COST) ? sqa[r] : 0.f;
#pragma unroll
            for (int nf = 0; nf < 8; nf++) {
                int c0 = colBase + warpCol * 64 + nf * 8 + qp * 2;
                float v0 = acc[mf][nf][half * 2 + 0];
                float v1 = acc[mf][nf][half * 2 + 1];
                if (EPI == EPI_COST) {
                    float d20 = sa + sqb[c0 + 0] - 2.0f * v0;
                    float d21 = sa + sqb[c0 + 1] - 2.0f * v1;
                    v0 = __expf(-sqrtf(fmaxf(d20, 0.0f)) * invT);
                    v1 = __expf(-sqrtf(fmaxf(d21, 0.0f)) * invT);
                } else if (EPI == EPI_BIAS) {
                    v0 += bias[c0 + 0];
                    v1 += bias[c0 + 1];
                }
                *(float2*)(C + (size_t)r * N + c0) = make_float2(v0, v1);
                if (EPI == EPI_BIAS) {
                    unsigned short h0, h1, l0, l1;
                    f32_split(v0, h0, l0);
                    f32_split(v1, h1, l1);
                    *(uint32_t*)(Chb + (size_t)r * N + c0) =
                        (uint32_t)h0 | ((uint32_t)h1 << 16);
                    *(uint32_t*)(Clb + (size_t)r * N + c0) =
                        (uint32_t)l0 | ((uint32_t)l1 << 16);
                }
            }
        }
    }
}

// ---------------- small kernels ---------------------------------------------
__global__ __launch_bounds__(256) void split_kernel(
    const float* __restrict__ in, __nv_bfloat16* __restrict__ oh,
    __nv_bfloat16* __restrict__ ol, size_t n4)
{
    size_t i = (size_t)blockIdx.x * 256 + threadIdx.x;
    if (i >= n4) return;
    float4 v = ((const float4*)in)[i];
    unsigned short h0, h1, h2, h3, l0, l1, l2, l3;
    f32_split(v.x, h0, l0); f32_split(v.y, h1, l1);
    f32_split(v.z, h2, l2); f32_split(v.w, h3, l3);
    ((uint2*)oh)[i] = make_uint2((uint32_t)h0 | ((uint32_t)h1 << 16),
                                 (uint32_t)h2 | ((uint32_t)h3 << 16));
    ((uint2*)ol)[i] = make_uint2((uint32_t)l0 | ((uint32_t)l1 << 16),
                                 (uint32_t)l2 | ((uint32_t)l3 << 16));
}

// target [NTGT][DIM] fp32 -> hi/lo bf16 [DIM][NTGT]
__global__ void transpose_split(const float* __restrict__ in,
                                __nv_bfloat16* __restrict__ oh,
                                __nv_bfloat16* __restrict__ ol)
{
    __shared__ float t[32][33];
    int x  = blockIdx.x * 32 + threadIdx.x;
    int y0 = blockIdx.y * 32;
#pragma unroll
    for (int i = 0; i < 4; i++)
        t[threadIdx.y + i * 8][threadIdx.x] = in[(size_t)(y0 + threadIdx.y + i * 8) * DIM + x];
    __syncthreads();
    int ox  = y0 + threadIdx.x;
    int oy0 = blockIdx.x * 32;
#pragma unroll
    for (int i = 0; i < 4; i++) {
        float v = t[threadIdx.x][threadIdx.y + i * 8];
        unsigned short h, l;
        f32_split(v, h, l);
        size_t o = (size_t)(oy0 + threadIdx.y + i * 8) * NTGT + ox;
        oh[o] = __ushort_as_bfloat16(h);
        ol[o] = __ushort_as_bfloat16(l);
    }
}

template <bool SQ>
__global__ __launch_bounds__(256) void row_reduce(
    const float* __restrict__ X, float* __restrict__ out, int cols)
{
    const int row = blockIdx.x;
    const float4* p = reinterpret_cast<const float4*>(X + (size_t)row * cols);
    const int n4 = cols >> 2;
    float s = 0.f;
    for (int j = threadIdx.x; j < n4; j += 256) {
        float4 v = p[j];
        if (SQ) s += v.x * v.x + v.y * v.y + v.z * v.z + v.w * v.w;
        else    s += v.x + v.y + v.z + v.w;
    }
    __shared__ float red[256];
    red[threadIdx.x] = s;
    __syncthreads();
#pragma unroll
    for (int st = 128; st > 0; st >>= 1) {
        if (threadIdx.x < st) red[threadIdx.x] += red[threadIdx.x + st];
        __syncthreads();
    }
    if (threadIdx.x == 0) out[row] = red[0];
}

// normalize K rows in place (fp32) and emit bf16 hi/lo split of K
__global__ __launch_bounds__(256) void normalize_split(
    float* __restrict__ Kmat, const float* __restrict__ rowsum,
    __nv_bfloat16* __restrict__ Kh, __nv_bfloat16* __restrict__ Kl)
{
    size_t idx = (size_t)blockIdx.x * 256 + threadIdx.x;   // float4 index
    size_t total4 = ((size_t)NSRC * NTGT) >> 2;
    if (idx >= total4) return;
    int row = (int)(idx >> 10);                            // 1024 float4 per row
    float inv = 1.0f / rowsum[row];
    float4* p = (float4*)Kmat + idx;
    float4 v = *p;
    v.x *= inv; v.y *= inv; v.z *= inv; v.w *= inv;
    *p = v;
    unsigned short h0, h1, h2, h3, l0, l1, l2, l3;
    f32_split(v.x, h0, l0); f32_split(v.y, h1, l1);
    f32_split(v.z, h2, l2); f32_split(v.w, h3, l3);
    ((uint2*)Kh)[idx] = make_uint2((uint32_t)h0 | ((uint32_t)h1 << 16),
                                   (uint32_t)h2 | ((uint32_t)h3 << 16));
    ((uint2*)Kl)[idx] = make_uint2((uint32_t)l0 | ((uint32_t)l1 << 16),
                                   (uint32_t)l2 | ((uint32_t)l3 << 16));
}

// ---------------- launch -----------------------------------------------------
extern "C" void kernel_launch(void* const* d_in, const int* in_sizes, int n_in,
                              void* d_out, int out_size)
{
    const float* source = (const float*)d_in[0];
    const float* target = (const float*)d_in[1];
    const float* W_src  = (const float*)d_in[2];
    const float* b_src  = (const float*)d_in[3];
    const float* W_tgt  = (const float*)d_in[4];
    const float* b_tgt  = (const float*)d_in[5];
    const float* temp   = (const float*)d_in[6];

    float* aligned = (float*)d_out;                       // [NSRC, DIM]
    float* Kout    = (float*)d_out + (size_t)NSRC * DIM;  // [NSRC, NTGT]

    float *sp, *tp, *sqs, *sqt, *rs;
    __nv_bfloat16 *srch, *srcl, *tgth, *tgtl, *Wsh, *Wsl, *Wth, *Wtl;
    __nv_bfloat16 *sph, *spl, *tph, *tpl, *tTh, *tTl, *Kh, *Kl;
    cudaGetSymbolAddress((void**)&sp,  g_sp);
    cudaGetSymbolAddress((void**)&tp,  g_tp);
    cudaGetSymbolAddress((void**)&sqs, g_sqs);
    cudaGetSymbolAddress((void**)&sqt, g_sqt);
    cudaGetSymbolAddress((void**)&rs,  g_rowsum);
    cudaGetSymbolAddress((void**)&srch, g_srch); cudaGetSymbolAddress((void**)&srcl, g_srcl);
    cudaGetSymbolAddress((void**)&tgth, g_tgth); cudaGetSymbolAddress((void**)&tgtl, g_tgtl);
    cudaGetSymbolAddress((void**)&Wsh,  g_Wsh);  cudaGetSymbolAddress((void**)&Wsl,  g_Wsl);
    cudaGetSymbolAddress((void**)&Wth,  g_Wth);  cudaGetSymbolAddress((void**)&Wtl,  g_Wtl);
    cudaGetSymbolAddress((void**)&sph,  g_sph);  cudaGetSymbolAddress((void**)&spl,  g_spl);
    cudaGetSymbolAddress((void**)&tph,  g_tph);  cudaGetSymbolAddress((void**)&tpl,  g_tpl);
    cudaGetSymbolAddress((void**)&tTh,  g_tTh);  cudaGetSymbolAddress((void**)&tTl,  g_tTl);
    cudaGetSymbolAddress((void**)&Kh,   g_Kh);   cudaGetSymbolAddress((void**)&Kl,   g_Kl);

    cudaFuncSetAttribute(tc_gemm<EPI_BIAS>, cudaFuncAttributeMaxDynamicSharedMemorySize, SMEM_DYN);
    cudaFuncSetAttribute(tc_gemm<EPI_COST>, cudaFuncAttributeMaxDynamicSharedMemorySize, SMEM_DYN);
    cudaFuncSetAttribute(tc_gemm<EPI_NONE>, cudaFuncAttributeMaxDynamicSharedMemorySize, SMEM_DYN);

    // 1) split inputs to bf16 hi/lo
    split_kernel<<<(NSRC * DIM / 4 + 255) / 256, 256>>>(source, srch, srcl, (size_t)NSRC * DIM / 4);
    split_kernel<<<(NTGT * DIM / 4 + 255) / 256, 256>>>(target, tgth, tgtl, (size_t)NTGT * DIM / 4);
    split_kernel<<<(DIM * DIM / 4 + 255) / 256, 256>>>(W_src, Wsh, Wsl, (size_t)DIM * DIM / 4);
    split_kernel<<<(DIM * DIM / 4 + 255) / 256, 256>>>(W_tgt, Wth, Wtl, (size_t)DIM * DIM / 4);
    transpose_split<<<dim3(DIM / 32, NTGT / 32), dim3(32, 8)>>>(target, tTh, tTl);

    // 2) projections (emit fp32 result + bf16 hi/lo split)
    tc_gemm<EPI_BIAS><<<dim3(DIM / 128, NSRC / 128), 128, SMEM_DYN>>>(
        srch, srcl, Wsh, Wsl, b_src, nullptr, nullptr, nullptr, sp, sph, spl, DIM, DIM);
    tc_gemm<EPI_BIAS><<<dim3(DIM / 128, NTGT / 128), 128, SMEM_DYN>>>(
        tgth, tgtl, Wth, Wtl, b_tgt, nullptr, nullptr, nullptr, tp, tph, tpl, DIM, DIM);

    // 3) squared norms
    row_reduce<true><<<NSRC, 256>>>(sp, sqs, DIM);
    row_reduce<true><<<NTGT, 256>>>(tp, sqt, DIM);

    // 4) K (unnormalized) = exp(-cdist/T), fused epilogue
    tc_gemm<EPI_COST><<<dim3(NTGT / 128, NSRC / 128), 128, SMEM_DYN>>>(
        sph, spl, tph, tpl, nullptr, sqs, sqt, temp, Kout, nullptr, nullptr, NTGT, DIM);

    // 5) row sums + normalize (+ bf16 split of K)
    row_reduce<false><<<NSRC, 256>>>(Kout, rs, NTGT);
    normalize_split<<<(int)(((size_t)NSRC * NTGT / 4 + 255) / 256), 256>>>(Kout, rs, Kh, Kl);

    // 6) aligned = K @ target (NT with pre-split target^T)
    tc_gemm<EPI_NONE><<<dim3(DIM / 128, NSRC / 128), 128, SMEM_DYN>>>(
        Kh, Kl, tTh, tTl, nullptr, nullptr, nullptr, nullptr, aligned, nullptr, nullptr,
        DIM, NTGT);
}

// round 6
// speedup vs baseline: 1.4436x; 1.4436x over previous
#include <cuda_runtime.h>
#include <cuda_bf16.h>
#include <cstdint>
#include <cstddef>

#define NSRC 4096
#define NTGT 4096
#define DIM  1024

// ---------------- scratch (__device__ globals; no allocations allowed) -----
__device__ float g_sp[(size_t)NSRC * DIM];
__device__ float g_tp[(size_t)NTGT * DIM];
__device__ float g_sqs[NSRC];
__device__ float g_sqt[NTGT];
__device__ float g_rowsum[NSRC];

__device__ __nv_bfloat16 g_srch[(size_t)NSRC * DIM], g_srcl[(size_t)NSRC * DIM];
__device__ __nv_bfloat16 g_tgth[(size_t)NTGT * DIM], g_tgtl[(size_t)NTGT * DIM];
__device__ __nv_bfloat16 g_Wsh[(size_t)DIM * DIM],   g_Wsl[(size_t)DIM * DIM];
__device__ __nv_bfloat16 g_Wth[(size_t)DIM * DIM],   g_Wtl[(size_t)DIM * DIM];
__device__ __nv_bfloat16 g_sph[(size_t)NSRC * DIM],  g_spl[(size_t)NSRC * DIM];
__device__ __nv_bfloat16 g_tph[(size_t)NTGT * DIM],  g_tpl[(size_t)NTGT * DIM];
__device__ __nv_bfloat16 g_tTh[(size_t)DIM * NTGT],  g_tTl[(size_t)DIM * NTGT];
__device__ __nv_bfloat16 g_Kh[(size_t)NSRC * NTGT],  g_Kl[(size_t)NSRC * NTGT];

// ---------------- helpers ----------------------------------------------------
__device__ __forceinline__ uint32_t smem_to_u32(const void* p) {
    uint32_t a;
    asm("{ .reg .u64 t; cvta.to.shared.u64 t, %1; cvt.u32.u64 %0, t; }" : "=r"(a) : "l"(p));
    return a;
}
__device__ __forceinline__ void cp_async16(uint32_t dst, const void* src) {
    asm volatile("cp.async.cg.shared.global [%0], [%1], 16;" :: "r"(dst), "l"(src) : "memory");
}
__device__ __forceinline__ void ldm4(uint32_t* r, uint32_t addr) {
    asm volatile("ldmatrix.sync.aligned.m8n8.x4.shared.b16 {%0,%1,%2,%3}, [%4];"
                 : "=r"(r[0]), "=r"(r[1]), "=r"(r[2]), "=r"(r[3]) : "r"(addr));
}
__device__ __forceinline__ void mma_bf16(float* c, const uint32_t* a, const uint32_t* b) {
    asm volatile(
        "mma.sync.aligned.m16n8k16.row.col.f32.bf16.bf16.f32 "
        "{%0,%1,%2,%3}, {%4,%5,%6,%7}, {%8,%9}, {%0,%1,%2,%3};"
        : "+f"(c[0]), "+f"(c[1]), "+f"(c[2]), "+f"(c[3])
        : "r"(a[0]), "r"(a[1]), "r"(a[2]), "r"(a[3]), "r"(b[0]), "r"(b[1]));
}
__device__ __forceinline__ void f32_split(float x, unsigned short& h, unsigned short& l) {
    __nv_bfloat16 bh = __float2bfloat16(x);
    float r = x - __bfloat162float(bh);
    __nv_bfloat16 bl = __float2bfloat16(r);
    h = __bfloat16_as_ushort(bh);
    l = __bfloat16_as_ushort(bl);
}

// ---------------- warp-MMA split-bf16 NT GEMM -------------------------------
// C[r,c] = sum_k A[r,k]*B[c,k]; bf16 hi/lo operands, 3 passes (hh+hl+lh).
// CTA 128x128, 8 warps (2 row x 4 col), warp tile 64x32, BK=32,
// double-buffered cp.async, fragment loads via ldmatrix.x4.
#define EPI_NONE 0
#define EPI_BIAS 1
#define EPI_COST 2

#define BK 32
#define ROW_BYTES 80                        // 32 halves (64B) + 16B pad
enum { TILE_BYTES = 128 * ROW_BYTES,        // 10240
       BUF_BYTES  = 4 * TILE_BYTES,         // Ah,Al,Bh,Bl
       SMEM_DYN   = 2 * BUF_BYTES };        // 81920

template <int EPI>
__global__ void __launch_bounds__(256, 2) tc_gemm(
    const __nv_bfloat16* __restrict__ Ah, const __nv_bfloat16* __restrict__ Al,
    const __nv_bfloat16* __restrict__ Bh, const __nv_bfloat16* __restrict__ Bl,
    const float* __restrict__ bias,
    const float* __restrict__ sqa, const float* __restrict__ sqb,
    const float* __restrict__ temp,
    float* __restrict__ C,
    __nv_bfloat16* __restrict__ Chb, __nv_bfloat16* __restrict__ Clb,
    int N, int Kdim)
{
    extern __shared__ char dsm[];
    const uint32_t sm0 = smem_to_u32(dsm);
    const int tid = threadIdx.x;
    const int wid = tid >> 5, lane = tid & 31;
    const int warpRow = wid & 1;            // 2 row-warps (64 rows each)
    const int warpCol = wid >> 1;           // 4 col-warps (32 cols each)
    const int g  = lane >> 2;
    const int qp = lane & 3;
    const int rowBase = blockIdx.y * 128;
    const int colBase = blockIdx.x * 128;

    // ldmatrix lane->address offsets (same layouts validated in R5)
    // A x4: m0 rows0-7 klo, m1 rows8-15 klo, m2 rows0-7 khi, m3 rows8-15 khi
    const uint32_t offA = (uint32_t)((warpRow * 64 + (lane & 7) + ((lane >> 3) & 1) * 8) * ROW_BYTES
                                     + ((lane >> 4) & 1) * 16);
    // B x4 (pair of nf): m0 nf klo, m1 nf khi, m2 nf+1 klo, m3 nf+1 khi
    const uint32_t offB = (uint32_t)(((lane & 7) + ((lane >> 4) & 1) * 8) * ROW_BYTES
                                     + ((lane >> 3) & 1) * 16);

    const __nv_bfloat16* basep[4] = {
        Ah + (size_t)rowBase * Kdim, Al + (size_t)rowBase * Kdim,
        Bh + (size_t)colBase * Kdim, Bl + (size_t)colBase * Kdim };

    float acc[4][4][4];
#pragma unroll
    for (int mf = 0; mf < 4; mf++)
#pragma unroll
        for (int nf = 0; nf < 4; nf++)
#pragma unroll
            for (int e = 0; e < 4; e++) acc[mf][nf][e] = 0.f;

    const int KC = Kdim / BK;

    auto issue = [&](int ch, int buf) {
        uint32_t sbase = sm0 + (uint32_t)buf * BUF_BYTES;
        int kt = ch * BK;
#pragma unroll
        for (int j = 0; j < 8; j++) {
            int id  = j * 256 + tid;          // 0..2047
            int t   = id >> 9;                // tile 0..3
            int c   = id & 511;
            int row = c >> 2;
            int seg = c & 3;
            const void* src = basep[t] + (size_t)row * Kdim + kt + seg * 8;
            uint32_t dst = sbase + (uint32_t)t * TILE_BYTES + row * ROW_BYTES + seg * 16;
            cp_async16(dst, src);
        }
        asm volatile("cp.async.commit_group;" ::: "memory");
    };

    issue(0, 0);
#pragma unroll 1
    for (int ch = 0; ch < KC; ch++) {
        int buf = ch & 1;
        if (ch + 1 < KC) {
            issue(ch + 1, buf ^ 1);
            asm volatile("cp.async.wait_group 1;" ::: "memory");
        } else {
            asm volatile("cp.async.wait_group 0;" ::: "memory");
        }
        __syncthreads();

        uint32_t sb = sm0 + (uint32_t)buf * BUF_BYTES;
#pragma unroll
        for (int ks = 0; ks < 2; ks++) {
            const uint32_t kof = (uint32_t)(ks * 32);
            // B fragments: 4 nf, hi+lo (2 pairs x 2 = 4 ldmatrix.x4)
            uint32_t bh[4][2], bl[4][2];
#pragma unroll
            for (int p = 0; p < 2; p++) {
                uint32_t nboff = (uint32_t)((warpCol * 32 + p * 16) * ROW_BYTES);
                uint32_t rh[4], rl[4];
                ldm4(rh, sb + 2u * TILE_BYTES + nboff + offB + kof);
                ldm4(rl, sb + 3u * TILE_BYTES + nboff + offB + kof);
                bh[p * 2][0] = rh[0]; bh[p * 2][1] = rh[1];
                bh[p * 2 + 1][0] = rh[2]; bh[p * 2 + 1][1] = rh[3];
                bl[p * 2][0] = rl[0]; bl[p * 2][1] = rl[1];
                bl[p * 2 + 1][0] = rl[2]; bl[p * 2 + 1][1] = rl[3];
            }
#pragma unroll
            for (int mf = 0; mf < 4; mf++) {
                uint32_t mof = (uint32_t)(mf * 16 * ROW_BYTES);
                uint32_t ah[4], al[4];
                ldm4(ah, sb + mof + offA + kof);
                ldm4(al, sb + TILE_BYTES + mof + offA + kof);
#pragma unroll
                for (int nf = 0; nf < 4; nf++) {
                    mma_bf16(acc[mf][nf], ah, bh[nf]);   // hh
                    mma_bf16(acc[mf][nf], ah, bl[nf]);   // hl
                    mma_bf16(acc[mf][nf], al, bh[nf]);   // lh
                }
            }
        }
        __syncthreads();
    }

    // ---- epilogue -----------------------------------------------------------
    const float invT = (EPI == EPI_COST) ? (1.0f / temp[0]) : 0.f;
#pragma unroll
    for (int mf = 0; mf < 4; mf++) {
        int r0 = rowBase + warpRow * 64 + mf * 16 + g;
#pragma unroll
        for (int half = 0; half < 2; half++) {
            int r = r0 + half * 8;
            float sa = (EPI == EPI_COST) ? sqa[r] : 0.f;
#pragma unroll
            for (int nf = 0; nf < 4; nf++) {
                int c0 = colBase + warpCol * 32 + nf * 8 + qp * 2;
                float v0 = acc[mf][nf][half * 2 + 0];
                float v1 = acc[mf][nf][half * 2 + 1];
                if (EPI == EPI_COST) {
                    float d20 = sa + sqb[c0 + 0] - 2.0f * v0;
                    float d21 = sa + sqb[c0 + 1] - 2.0f * v1;
                    v0 = __expf(-sqrtf(fmaxf(d20, 0.0f)) * invT);
                    v1 = __expf(-sqrtf(fmaxf(d21, 0.0f)) * invT);
                } else if (EPI == EPI_BIAS) {
                    v0 += bias[c0 + 0];
                    v1 += bias[c0 + 1];
                }
                *(float2*)(C + (size_t)r * N + c0) = make_float2(v0, v1);
                if (EPI == EPI_BIAS) {
                    unsigned short h0, h1, l0, l1;
                    f32_split(v0, h0, l0);
                    f32_split(v1, h1, l1);
                    *(uint32_t*)(Chb + (size_t)r * N + c0) =
                        (uint32_t)h0 | ((uint32_t)h1 << 16);
                    *(uint32_t*)(Clb + (size_t)r * N + c0) =
                        (uint32_t)l0 | ((uint32_t)l1 << 16);
                }
            }
        }
    }
}

// ---------------- small kernels ---------------------------------------------
__global__ __launch_bounds__(256) void split_kernel(
    const float* __restrict__ in, __nv_bfloat16* __restrict__ oh,
    __nv_bfloat16* __restrict__ ol, size_t n4)
{
    size_t i = (size_t)blockIdx.x * 256 + threadIdx.x;
    if (i >= n4) return;
    float4 v = ((const float4*)in)[i];
    unsigned short h0, h1, h2, h3, l0, l1, l2, l3;
    f32_split(v.x, h0, l0); f32_split(v.y, h1, l1);
    f32_split(v.z, h2, l2); f32_split(v.w, h3, l3);
    ((uint2*)oh)[i] = make_uint2((uint32_t)h0 | ((uint32_t)h1 << 16),
                                 (uint32_t)h2 | ((uint32_t)h3 << 16));
    ((uint2*)ol)[i] = make_uint2((uint32_t)l0 | ((uint32_t)l1 << 16),
                                 (uint32_t)l2 | ((uint32_t)l3 << 16));
}

// target [NTGT][DIM] fp32 -> hi/lo bf16 [DIM][NTGT]
__global__ void transpose_split(const float* __restrict__ in,
                                __nv_bfloat16* __restrict__ oh,
                                __nv_bfloat16* __restrict__ ol)
{
    __shared__ float t[32][33];
    int x  = blockIdx.x * 32 + threadIdx.x;
    int y0 = blockIdx.y * 32;
#pragma unroll
    for (int i = 0; i < 4; i++)
        t[threadIdx.y + i * 8][threadIdx.x] = in[(size_t)(y0 + threadIdx.y + i * 8) * DIM + x];
    __syncthreads();
    int ox  = y0 + threadIdx.x;
    int oy0 = blockIdx.x * 32;
#pragma unroll
    for (int i = 0; i < 4; i++) {
        float v = t[threadIdx.x][threadIdx.y + i * 8];
        unsigned short h, l;
        f32_split(v, h, l);
        size_t o = (size_t)(oy0 + threadIdx.y + i * 8) * NTGT + ox;
        oh[o] = __ushort_as_bfloat16(h);
        ol[o] = __ushort_as_bfloat16(l);
    }
}

template <bool SQ>
__global__ __launch_bounds__(256) void row_reduce(
    const float* __restrict__ X, float* __restrict__ out, int cols)
{
    const int row = blockIdx.x;
    const float4* p = reinterpret_cast<const float4*>(X + (size_t)row * cols);
    const int n4 = cols >> 2;
    float s = 0.f;
    for (int j = threadIdx.x; j < n4; j += 256) {
        float4 v = p[j];
        if (SQ) s += v.x * v.x + v.y * v.y + v.z * v.z + v.w * v.w;
        else    s += v.x + v.y + v.z + v.w;
    }
    __shared__ float red[256];
    red[threadIdx.x] = s;
    __syncthreads();
#pragma unroll
    for (int st = 128; st > 0; st >>= 1) {
        if (threadIdx.x < st) red[threadIdx.x] += red[threadIdx.x + st];
        __syncthreads();
    }
    if (threadIdx.x == 0) out[row] = red[0];
}

// normalize K rows in place (fp32) and emit bf16 hi/lo split of K
__global__ __launch_bounds__(256) void normalize_split(
    float* __restrict__ Kmat, const float* __restrict__ rowsum,
    __nv_bfloat16* __restrict__ Kh, __nv_bfloat16* __restrict__ Kl)
{
    size_t idx = (size_t)blockIdx.x * 256 + threadIdx.x;   // float4 index
    size_t total4 = ((size_t)NSRC * NTGT) >> 2;
    if (idx >= total4) return;
    int row = (int)(idx >> 10);                            // 1024 float4 per row
    float inv = 1.0f / rowsum[row];
    float4* p = (float4*)Kmat + idx;
    float4 v = *p;
    v.x *= inv; v.y *= inv; v.z *= inv; v.w *= inv;
    *p = v;
    unsigned short h0, h1, h2, h3, l0, l1, l2, l3;
    f32_split(v.x, h0, l0); f32_split(v.y, h1, l1);
    f32_split(v.z, h2, l2); f32_split(v.w, h3, l3);
    ((uint2*)Kh)[idx] = make_uint2((uint32_t)h0 | ((uint32_t)h1 << 16),
                                   (uint32_t)h2 | ((uint32_t)h3 << 16));
    ((uint2*)Kl)[idx] = make_uint2((uint32_t)l0 | ((uint32_t)l1 << 16),
                                   (uint32_t)l2 | ((uint32_t)l3 << 16));
}

// ---------------- launch -----------------------------------------------------
extern "C" void kernel_launch(void* const* d_in, const int* in_sizes, int n_in,
                              void* d_out, int out_size)
{
    const float* source = (const float*)d_in[0];
    const float* target = (const float*)d_in[1];
    const float* W_src  = (const float*)d_in[2];
    const float* b_src  = (const float*)d_in[3];
    const float* W_tgt  = (const float*)d_in[4];
    const float* b_tgt  = (const float*)d_in[5];
    const float* temp   = (const float*)d_in[6];

    float* aligned = (float*)d_out;                       // [NSRC, DIM]
    float* Kout    = (float*)d_out + (size_t)NSRC * DIM;  // [NSRC, NTGT]

    float *sp, *tp, *sqs, *sqt, *rs;
    __nv_bfloat16 *srch, *srcl, *tgth, *tgtl, *Wsh, *Wsl, *Wth, *Wtl;
    __nv_bfloat16 *sph, *spl, *tph, *tpl, *tTh, *tTl, *Kh, *Kl;
    cudaGetSymbolAddress((void**)&sp,  g_sp);
    cudaGetSymbolAddress((void**)&tp,  g_tp);
    cudaGetSymbolAddress((void**)&sqs, g_sqs);
    cudaGetSymbolAddress((void**)&sqt, g_sqt);
    cudaGetSymbolAddress((void**)&rs,  g_rowsum);
    cudaGetSymbolAddress((void**)&srch, g_srch); cudaGetSymbolAddress((void**)&srcl, g_srcl);
    cudaGetSymbolAddress((void**)&tgth, g_tgth); cudaGetSymbolAddress((void**)&tgtl, g_tgtl);
    cudaGetSymbolAddress((void**)&Wsh,  g_Wsh);  cudaGetSymbolAddress((void**)&Wsl,  g_Wsl);
    cudaGetSymbolAddress((void**)&Wth,  g_Wth);  cudaGetSymbolAddress((void**)&Wtl,  g_Wtl);
    cudaGetSymbolAddress((void**)&sph,  g_sph);  cudaGetSymbolAddress((void**)&spl,  g_spl);
    cudaGetSymbolAddress((void**)&tph,  g_tph);  cudaGetSymbolAddress((void**)&tpl,  g_tpl);
    cudaGetSymbolAddress((void**)&tTh,  g_tTh);  cudaGetSymbolAddress((void**)&tTl,  g_tTl);
    cudaGetSymbolAddress((void**)&Kh,   g_Kh);   cudaGetSymbolAddress((void**)&Kl,   g_Kl);

    cudaFuncSetAttribute(tc_gemm<EPI_BIAS>, cudaFuncAttributeMaxDynamicSharedMemorySize, SMEM_DYN);
    cudaFuncSetAttribute(tc_gemm<EPI_COST>, cudaFuncAttributeMaxDynamicSharedMemorySize, SMEM_DYN);
    cudaFuncSetAttribute(tc_gemm<EPI_NONE>, cudaFuncAttributeMaxDynamicSharedMemorySize, SMEM_DYN);

    // 1) split inputs to bf16 hi/lo
    split_kernel<<<(NSRC * DIM / 4 + 255) / 256, 256>>>(source, srch, srcl, (size_t)NSRC * DIM / 4);
    split_kernel<<<(NTGT * DIM / 4 + 255) / 256, 256>>>(target, tgth, tgtl, (size_t)NTGT * DIM / 4);
    split_kernel<<<(DIM * DIM / 4 + 255) / 256, 256>>>(W_src, Wsh, Wsl, (size_t)DIM * DIM / 4);
    split_kernel<<<(DIM * DIM / 4 + 255) / 256, 256>>>(W_tgt, Wth, Wtl, (size_t)DIM * DIM / 4);
    transpose_split<<<dim3(DIM / 32, NTGT / 32), dim3(32, 8)>>>(target, tTh, tTl);

    // 2) projections (emit fp32 result + bf16 hi/lo split)
    tc_gemm<EPI_BIAS><<<dim3(DIM / 128, NSRC / 128), 256, SMEM_DYN>>>(
        srch, srcl, Wsh, Wsl, b_src, nullptr, nullptr, nullptr, sp, sph, spl, DIM, DIM);
    tc_gemm<EPI_BIAS><<<dim3(DIM / 128, NTGT / 128), 256, SMEM_DYN>>>(
        tgth, tgtl, Wth, Wtl, b_tgt, nullptr, nullptr, nullptr, tp, tph, tpl, DIM, DIM);

    // 3) squared norms
    row_reduce<true><<<NSRC, 256>>>(sp, sqs, DIM);
    row_reduce<true><<<NTGT, 256>>>(tp, sqt, DIM);

    // 4) K (unnormalized) = exp(-cdist/T), fused epilogue
    tc_gemm<EPI_COST><<<dim3(NTGT / 128, NSRC / 128), 256, SMEM_DYN>>>(
        sph, spl, tph, tpl, nullptr, sqs, sqt, temp, Kout, nullptr, nullptr, NTGT, DIM);

    // 5) row sums + normalize (+ bf16 split of K)
    row_reduce<false><<<NSRC, 256>>>(Kout, rs, NTGT);
    normalize_split<<<(int)(((size_t)NSRC * NTGT / 4 + 255) / 256), 256>>>(Kout, rs, Kh, Kl);

    // 6) aligned = K @ target (NT with pre-split target^T)
    tc_gemm<EPI_NONE><<<dim3(DIM / 128, NSRC / 128), 256, SMEM_DYN>>>(
        Kh, Kl, tTh, tTl, nullptr, nullptr, nullptr, nullptr, aligned, nullptr, nullptr,
        DIM, NTGT);
}

// round 7
// speedup vs baseline: 1.8237x; 1.2633x over previous
#include <cuda_runtime.h>
#include <cuda_fp16.h>
#include <cstdint>
#include <cstddef>

#define NSRC 4096
#define NTGT 4096
#define DIM  1024

// ---------------- scratch (__device__ globals; no allocations allowed) -----
__device__ float g_sp[(size_t)NSRC * DIM];
__device__ float g_tp[(size_t)NTGT * DIM];
__device__ float g_sqs[NSRC];
__device__ float g_sqt[NTGT];
__device__ float g_rowsum[NSRC];

__device__ __half g_srch[(size_t)NSRC * DIM], g_srcl[(size_t)NSRC * DIM];
__device__ __half g_tgth[(size_t)NTGT * DIM], g_tgtl[(size_t)NTGT * DIM];
__device__ __half g_Wsh[(size_t)DIM * DIM],   g_Wsl[(size_t)DIM * DIM];
__device__ __half g_Wth[(size_t)DIM * DIM],   g_Wtl[(size_t)DIM * DIM];
__device__ __half g_sph[(size_t)NSRC * DIM],  g_spl[(size_t)NSRC * DIM];
__device__ __half g_tph[(size_t)NTGT * DIM],  g_tpl[(size_t)NTGT * DIM];
__device__ __half g_tTh[(size_t)DIM * NTGT],  g_tTl[(size_t)DIM * NTGT];
__device__ __half g_Kh[(size_t)NSRC * NTGT],  g_Kl[(size_t)NSRC * NTGT];

// ---------------- helpers ----------------------------------------------------
__device__ __forceinline__ uint32_t smem_to_u32(const void* p) {
    uint32_t a;
    asm("{ .reg .u64 t; cvta.to.shared.u64 t, %1; cvt.u32.u64 %0, t; }" : "=r"(a) : "l"(p));
    return a;
}
__device__ __forceinline__ void cp_async16(uint32_t dst, const void* src) {
    asm volatile("cp.async.cg.shared.global [%0], [%1], 16;" :: "r"(dst), "l"(src) : "memory");
}
__device__ __forceinline__ void ldm4(uint32_t* r, uint32_t addr) {
    asm volatile("ldmatrix.sync.aligned.m8n8.x4.shared.b16 {%0,%1,%2,%3}, [%4];"
                 : "=r"(r[0]), "=r"(r[1]), "=r"(r[2]), "=r"(r[3]) : "r"(addr));
}
__device__ __forceinline__ void mma_f16(float* c, const uint32_t* a, const uint32_t* b) {
    asm volatile(
        "mma.sync.aligned.m16n8k16.row.col.f32.f16.f16.f32 "
        "{%0,%1,%2,%3}, {%4,%5,%6,%7}, {%8,%9}, {%0,%1,%2,%3};"
        : "+f"(c[0]), "+f"(c[1]), "+f"(c[2]), "+f"(c[3])
        : "r"(a[0]), "r"(a[1]), "r"(a[2]), "r"(a[3]), "r"(b[0]), "r"(b[1]));
}
// fp16 hi/lo split: x = h + l with h=fp16(x); captures ~22 mantissa bits
__device__ __forceinline__ void f32_split(float x, unsigned short& h, unsigned short& l) {
    __half hh = __float2half_rn(x);
    float r = x - __half2float(hh);
    __half hl = __float2half_rn(r);
    h = __half_as_ushort(hh);
    l = __half_as_ushort(hl);
}

// ---------------- warp-MMA split-fp16 NT GEMM -------------------------------
// C[r,c] = sum_k A[r,k]*B[c,k]; fp16 hi/lo operands.
// NPASS=3: hh + lh + hl (loads 4 tiles). NPASS=2: hh + lh (loads 3 tiles; drops
// A_h*B_l term ~2^-11 rel). CTA 128x128, 8 warps (2x4), warp tile 64x32, BK=32,
// double-buffered cp.async, ldmatrix.x4 fragment loads.
#define EPI_NONE 0
#define EPI_BIAS 1
#define EPI_COST 2

#define BK 32
#define ROW_BYTES 80                        // 32 halves (64B) + 16B pad
enum { TILE_BYTES = 128 * ROW_BYTES,        // 10240
       BUF_BYTES  = 4 * TILE_BYTES,         // Ah,Al,Bh,(Bl)
       SMEM_DYN   = 2 * BUF_BYTES };        // 81920

template <int EPI, int NPASS>
__global__ void __launch_bounds__(256, 2) tc_gemm(
    const __half* __restrict__ Ah, const __half* __restrict__ Al,
    const __half* __restrict__ Bh, const __half* __restrict__ Bl,
    const float* __restrict__ bias,
    const float* __restrict__ sqa, const float* __restrict__ sqb,
    const float* __restrict__ temp,
    float* __restrict__ C,
    __half* __restrict__ Chb, __half* __restrict__ Clb,
    int N, int Kdim, float oscale)
{
    extern __shared__ char dsm[];
    const uint32_t sm0 = smem_to_u32(dsm);
    const int tid = threadIdx.x;
    const int wid = tid >> 5, lane = tid & 31;
    const int warpRow = wid & 1;            // 2 row-warps (64 rows each)
    const int warpCol = wid >> 1;           // 4 col-warps (32 cols each)
    const int g  = lane >> 2;
    const int qp = lane & 3;
    const int rowBase = blockIdx.y * 128;
    const int colBase = blockIdx.x * 128;
    const int NTILE = (NPASS == 3) ? 4 : 3;

    const uint32_t offA = (uint32_t)((warpRow * 64 + (lane & 7) + ((lane >> 3) & 1) * 8) * ROW_BYTES
                                     + ((lane >> 4) & 1) * 16);
    const uint32_t offB = (uint32_t)(((lane & 7) + ((lane >> 4) & 1) * 8) * ROW_BYTES
                                     + ((lane >> 3) & 1) * 16);

    const __half* basep[4] = {
        Ah + (size_t)rowBase * Kdim, Al + (size_t)rowBase * Kdim,
        Bh + (size_t)colBase * Kdim,
        (NPASS == 3) ? (Bl + (size_t)colBase * Kdim) : (Bh + (size_t)colBase * Kdim) };

    float acc[4][4][4];
#pragma unroll
    for (int mf = 0; mf < 4; mf++)
#pragma unroll
        for (int nf = 0; nf < 4; nf++)
#pragma unroll
            for (int e = 0; e < 4; e++) acc[mf][nf][e] = 0.f;

    const int KC = Kdim / BK;

    auto issue = [&](int ch, int buf) {
        uint32_t sbase = sm0 + (uint32_t)buf * BUF_BYTES;
        int kt = ch * BK;
#pragma unroll
        for (int j = 0; j < 2 * NTILE; j++) {
            int id  = j * 256 + tid;          // 0..(512*NTILE-1)
            int t   = id >> 9;                // tile 0..NTILE-1
            int c   = id & 511;
            int row = c >> 2;
            int seg = c & 3;
            const void* src = basep[t] + (size_t)row * Kdim + kt + seg * 8;
            uint32_t dst = sbase + (uint32_t)t * TILE_BYTES + row * ROW_BYTES + seg * 16;
            cp_async16(dst, src);
        }
        asm volatile("cp.async.commit_group;" ::: "memory");
    };

    issue(0, 0);
#pragma unroll 1
    for (int ch = 0; ch < KC; ch++) {
        int buf = ch & 1;
        if (ch + 1 < KC) {
            issue(ch + 1, buf ^ 1);
            asm volatile("cp.async.wait_group 1;" ::: "memory");
        } else {
            asm volatile("cp.async.wait_group 0;" ::: "memory");
        }
        __syncthreads();

        uint32_t sb = sm0 + (uint32_t)buf * BUF_BYTES;
#pragma unroll
        for (int ks = 0; ks < 2; ks++) {
            const uint32_t kof = (uint32_t)(ks * 32);
            uint32_t bh[4][2], bl[4][2];
#pragma unroll
            for (int p = 0; p < 2; p++) {
                uint32_t nboff = (uint32_t)((warpCol * 32 + p * 16) * ROW_BYTES);
                uint32_t rh[4];
                ldm4(rh, sb + 2u * TILE_BYTES + nboff + offB + kof);
                bh[p * 2][0] = rh[0]; bh[p * 2][1] = rh[1];
                bh[p * 2 + 1][0] = rh[2]; bh[p * 2 + 1][1] = rh[3];
                if (NPASS == 3) {
                    uint32_t rl[4];
                    ldm4(rl, sb + 3u * TILE_BYTES + nboff + offB + kof);
                    bl[p * 2][0] = rl[0]; bl[p * 2][1] = rl[1];
                    bl[p * 2 + 1][0] = rl[2]; bl[p * 2 + 1][1] = rl[3];
                }
            }
#pragma unroll
            for (int mf = 0; mf < 4; mf++) {
                uint32_t mof = (uint32_t)(mf * 16 * ROW_BYTES);
                uint32_t ah[4], al[4];
                ldm4(ah, sb + mof + offA + kof);
                ldm4(al, sb + TILE_BYTES + mof + offA + kof);
                // pass-separated: same-acc MMAs spaced 4 apart
#pragma unroll
                for (int nf = 0; nf < 4; nf++) mma_f16(acc[mf][nf], ah, bh[nf]);  // hh
#pragma unroll
                for (int nf = 0; nf < 4; nf++) mma_f16(acc[mf][nf], al, bh[nf]);  // lh
                if (NPASS == 3) {
#pragma unroll
                    for (int nf = 0; nf < 4; nf++) mma_f16(acc[mf][nf], ah, bl[nf]);  // hl
                }
            }
        }
        __syncthreads();
    }

    // ---- epilogue -----------------------------------------------------------
    const float invT = (EPI == EPI_COST) ? (1.0f / temp[0]) : 0.f;
#pragma unroll
    for (int mf = 0; mf < 4; mf++) {
        int r0 = rowBase + warpRow * 64 + mf * 16 + g;
#pragma unroll
        for (int half = 0; half < 2; half++) {
            int r = r0 + half * 8;
            float sa = (EPI == EPI_COST) ? sqa[r] : 0.f;
#pragma unroll
            for (int nf = 0; nf < 4; nf++) {
                int c0 = colBase + warpCol * 32 + nf * 8 + qp * 2;
                float v0 = acc[mf][nf][half * 2 + 0];
                float v1 = acc[mf][nf][half * 2 + 1];
                if (EPI == EPI_COST) {
                    float d20 = sa + sqb[c0 + 0] - 2.0f * v0;
                    float d21 = sa + sqb[c0 + 1] - 2.0f * v1;
                    v0 = __expf(-sqrtf(fmaxf(d20, 0.0f)) * invT);
                    v1 = __expf(-sqrtf(fmaxf(d21, 0.0f)) * invT);
                } else if (EPI == EPI_BIAS) {
                    v0 += bias[c0 + 0];
                    v1 += bias[c0 + 1];
                } else {
                    v0 *= oscale;
                    v1 *= oscale;
                }
                *(float2*)(C + (size_t)r * N + c0) = make_float2(v0, v1);
                if (EPI == EPI_BIAS) {
                    unsigned short h0, h1, l0, l1;
                    f32_split(v0, h0, l0);
                    f32_split(v1, h1, l1);
                    *(uint32_t*)(Chb + (size_t)r * N + c0) =
                        (uint32_t)h0 | ((uint32_t)h1 << 16);
                    *(uint32_t*)(Clb + (size_t)r * N + c0) =
                        (uint32_t)l0 | ((uint32_t)l1 << 16);
                }
            }
        }
    }
}

// ---------------- small kernels ---------------------------------------------
__global__ __launch_bounds__(256) void split_kernel(
    const float* __restrict__ in, __half* __restrict__ oh,
    __half* __restrict__ ol, size_t n4)
{
    size_t i = (size_t)blockIdx.x * 256 + threadIdx.x;
    if (i >= n4) return;
    float4 v = ((const float4*)in)[i];
    unsigned short h0, h1, h2, h3, l0, l1, l2, l3;
    f32_split(v.x, h0, l0); f32_split(v.y, h1, l1);
    f32_split(v.z, h2, l2); f32_split(v.w, h3, l3);
    ((uint2*)oh)[i] = make_uint2((uint32_t)h0 | ((uint32_t)h1 << 16),
                                 (uint32_t)h2 | ((uint32_t)h3 << 16));
    ((uint2*)ol)[i] = make_uint2((uint32_t)l0 | ((uint32_t)l1 << 16),
                                 (uint32_t)l2 | ((uint32_t)l3 << 16));
}

// target [NTGT][DIM] fp32 -> hi/lo fp16 [DIM][NTGT]
__global__ void transpose_split(const float* __restrict__ in,
                                __half* __restrict__ oh,
                                __half* __restrict__ ol)
{
    __shared__ float t[32][33];
    int x  = blockIdx.x * 32 + threadIdx.x;
    int y0 = blockIdx.y * 32;
#pragma unroll
    for (int i = 0; i < 4; i++)
        t[threadIdx.y + i * 8][threadIdx.x] = in[(size_t)(y0 + threadIdx.y + i * 8) * DIM + x];
    __syncthreads();
    int ox  = y0 + threadIdx.x;
    int oy0 = blockIdx.x * 32;
#pragma unroll
    for (int i = 0; i < 4; i++) {
        float v = t[threadIdx.x][threadIdx.y + i * 8];
        unsigned short h, l;
        f32_split(v, h, l);
        size_t o = (size_t)(oy0 + threadIdx.y + i * 8) * NTGT + ox;
        oh[o] = __ushort_as_half(h);
        ol[o] = __ushort_as_half(l);
    }
}

template <bool SQ>
__global__ __launch_bounds__(256) void row_reduce(
    const float* __restrict__ X, float* __restrict__ out, int cols)
{
    const int row = blockIdx.x;
    const float4* p = reinterpret_cast<const float4*>(X + (size_t)row * cols);
    const int n4 = cols >> 2;
    float s = 0.f;
    for (int j = threadIdx.x; j < n4; j += 256) {
        float4 v = p[j];
        if (SQ) s += v.x * v.x + v.y * v.y + v.z * v.z + v.w * v.w;
        else    s += v.x + v.y + v.z + v.w;
    }
    __shared__ float red[256];
    red[threadIdx.x] = s;
    __syncthreads();
#pragma unroll
    for (int st = 128; st > 0; st >>= 1) {
        if (threadIdx.x < st) red[threadIdx.x] += red[threadIdx.x + st];
        __syncthreads();
    }
    if (threadIdx.x == 0) out[row] = red[0];
}

// normalize K rows in place (fp32) and emit fp16 hi/lo split of K * 2^12
// (scaling keeps K_lo out of fp16 subnormal territory; undone in aligned GEMM)
#define KSCALE 4096.0f
__global__ __launch_bounds__(256) void normalize_split(
    float* __restrict__ Kmat, const float* __restrict__ rowsum,
    __half* __restrict__ Kh, __half* __restrict__ Kl)
{
    size_t idx = (size_t)blockIdx.x * 256 + threadIdx.x;   // float4 index
    size_t total4 = ((size_t)NSRC * NTGT) >> 2;
    if (idx >= total4) return;
    int row = (int)(idx >> 10);                            // 1024 float4 per row
    float inv = 1.0f / rowsum[row];
    float4* p = (float4*)Kmat + idx;
    float4 v = *p;
    v.x *= inv; v.y *= inv; v.z *= inv; v.w *= inv;
    *p = v;
    unsigned short h0, h1, h2, h3, l0, l1, l2, l3;
    f32_split(v.x * KSCALE, h0, l0); f32_split(v.y * KSCALE, h1, l1);
    f32_split(v.z * KSCALE, h2, l2); f32_split(v.w * KSCALE, h3, l3);
    ((uint2*)Kh)[idx] = make_uint2((uint32_t)h0 | ((uint32_t)h1 << 16),
                                   (uint32_t)h2 | ((uint32_t)h3 << 16));
    ((uint2*)Kl)[idx] = make_uint2((uint32_t)l0 | ((uint32_t)l1 << 16),
                                   (uint32_t)l2 | ((uint32_t)l3 << 16));
}

// ---------------- launch -----------------------------------------------------
extern "C" void kernel_launch(void* const* d_in, const int* in_sizes, int n_in,
                              void* d_out, int out_size)
{
    const float* source = (const float*)d_in[0];
    const float* target = (const float*)d_in[1];
    const float* W_src  = (const float*)d_in[2];
    const float* b_src  = (const float*)d_in[3];
    const float* W_tgt  = (const float*)d_in[4];
    const float* b_tgt  = (const float*)d_in[5];
    const float* temp   = (const float*)d_in[6];

    float* aligned = (float*)d_out;                       // [NSRC, DIM]
    float* Kout    = (float*)d_out + (size_t)NSRC * DIM;  // [NSRC, NTGT]

    float *sp, *tp, *sqs, *sqt, *rs;
    __half *srch, *srcl, *tgth, *tgtl, *Wsh, *Wsl, *Wth, *Wtl;
    __half *sph, *spl, *tph, *tpl, *tTh, *tTl, *Kh, *Kl;
    cudaGetSymbolAddress((void**)&sp,  g_sp);
    cudaGetSymbolAddress((void**)&tp,  g_tp);
    cudaGetSymbolAddress((void**)&sqs, g_sqs);
    cudaGetSymbolAddress((void**)&sqt, g_sqt);
    cudaGetSymbolAddress((void**)&rs,  g_rowsum);
    cudaGetSymbolAddress((void**)&srch, g_srch); cudaGetSymbolAddress((void**)&srcl, g_srcl);
    cudaGetSymbolAddress((void**)&tgth, g_tgth); cudaGetSymbolAddress((void**)&tgtl, g_tgtl);
    cudaGetSymbolAddress((void**)&Wsh,  g_Wsh);  cudaGetSymbolAddress((void**)&Wsl,  g_Wsl);
    cudaGetSymbolAddress((void**)&Wth,  g_Wth);  cudaGetSymbolAddress((void**)&Wtl,  g_Wtl);
    cudaGetSymbolAddress((void**)&sph,  g_sph);  cudaGetSymbolAddress((void**)&spl,  g_spl);
    cudaGetSymbolAddress((void**)&tph,  g_tph);  cudaGetSymbolAddress((void**)&tpl,  g_tpl);
    cudaGetSymbolAddress((void**)&tTh,  g_tTh);  cudaGetSymbolAddress((void**)&tTl,  g_tTl);
    cudaGetSymbolAddress((void**)&Kh,   g_Kh);   cudaGetSymbolAddress((void**)&Kl,   g_Kl);

    cudaFuncSetAttribute((const void*)tc_gemm<EPI_BIAS, 3>, cudaFuncAttributeMaxDynamicSharedMemorySize, SMEM_DYN);
    cudaFuncSetAttribute((const void*)tc_gemm<EPI_COST, 2>, cudaFuncAttributeMaxDynamicSharedMemorySize, SMEM_DYN);
    cudaFuncSetAttribute((const void*)tc_gemm<EPI_NONE, 2>, cudaFuncAttributeMaxDynamicSharedMemorySize, SMEM_DYN);

    // 1) split inputs to fp16 hi/lo
    split_kernel<<<(NSRC * DIM / 4 + 255) / 256, 256>>>(source, srch, srcl, (size_t)NSRC * DIM / 4);
    split_kernel<<<(NTGT * DIM / 4 + 255) / 256, 256>>>(target, tgth, tgtl, (size_t)NTGT * DIM / 4);
    split_kernel<<<(DIM * DIM / 4 + 255) / 256, 256>>>(W_src, Wsh, Wsl, (size_t)DIM * DIM / 4);
    split_kernel<<<(DIM * DIM / 4 + 255) / 256, 256>>>(W_tgt, Wth, Wtl, (size_t)DIM * DIM / 4);
    transpose_split<<<dim3(DIM / 32, NTGT / 32), dim3(32, 8)>>>(target, tTh, tTl);

    // 2) projections: 3-pass fp16 (emit fp32 result + fp16 hi/lo split)
    tc_gemm<EPI_BIAS, 3><<<dim3(DIM / 128, NSRC / 128), 256, SMEM_DYN>>>(
        srch, srcl, Wsh, Wsl, b_src, nullptr, nullptr, nullptr, sp, sph, spl, DIM, DIM, 1.f);
    tc_gemm<EPI_BIAS, 3><<<dim3(DIM / 128, NTGT / 128), 256, SMEM_DYN>>>(
        tgth, tgtl, Wth, Wtl, b_tgt, nullptr, nullptr, nullptr, tp, tph, tpl, DIM, DIM, 1.f);

    // 3) squared norms
    row_reduce<true><<<NSRC, 256>>>(sp, sqs, DIM);
    row_reduce<true><<<NTGT, 256>>>(tp, sqt, DIM);

    // 4) K (unnormalized) = exp(-cdist/T): 2-pass fp16 + fused epilogue
    tc_gemm<EPI_COST, 2><<<dim3(NTGT / 128, NSRC / 128), 256, SMEM_DYN>>>(
        sph, spl, tph, tpl, nullptr, sqs, sqt, temp, Kout, nullptr, nullptr, NTGT, DIM, 1.f);

    // 5) row sums + normalize (+ scaled fp16 split of K)
    row_reduce<false><<<NSRC, 256>>>(Kout, rs, NTGT);
    normalize_split<<<(int)(((size_t)NSRC * NTGT / 4 + 255) / 256), 256>>>(Kout, rs, Kh, Kl);

    // 6) aligned = K @ target: 2-pass fp16, output scaled by 2^-12
    tc_gemm<EPI_NONE, 2><<<dim3(DIM / 128, NSRC / 128), 256, SMEM_DYN>>>(
        Kh, Kl, tTh, tTl, nullptr, nullptr, nullptr, nullptr, aligned, nullptr, nullptr,
        DIM, NTGT, 1.0f / KSCALE);
}

// round 8
// speedup vs baseline: 2.2414x; 1.2291x over previous
#include <cuda_runtime.h>
#include <cuda_fp16.h>
#include <cstdint>
#include <cstddef>

#define NSRC 4096
#define NTGT 4096
#define DIM  1024

// ---------------- scratch (__device__ globals; no allocations allowed) -----
__device__ float g_sqs[NSRC];
__device__ float g_sqt[NTGT];
__device__ float g_rowsum[NSRC];
__device__ float g_sqpart_s[(size_t)NSRC * (DIM / 32)];
__device__ float g_sqpart_t[(size_t)NTGT * (DIM / 32)];
__device__ float g_krspart[(size_t)NSRC * (NTGT / 32)];

__device__ __half g_srch[(size_t)NSRC * DIM], g_srcl[(size_t)NSRC * DIM];
__device__ __half g_tgth[(size_t)NTGT * DIM], g_tgtl[(size_t)NTGT * DIM];
__device__ __half g_Wsh[(size_t)DIM * DIM],   g_Wsl[(size_t)DIM * DIM];
__device__ __half g_Wth[(size_t)DIM * DIM],   g_Wtl[(size_t)DIM * DIM];
__device__ __half g_sph[(size_t)NSRC * DIM];
__device__ __half g_tph[(size_t)NTGT * DIM];
__device__ __half g_tTh[(size_t)DIM * NTGT];
__device__ __half g_Kh[(size_t)NSRC * NTGT],  g_Kl[(size_t)NSRC * NTGT];

// ---------------- helpers ----------------------------------------------------
__device__ __forceinline__ uint32_t smem_to_u32(const void* p) {
    uint32_t a;
    asm("{ .reg .u64 t; cvta.to.shared.u64 t, %1; cvt.u32.u64 %0, t; }" : "=r"(a) : "l"(p));
    return a;
}
__device__ __forceinline__ void cp_async16(uint32_t dst, const void* src) {
    asm volatile("cp.async.cg.shared.global [%0], [%1], 16;" :: "r"(dst), "l"(src) : "memory");
}
__device__ __forceinline__ void ldm4(uint32_t* r, uint32_t addr) {
    asm volatile("ldmatrix.sync.aligned.m8n8.x4.shared.b16 {%0,%1,%2,%3}, [%4];"
                 : "=r"(r[0]), "=r"(r[1]), "=r"(r[2]), "=r"(r[3]) : "r"(addr));
}
__device__ __forceinline__ void mma_f16(float* c, const uint32_t* a, const uint32_t* b) {
    asm volatile(
        "mma.sync.aligned.m16n8k16.row.col.f32.f16.f16.f32 "
        "{%0,%1,%2,%3}, {%4,%5,%6,%7}, {%8,%9}, {%0,%1,%2,%3};"
        : "+f"(c[0]), "+f"(c[1]), "+f"(c[2]), "+f"(c[3])
        : "r"(a[0]), "r"(a[1]), "r"(a[2]), "r"(a[3]), "r"(b[0]), "r"(b[1]));
}
// fp16 hi/lo split: x = h + l, captures ~22 mantissa bits
__device__ __forceinline__ void f32_split(float x, unsigned short& h, unsigned short& l) {
    __half hh = __float2half_rn(x);
    float r = x - __half2float(hh);
    __half hl = __float2half_rn(r);
    h = __half_as_ushort(hh);
    l = __half_as_ushort(hl);
}

// ---------------- warp-MMA split-fp16 NT GEMM -------------------------------
// C[r,c] = sum_k A[r,k]*B[c,k]; fp16 operands.
// NPASS=3: hh+lh+hl (4 tiles). NPASS=2: hh+lh (3 tiles; B hi only).
// NPASS=1: hh (2 tiles). CTA 128x128, 8 warps (2x4), warp tile 64x32, BK=32,
// double-buffered cp.async, ldmatrix.x4 fragment loads.
// Fused row-reduction: EPI_BIAS emits sum(v^2) partials, EPI_COST emits sum(v)
// partials at 32-column granularity (deterministic; reduced by reduce_rows).
#define EPI_NONE 0
#define EPI_BIAS 1
#define EPI_COST 2

#define BK 32
#define ROW_BYTES 80                        // 32 halves (64B) + 16B pad
#define TILE_BYTES (128 * ROW_BYTES)        // 10240

template <int EPI, int NPASS>
__global__ void __launch_bounds__(256, 2) tc_gemm(
    const __half* __restrict__ Ah, const __half* __restrict__ Al,
    const __half* __restrict__ Bh, const __half* __restrict__ Bl,
    const float* __restrict__ bias,
    const float* __restrict__ sqa, const float* __restrict__ sqb,
    const float* __restrict__ temp,
    float* __restrict__ C,
    __half* __restrict__ Chb,
    float* __restrict__ partial,
    int N, int Kdim, float oscale)
{
    constexpr int NTILE = (NPASS == 3) ? 4 : ((NPASS == 2) ? 3 : 2);
    constexpr int BSLOT = (NPASS == 1) ? 1 : 2;
    constexpr uint32_t BUFB = (uint32_t)NTILE * TILE_BYTES;

    extern __shared__ char dsm[];
    const uint32_t sm0 = smem_to_u32(dsm);
    const int tid = threadIdx.x;
    const int wid = tid >> 5, lane = tid & 31;
    const int warpRow = wid & 1;            // 2 row-warps (64 rows each)
    const int warpCol = wid >> 1;           // 4 col-warps (32 cols each)
    const int g  = lane >> 2;
    const int qp = lane & 3;
    const int rowBase = blockIdx.y * 128;
    const int colBase = blockIdx.x * 128;

    const uint32_t offA = (uint32_t)((warpRow * 64 + (lane & 7) + ((lane >> 3) & 1) * 8) * ROW_BYTES
                                     + ((lane >> 4) & 1) * 16);
    const uint32_t offB = (uint32_t)(((lane & 7) + ((lane >> 4) & 1) * 8) * ROW_BYTES
                                     + ((lane >> 3) & 1) * 16);

    const __half* basep[NTILE];
    basep[0] = Ah + (size_t)rowBase * Kdim;
    if (NPASS >= 2) basep[1] = Al + (size_t)rowBase * Kdim;
    basep[BSLOT] = Bh + (size_t)colBase * Kdim;
    if (NPASS == 3) basep[3] = Bl + (size_t)colBase * Kdim;

    float acc[4][4][4];
#pragma unroll
    for (int mf = 0; mf < 4; mf++)
#pragma unroll
        for (int nf = 0; nf < 4; nf++)
#pragma unroll
            for (int e = 0; e < 4; e++) acc[mf][nf][e] = 0.f;

    const int KC = Kdim / BK;

    auto issue = [&](int ch, int buf) {
        uint32_t sbase = sm0 + (uint32_t)buf * BUFB;
        int kt = ch * BK;
#pragma unroll
        for (int j = 0; j < 2 * NTILE; j++) {
            int id  = j * 256 + tid;
            int t   = id >> 9;                // tile 0..NTILE-1
            int c   = id & 511;
            int row = c >> 2;
            int seg = c & 3;
            const void* src = basep[t] + (size_t)row * Kdim + kt + seg * 8;
            uint32_t dst = sbase + (uint32_t)t * TILE_BYTES + row * ROW_BYTES + seg * 16;
            cp_async16(dst, src);
        }
        asm volatile("cp.async.commit_group;" ::: "memory");
    };

    issue(0, 0);
#pragma unroll 1
    for (int ch = 0; ch < KC; ch++) {
        int buf = ch & 1;
        if (ch + 1 < KC) {
            issue(ch + 1, buf ^ 1);
            asm volatile("cp.async.wait_group 1;" ::: "memory");
        } else {
            asm volatile("cp.async.wait_group 0;" ::: "memory");
        }
        __syncthreads();

        uint32_t sb = sm0 + (uint32_t)buf * BUFB;
#pragma unroll
        for (int ks = 0; ks < 2; ks++) {
            const uint32_t kof = (uint32_t)(ks * 32);
            uint32_t bh[4][2], bl[4][2];
#pragma unroll
            for (int p = 0; p < 2; p++) {
                uint32_t nboff = (uint32_t)((warpCol * 32 + p * 16) * ROW_BYTES);
                uint32_t rh[4];
                ldm4(rh, sb + (uint32_t)BSLOT * TILE_BYTES + nboff + offB + kof);
                bh[p * 2][0] = rh[0]; bh[p * 2][1] = rh[1];
                bh[p * 2 + 1][0] = rh[2]; bh[p * 2 + 1][1] = rh[3];
                if (NPASS == 3) {
                    uint32_t rl[4];
                    ldm4(rl, sb + 3u * TILE_BYTES + nboff + offB + kof);
                    bl[p * 2][0] = rl[0]; bl[p * 2][1] = rl[1];
                    bl[p * 2 + 1][0] = rl[2]; bl[p * 2 + 1][1] = rl[3];
                }
            }
#pragma unroll
            for (int mf = 0; mf < 4; mf++) {
                uint32_t mof = (uint32_t)(mf * 16 * ROW_BYTES);
                uint32_t ah[4], al[4];
                ldm4(ah, sb + mof + offA + kof);
                if (NPASS >= 2) ldm4(al, sb + TILE_BYTES + mof + offA + kof);
#pragma unroll
                for (int nf = 0; nf < 4; nf++) mma_f16(acc[mf][nf], ah, bh[nf]);  // hh
                if (NPASS >= 2) {
#pragma unroll
                    for (int nf = 0; nf < 4; nf++) mma_f16(acc[mf][nf], al, bh[nf]);  // lh
                }
                if (NPASS == 3) {
#pragma unroll
                    for (int nf = 0; nf < 4; nf++) mma_f16(acc[mf][nf], ah, bl[nf]);  // hl
                }
            }
        }
        __syncthreads();
    }

    // ---- epilogue (with fused deterministic row partial sums) ---------------
    const float invT = (EPI == EPI_COST) ? (1.0f / temp[0]) : 0.f;
    const int nchunk = N >> 5;
    const int chunkIdx = (colBase >> 5) + warpCol;
#pragma unroll
    for (int mf = 0; mf < 4; mf++) {
#pragma unroll
        for (int half = 0; half < 2; half++) {
            int r = rowBase + warpRow * 64 + mf * 16 + g + half * 8;
            float sa = (EPI == EPI_COST) ? sqa[r] : 0.f;
            float rs = 0.f;
#pragma unroll
            for (int nf = 0; nf < 4; nf++) {
                int c0 = colBase + warpCol * 32 + nf * 8 + qp * 2;
                float v0 = acc[mf][nf][half * 2 + 0];
                float v1 = acc[mf][nf][half * 2 + 1];
                if (EPI == EPI_COST) {
                    float d20 = sa + sqb[c0 + 0] - 2.0f * v0;
                    float d21 = sa + sqb[c0 + 1] - 2.0f * v1;
                    v0 = __expf(-sqrtf(fmaxf(d20, 0.0f)) * invT);
                    v1 = __expf(-sqrtf(fmaxf(d21, 0.0f)) * invT);
                    *(float2*)(C + (size_t)r * N + c0) = make_float2(v0, v1);
                    rs += v0 + v1;
                } else if (EPI == EPI_BIAS) {
                    v0 += bias[c0 + 0];
                    v1 += bias[c0 + 1];
                    unsigned short h0 = __half_as_ushort(__float2half_rn(v0));
                    unsigned short h1 = __half_as_ushort(__float2half_rn(v1));
                    *(uint32_t*)(Chb + (size_t)r * N + c0) =
                        (uint32_t)h0 | ((uint32_t)h1 << 16);
                    rs += v0 * v0 + v1 * v1;
                } else {
                    *(float2*)(C + (size_t)r * N + c0) =
                        make_float2(v0 * oscale, v1 * oscale);
                }
            }
            if (EPI != EPI_NONE) {
                rs += __shfl_xor_sync(0xffffffffu, rs, 1);
                rs += __shfl_xor_sync(0xffffffffu, rs, 2);
                if (qp == 0) partial[(size_t)r * nchunk + chunkIdx] = rs;
            }
        }
    }
}

// ---------------- small kernels ---------------------------------------------
__global__ __launch_bounds__(256) void split_kernel(
    const float* __restrict__ in, __half* __restrict__ oh,
    __half* __restrict__ ol, size_t n4)
{
    size_t i = (size_t)blockIdx.x * 256 + threadIdx.x;
    if (i >= n4) return;
    float4 v = ((const float4*)in)[i];
    unsigned short h0, h1, h2, h3, l0, l1, l2, l3;
    f32_split(v.x, h0, l0); f32_split(v.y, h1, l1);
    f32_split(v.z, h2, l2); f32_split(v.w, h3, l3);
    ((uint2*)oh)[i] = make_uint2((uint32_t)h0 | ((uint32_t)h1 << 16),
                                 (uint32_t)h2 | ((uint32_t)h3 << 16));
    ((uint2*)ol)[i] = make_uint2((uint32_t)l0 | ((uint32_t)l1 << 16),
                                 (uint32_t)l2 | ((uint32_t)l3 << 16));
}

// target [NTGT][DIM] fp32 -> hi fp16 [DIM][NTGT]
__global__ void transpose_hi(const float* __restrict__ in,
                             __half* __restrict__ oh)
{
    __shared__ float t[32][33];
    int x  = blockIdx.x * 32 + threadIdx.x;
    int y0 = blockIdx.y * 32;
#pragma unroll
    for (int i = 0; i < 4; i++)
        t[threadIdx.y + i * 8][threadIdx.x] = in[(size_t)(y0 + threadIdx.y + i * 8) * DIM + x];
    __syncthreads();
    int ox  = y0 + threadIdx.x;
    int oy0 = blockIdx.x * 32;
#pragma unroll
    for (int i = 0; i < 4; i++) {
        float v = t[threadIdx.x][threadIdx.y + i * 8];
        size_t o = (size_t)(oy0 + threadIdx.y + i * 8) * NTGT + ox;
        oh[o] = __float2half_rn(v);
    }
}

// deterministic serial per-row reduce of 32-col partials
__global__ __launch_bounds__(256) void reduce_rows(
    const float* __restrict__ part, float* __restrict__ out, int nchunk)
{
    int row = blockIdx.x * blockDim.x + threadIdx.x;
    const float* p = part + (size_t)row * nchunk;
    float s = 0.f;
    for (int i = 0; i < nchunk; i++) s += p[i];
    out[row] = s;
}

// normalize K rows in place (fp32) and emit fp16 hi/lo split of K * 2^12
#define KSCALE 4096.0f
__global__ __launch_bounds__(256) void normalize_split(
    float* __restrict__ Kmat, const float* __restrict__ rowsum,
    __half* __restrict__ Kh, __half* __restrict__ Kl)
{
    size_t idx = (size_t)blockIdx.x * 256 + threadIdx.x;   // float4 index
    size_t total4 = ((size_t)NSRC * NTGT) >> 2;
    if (idx >= total4) return;
    int row = (int)(idx >> 10);                            // 1024 float4 per row
    float inv = 1.0f / rowsum[row];
    float4* p = (float4*)Kmat + idx;
    float4 v = *p;
    v.x *= inv; v.y *= inv; v.z *= inv; v.w *= inv;
    *p = v;
    unsigned short h0, h1, h2, h3, l0, l1, l2, l3;
    f32_split(v.x * KSCALE, h0, l0); f32_split(v.y * KSCALE, h1, l1);
    f32_split(v.z * KSCALE, h2, l2); f32_split(v.w * KSCALE, h3, l3);
    ((uint2*)Kh)[idx] = make_uint2((uint32_t)h0 | ((uint32_t)h1 << 16),
                                   (uint32_t)h2 | ((uint32_t)h3 << 16));
    ((uint2*)Kl)[idx] = make_uint2((uint32_t)l0 | ((uint32_t)l1 << 16),
                                   (uint32_t)l2 | ((uint32_t)l3 << 16));
}

// ---------------- launch -----------------------------------------------------
extern "C" void kernel_launch(void* const* d_in, const int* in_sizes, int n_in,
                              void* d_out, int out_size)
{
    const float* source = (const float*)d_in[0];
    const float* target = (const float*)d_in[1];
    const float* W_src  = (const float*)d_in[2];
    const float* b_src  = (const float*)d_in[3];
    const float* W_tgt  = (const float*)d_in[4];
    const float* b_tgt  = (const float*)d_in[5];
    const float* temp   = (const float*)d_in[6];

    float* aligned = (float*)d_out;                       // [NSRC, DIM]
    float* Kout    = (float*)d_out + (size_t)NSRC * DIM;  // [NSRC, NTGT]

    float *sqs, *sqt, *rs, *sqps, *sqpt, *krsp;
    __half *srch, *srcl, *tgth, *tgtl, *Wsh, *Wsl, *Wth, *Wtl;
    __half *sph, *tph, *tTh, *Kh, *Kl;
    cudaGetSymbolAddress((void**)&sqs,  g_sqs);
    cudaGetSymbolAddress((void**)&sqt,  g_sqt);
    cudaGetSymbolAddress((void**)&rs,   g_rowsum);
    cudaGetSymbolAddress((void**)&sqps, g_sqpart_s);
    cudaGetSymbolAddress((void**)&sqpt, g_sqpart_t);
    cudaGetSymbolAddress((void**)&krsp, g_krspart);
    cudaGetSymbolAddress((void**)&srch, g_srch); cudaGetSymbolAddress((void**)&srcl, g_srcl);
    cudaGetSymbolAddress((void**)&tgth, g_tgth); cudaGetSymbolAddress((void**)&tgtl, g_tgtl);
    cudaGetSymbolAddress((void**)&Wsh,  g_Wsh);  cudaGetSymbolAddress((void**)&Wsl,  g_Wsl);
    cudaGetSymbolAddress((void**)&Wth,  g_Wth);  cudaGetSymbolAddress((void**)&Wtl,  g_Wtl);
    cudaGetSymbolAddress((void**)&sph,  g_sph);
    cudaGetSymbolAddress((void**)&tph,  g_tph);
    cudaGetSymbolAddress((void**)&tTh,  g_tTh);
    cudaGetSymbolAddress((void**)&Kh,   g_Kh);   cudaGetSymbolAddress((void**)&Kl,   g_Kl);

    const int SMEM2 = 2 * 3 * TILE_BYTES;   // NPASS=2: 61440
    const int SMEM1 = 2 * 2 * TILE_BYTES;   // NPASS=1: 40960
    cudaFuncSetAttribute((const void*)tc_gemm<EPI_BIAS, 2>, cudaFuncAttributeMaxDynamicSharedMemorySize, SMEM2);
    cudaFuncSetAttribute((const void*)tc_gemm<EPI_COST, 1>, cudaFuncAttributeMaxDynamicSharedMemorySize, SMEM1);
    cudaFuncSetAttribute((const void*)tc_gemm<EPI_NONE, 2>, cudaFuncAttributeMaxDynamicSharedMemorySize, SMEM2);

    // 1) split inputs to fp16 hi/lo (W lo is written but unused by 2-pass proj)
    split_kernel<<<(NSRC * DIM / 4 + 255) / 256, 256>>>(source, srch, srcl, (size_t)NSRC * DIM / 4);
    split_kernel<<<(NTGT * DIM / 4 + 255) / 256, 256>>>(target, tgth, tgtl, (size_t)NTGT * DIM / 4);
    split_kernel<<<(DIM * DIM / 4 + 255) / 256, 256>>>(W_src, Wsh, Wsl, (size_t)DIM * DIM / 4);
    split_kernel<<<(DIM * DIM / 4 + 255) / 256, 256>>>(W_tgt, Wth, Wtl, (size_t)DIM * DIM / 4);
    transpose_hi<<<dim3(DIM / 32, NTGT / 32), dim3(32, 8)>>>(target, tTh);

    // 2) projections: 2-pass fp16, emit fp16 hi + fused sq-norm partials
    tc_gemm<EPI_BIAS, 2><<<dim3(DIM / 128, NSRC / 128), 256, SMEM2>>>(
        srch, srcl, Wsh, nullptr, b_src, nullptr, nullptr, nullptr,
        nullptr, sph, sqps, DIM, DIM, 1.f);
    tc_gemm<EPI_BIAS, 2><<<dim3(DIM / 128, NTGT / 128), 256, SMEM2>>>(
        tgth, tgtl, Wth, nullptr, b_tgt, nullptr, nullptr, nullptr,
        nullptr, tph, sqpt, DIM, DIM, 1.f);

    // 3) reduce sq-norm partials (deterministic serial)
    reduce_rows<<<NSRC / 256, 256>>>(sqps, sqs, DIM / 32);
    reduce_rows<<<NTGT / 256, 256>>>(sqpt, sqt, DIM / 32);

    // 4) K (unnormalized) = exp(-cdist/T): 1-pass fp16 + fused rowsum partials
    tc_gemm<EPI_COST, 1><<<dim3(NTGT / 128, NSRC / 128), 256, SMEM1>>>(
        sph, nullptr, tph, nullptr, nullptr, sqs, sqt, temp,
        Kout, nullptr, krsp, NTGT, DIM, 1.f);

    // 5) reduce rowsum partials, normalize + scaled fp16 split of K
    reduce_rows<<<NSRC / 256, 256>>>(krsp, rs, NTGT / 32);
    normalize_split<<<(int)(((size_t)NSRC * NTGT / 4 + 255) / 256), 256>>>(Kout, rs, Kh, Kl);

    // 6) aligned = K @ target: 2-pass fp16 (K hi/lo x target hi), scaled 2^-12
    tc_gemm<EPI_NONE, 2><<<dim3(DIM / 128, NSRC / 128), 256, SMEM2>>>(
        Kh, Kl, tTh, nullptr, nullptr, nullptr, nullptr, nullptr,
        aligned, nullptr, nullptr, DIM, NTGT, 1.0f / KSCALE);
}

// round 9
// speedup vs baseline: 2.9176x; 1.3017x over previous
#include <cuda_runtime.h>
#include <cuda_fp16.h>
#include <cstdint>
#include <cstddef>

#define NSRC 4096
#define NTGT 4096
#define DIM  1024

// ---------------- scratch (__device__ globals; no allocations allowed) -----
__device__ float g_sqs[NSRC];
__device__ float g_sqt[NTGT];
__device__ float g_rowsum[NSRC];
__device__ float g_sqpart_s[(size_t)NSRC * (DIM / 32)];
__device__ float g_sqpart_t[(size_t)NTGT * (DIM / 32)];
__device__ float g_krspart[(size_t)NSRC * (NTGT / 32)];

__device__ __half g_srch[(size_t)NSRC * DIM];
__device__ __half g_tgth[(size_t)NTGT * DIM];
__device__ __half g_Wsh[(size_t)DIM * DIM];
__device__ __half g_Wth[(size_t)DIM * DIM];
__device__ __half g_sph[(size_t)NSRC * DIM];
__device__ __half g_tph[(size_t)NTGT * DIM];
__device__ __half g_tTh[(size_t)DIM * NTGT];
__device__ __half g_Kh[(size_t)NSRC * NTGT];

// ---------------- helpers ----------------------------------------------------
__device__ __forceinline__ uint32_t smem_to_u32(const void* p) {
    uint32_t a;
    asm("{ .reg .u64 t; cvta.to.shared.u64 t, %1; cvt.u32.u64 %0, t; }" : "=r"(a) : "l"(p));
    return a;
}
__device__ __forceinline__ void cp_async16(uint32_t dst, const void* src) {
    asm volatile("cp.async.cg.shared.global [%0], [%1], 16;" :: "r"(dst), "l"(src) : "memory");
}
__device__ __forceinline__ void ldm4(uint32_t* r, uint32_t addr) {
    asm volatile("ldmatrix.sync.aligned.m8n8.x4.shared.b16 {%0,%1,%2,%3}, [%4];"
                 : "=r"(r[0]), "=r"(r[1]), "=r"(r[2]), "=r"(r[3]) : "r"(addr));
}
__device__ __forceinline__ void mma_f16(float* c, const uint32_t* a, const uint32_t* b) {
    asm volatile(
        "mma.sync.aligned.m16n8k16.row.col.f32.f16.f16.f32 "
        "{%0,%1,%2,%3}, {%4,%5,%6,%7}, {%8,%9}, {%0,%1,%2,%3};"
        : "+f"(c[0]), "+f"(c[1]), "+f"(c[2]), "+f"(c[3])
        : "r"(a[0]), "r"(a[1]), "r"(a[2]), "r"(a[3]), "r"(b[0]), "r"(b[1]));
}

// ---------------- warp-MMA fp16 NT GEMM (single-pass hi x hi) ----------------
// C[r,c] = sum_k A[r,k]*B[c,k]; fp16 operands, fp32 accumulate.
// CTA 128x128, 8 warps (2x4), warp tile 64x32, BK=32, double-buffered cp.async,
// ldmatrix.x4 fragment loads. Fused deterministic row partial sums:
// EPI_BIAS emits sum(v^2) partials, EPI_COST emits sum(v) partials (32-col
// granularity, reduced by reduce_rows).
#define EPI_NONE 0
#define EPI_BIAS 1
#define EPI_COST 2

#define BK 32
#define ROW_BYTES 80                        // 32 halves (64B) + 16B pad
#define TILE_BYTES (128 * ROW_BYTES)        // 10240
#define SMEM_DYN (2 * 2 * TILE_BYTES)       // 40960

template <int EPI>
__global__ void __launch_bounds__(256, 2) tc_gemm(
    const __half* __restrict__ Ah, const __half* __restrict__ Bh,
    const float* __restrict__ bias,
    const float* __restrict__ sqa, const float* __restrict__ sqb,
    const float* __restrict__ temp,
    float* __restrict__ C,
    __half* __restrict__ Chb,
    float* __restrict__ partial,
    int N, int Kdim, float oscale)
{
    extern __shared__ char dsm[];
    const uint32_t sm0 = smem_to_u32(dsm);
    const int tid = threadIdx.x;
    const int wid = tid >> 5, lane = tid & 31;
    const int warpRow = wid & 1;            // 2 row-warps (64 rows each)
    const int warpCol = wid >> 1;           // 4 col-warps (32 cols each)
    const int g  = lane >> 2;
    const int qp = lane & 3;
    const int rowBase = blockIdx.y * 128;
    const int colBase = blockIdx.x * 128;

    const uint32_t offA = (uint32_t)((warpRow * 64 + (lane & 7) + ((lane >> 3) & 1) * 8) * ROW_BYTES
                                     + ((lane >> 4) & 1) * 16);
    const uint32_t offB = (uint32_t)(((lane & 7) + ((lane >> 4) & 1) * 8) * ROW_BYTES
                                     + ((lane >> 3) & 1) * 16);

    const __half* basep[2] = { Ah + (size_t)rowBase * Kdim, Bh + (size_t)colBase * Kdim };

    float acc[4][4][4];
#pragma unroll
    for (int mf = 0; mf < 4; mf++)
#pragma unroll
        for (int nf = 0; nf < 4; nf++)
#pragma unroll
            for (int e = 0; e < 4; e++) acc[mf][nf][e] = 0.f;

    const int KC = Kdim / BK;

    auto issue = [&](int ch, int buf) {
        uint32_t sbase = sm0 + (uint32_t)buf * (2u * TILE_BYTES);
        int kt = ch * BK;
#pragma unroll
        for (int j = 0; j < 4; j++) {
            int id  = j * 256 + tid;          // 0..1023
            int t   = id >> 9;                // tile 0..1
            int c   = id & 511;
            int row = c >> 2;
            int seg = c & 3;
            const void* src = basep[t] + (size_t)row * Kdim + kt + seg * 8;
            uint32_t dst = sbase + (uint32_t)t * TILE_BYTES + row * ROW_BYTES + seg * 16;
            cp_async16(dst, src);
        }
        asm volatile("cp.async.commit_group;" ::: "memory");
    };

    issue(0, 0);
#pragma unroll 1
    for (int ch = 0; ch < KC; ch++) {
        int buf = ch & 1;
        if (ch + 1 < KC) {
            issue(ch + 1, buf ^ 1);
            asm volatile("cp.async.wait_group 1;" ::: "memory");
        } else {
            asm volatile("cp.async.wait_group 0;" ::: "memory");
        }
        __syncthreads();

        uint32_t sb = sm0 + (uint32_t)buf * (2u * TILE_BYTES);
#pragma unroll
        for (int ks = 0; ks < 2; ks++) {
            const uint32_t kof = (uint32_t)(ks * 32);
            uint32_t bh[4][2];
#pragma unroll
            for (int p = 0; p < 2; p++) {
                uint32_t nboff = (uint32_t)((warpCol * 32 + p * 16) * ROW_BYTES);
                uint32_t rh[4];
                ldm4(rh, sb + TILE_BYTES + nboff + offB + kof);
                bh[p * 2][0] = rh[0]; bh[p * 2][1] = rh[1];
                bh[p * 2 + 1][0] = rh[2]; bh[p * 2 + 1][1] = rh[3];
            }
#pragma unroll
            for (int mf = 0; mf < 4; mf++) {
                uint32_t mof = (uint32_t)(mf * 16 * ROW_BYTES);
                uint32_t ah[4];
                ldm4(ah, sb + mof + offA + kof);
#pragma unroll
                for (int nf = 0; nf < 4; nf++) mma_f16(acc[mf][nf], ah, bh[nf]);
            }
        }
        __syncthreads();
    }

    // ---- epilogue (with fused deterministic row partial sums) ---------------
    const float invT = (EPI == EPI_COST) ? (1.0f / temp[0]) : 0.f;
    const int nchunk = N >> 5;
    const int chunkIdx = (colBase >> 5) + warpCol;
#pragma unroll
    for (int mf = 0; mf < 4; mf++) {
#pragma unroll
        for (int half = 0; half < 2; half++) {
            int r = rowBase + warpRow * 64 + mf * 16 + g + half * 8;
            float sa = (EPI == EPI_COST) ? sqa[r] : 0.f;
            float rs = 0.f;
#pragma unroll
            for (int nf = 0; nf < 4; nf++) {
                int c0 = colBase + warpCol * 32 + nf * 8 + qp * 2;
                float v0 = acc[mf][nf][half * 2 + 0];
                float v1 = acc[mf][nf][half * 2 + 1];
                if (EPI == EPI_COST) {
                    float d20 = sa + sqb[c0 + 0] - 2.0f * v0;
                    float d21 = sa + sqb[c0 + 1] - 2.0f * v1;
                    v0 = __expf(-sqrtf(fmaxf(d20, 0.0f)) * invT);
                    v1 = __expf(-sqrtf(fmaxf(d21, 0.0f)) * invT);
                    *(float2*)(C + (size_t)r * N + c0) = make_float2(v0, v1);
                    rs += v0 + v1;
                } else if (EPI == EPI_BIAS) {
                    v0 += bias[c0 + 0];
                    v1 += bias[c0 + 1];
                    unsigned short h0 = __half_as_ushort(__float2half_rn(v0));
                    unsigned short h1 = __half_as_ushort(__float2half_rn(v1));
                    *(uint32_t*)(Chb + (size_t)r * N + c0) =
                        (uint32_t)h0 | ((uint32_t)h1 << 16);
                    rs += v0 * v0 + v1 * v1;
                } else {
                    *(float2*)(C + (size_t)r * N + c0) =
                        make_float2(v0 * oscale, v1 * oscale);
                }
            }
            if (EPI != EPI_NONE) {
                rs += __shfl_xor_sync(0xffffffffu, rs, 1);
                rs += __shfl_xor_sync(0xffffffffu, rs, 2);
                if (qp == 0) partial[(size_t)r * nchunk + chunkIdx] = rs;
            }
        }
    }
}

// ---------------- small kernels ---------------------------------------------
// fp32 -> fp16 (hi only)
__global__ __launch_bounds__(256) void convert_hi(
    const float* __restrict__ in, __half* __restrict__ oh, size_t n4)
{
    size_t i = (size_t)blockIdx.x * 256 + threadIdx.x;
    if (i >= n4) return;
    float4 v = ((const float4*)in)[i];
    unsigned short h0 = __half_as_ushort(__float2half_rn(v.x));
    unsigned short h1 = __half_as_ushort(__float2half_rn(v.y));
    unsigned short h2 = __half_as_ushort(__float2half_rn(v.z));
    unsigned short h3 = __half_as_ushort(__float2half_rn(v.w));
    ((uint2*)oh)[i] = make_uint2((uint32_t)h0 | ((uint32_t)h1 << 16),
                                 (uint32_t)h2 | ((uint32_t)h3 << 16));
}

// target [NTGT][DIM] fp32 -> hi fp16 [DIM][NTGT]
__global__ void transpose_hi(const float* __restrict__ in,
                             __half* __restrict__ oh)
{
    __shared__ float t[32][33];
    int x  = blockIdx.x * 32 + threadIdx.x;
    int y0 = blockIdx.y * 32;
#pragma unroll
    for (int i = 0; i < 4; i++)
        t[threadIdx.y + i * 8][threadIdx.x] = in[(size_t)(y0 + threadIdx.y + i * 8) * DIM + x];
    __syncthreads();
    int ox  = y0 + threadIdx.x;
    int oy0 = blockIdx.x * 32;
#pragma unroll
    for (int i = 0; i < 4; i++) {
        float v = t[threadIdx.x][threadIdx.y + i * 8];
        size_t o = (size_t)(oy0 + threadIdx.y + i * 8) * NTGT + ox;
        oh[o] = __float2half_rn(v);
    }
}

// deterministic serial per-row reduce of 32-col partials
__global__ __launch_bounds__(256) void reduce_rows(
    const float* __restrict__ part, float* __restrict__ out, int nchunk)
{
    int row = blockIdx.x * blockDim.x + threadIdx.x;
    const float* p = part + (size_t)row * nchunk;
    float s = 0.f;
    for (int i = 0; i < nchunk; i++) s += p[i];
    out[row] = s;
}

// normalize K rows in place (fp32) and emit fp16 hi of K * 2^12
#define KSCALE 4096.0f
__global__ __launch_bounds__(256) void normalize_hi(
    float* __restrict__ Kmat, const float* __restrict__ rowsum,
    __half* __restrict__ Kh)
{
    size_t idx = (size_t)blockIdx.x * 256 + threadIdx.x;   // float4 index
    size_t total4 = ((size_t)NSRC * NTGT) >> 2;
    if (idx >= total4) return;
    int row = (int)(idx >> 10);                            // 1024 float4 per row
    float inv = 1.0f / rowsum[row];
    float4* p = (float4*)Kmat + idx;
    float4 v = *p;
    v.x *= inv; v.y *= inv; v.z *= inv; v.w *= inv;
    *p = v;
    unsigned short h0 = __half_as_ushort(__float2half_rn(v.x * KSCALE));
    unsigned short h1 = __half_as_ushort(__float2half_rn(v.y * KSCALE));
    unsigned short h2 = __half_as_ushort(__float2half_rn(v.z * KSCALE));
    unsigned short h3 = __half_as_ushort(__float2half_rn(v.w * KSCALE));
    ((uint2*)Kh)[idx] = make_uint2((uint32_t)h0 | ((uint32_t)h1 << 16),
                                   (uint32_t)h2 | ((uint32_t)h3 << 16));
}

// ---------------- launch -----------------------------------------------------
extern "C" void kernel_launch(void* const* d_in, const int* in_sizes, int n_in,
                              void* d_out, int out_size)
{
    const float* source = (const float*)d_in[0];
    const float* target = (const float*)d_in[1];
    const float* W_src  = (const float*)d_in[2];
    const float* b_src  = (const float*)d_in[3];
    const float* W_tgt  = (const float*)d_in[4];
    const float* b_tgt  = (const float*)d_in[5];
    const float* temp   = (const float*)d_in[6];

    float* aligned = (float*)d_out;                       // [NSRC, DIM]
    float* Kout    = (float*)d_out + (size_t)NSRC * DIM;  // [NSRC, NTGT]

    float *sqs, *sqt, *rs, *sqps, *sqpt, *krsp;
    __half *srch, *tgth, *Wsh, *Wth, *sph, *tph, *tTh, *Kh;
    cudaGetSymbolAddress((void**)&sqs,  g_sqs);
    cudaGetSymbolAddress((void**)&sqt,  g_sqt);
    cudaGetSymbolAddress((void**)&rs,   g_rowsum);
    cudaGetSymbolAddress((void**)&sqps, g_sqpart_s);
    cudaGetSymbolAddress((void**)&sqpt, g_sqpart_t);
    cudaGetSymbolAddress((void**)&krsp, g_krspart);
    cudaGetSymbolAddress((void**)&srch, g_srch);
    cudaGetSymbolAddress((void**)&tgth, g_tgth);
    cudaGetSymbolAddress((void**)&Wsh,  g_Wsh);
    cudaGetSymbolAddress((void**)&Wth,  g_Wth);
    cudaGetSymbolAddress((void**)&sph,  g_sph);
    cudaGetSymbolAddress((void**)&tph,  g_tph);
    cudaGetSymbolAddress((void**)&tTh,  g_tTh);
    cudaGetSymbolAddress((void**)&Kh,   g_Kh);

    cudaFuncSetAttribute((const void*)tc_gemm<EPI_BIAS>, cudaFuncAttributeMaxDynamicSharedMemorySize, SMEM_DYN);
    cudaFuncSetAttribute((const void*)tc_gemm<EPI_COST>, cudaFuncAttributeMaxDynamicSharedMemorySize, SMEM_DYN);
    cudaFuncSetAttribute((const void*)tc_gemm<EPI_NONE>, cudaFuncAttributeMaxDynamicSharedMemorySize, SMEM_DYN);

    // 1) convert inputs to fp16 (hi)
    convert_hi<<<(NSRC * DIM / 4 + 255) / 256, 256>>>(source, srch, (size_t)NSRC * DIM / 4);
    convert_hi<<<(NTGT * DIM / 4 + 255) / 256, 256>>>(target, tgth, (size_t)NTGT * DIM / 4);
    convert_hi<<<(DIM * DIM / 4 + 255) / 256, 256>>>(W_src, Wsh, (size_t)DIM * DIM / 4);
    convert_hi<<<(DIM * DIM / 4 + 255) / 256, 256>>>(W_tgt, Wth, (size_t)DIM * DIM / 4);
    transpose_hi<<<dim3(DIM / 32, NTGT / 32), dim3(32, 8)>>>(target, tTh);

    // 2) projections: 1-pass fp16, emit fp16 hi + fused sq-norm partials
    tc_gemm<EPI_BIAS><<<dim3(DIM / 128, NSRC / 128), 256, SMEM_DYN>>>(
        srch, Wsh, b_src, nullptr, nullptr, nullptr,
        nullptr, sph, sqps, DIM, DIM, 1.f);
    tc_gemm<EPI_BIAS><<<dim3(DIM / 128, NTGT / 128), 256, SMEM_DYN>>>(
        tgth, Wth, b_tgt, nullptr, nullptr, nullptr,
        nullptr, tph, sqpt, DIM, DIM, 1.f);

    // 3) reduce sq-norm partials (deterministic serial)
    reduce_rows<<<NSRC / 256, 256>>>(sqps, sqs, DIM / 32);
    reduce_rows<<<NTGT / 256, 256>>>(sqpt, sqt, DIM / 32);

    // 4) K (unnormalized) = exp(-cdist/T): 1-pass fp16 + fused rowsum partials
    tc_gemm<EPI_COST><<<dim3(NTGT / 128, NSRC / 128), 256, SMEM_DYN>>>(
        sph, tph, nullptr, sqs, sqt, temp,
        Kout, nullptr, krsp, NTGT, DIM, 1.f);

    // 5) reduce rowsum partials, normalize + scaled fp16 hi of K
    reduce_rows<<<NSRC / 256, 256>>>(krsp, rs, NTGT / 32);
    normalize_hi<<<(int)(((size_t)NSRC * NTGT / 4 + 255) / 256), 256>>>(Kout, rs, Kh);

    // 6) aligned = K @ target: 1-pass fp16 (Kh x target hi), scaled 2^-12
    tc_gemm<EPI_NONE><<<dim3(DIM / 128, NSRC / 128), 256, SMEM_DYN>>>(
        Kh, tTh, nullptr, nullptr, nullptr, nullptr,
        aligned, nullptr, nullptr, DIM, NTGT, 1.0f / KSCALE);
}

// round 10
// speedup vs baseline: 3.0487x; 1.0449x over previous
#include <cuda_runtime.h>
#include <cuda_fp16.h>
#include <cstdint>
#include <cstddef>

#define NSRC 4096
#define NTGT 4096
#define DIM  1024

// ---------------- scratch (__device__ globals; no allocations allowed) -----
__device__ float g_sqs[NSRC];
__device__ float g_sqt[NTGT];
__device__ float g_rowsum[NSRC];
__device__ float g_sqpart_s[(size_t)NSRC * (DIM / 32)];
__device__ float g_sqpart_t[(size_t)NTGT * (DIM / 32)];
__device__ float g_krspart[(size_t)NSRC * (NTGT / 32)];

__device__ __half g_srch[(size_t)NSRC * DIM];
__device__ __half g_tgth[(size_t)NTGT * DIM];
__device__ __half g_Wsh[(size_t)DIM * DIM];
__device__ __half g_Wth[(size_t)DIM * DIM];
__device__ __half g_sph[(size_t)NSRC * DIM];
__device__ __half g_tph[(size_t)NTGT * DIM];
__device__ __half g_tTh[(size_t)DIM * NTGT];
__device__ __half g_Kh[(size_t)NSRC * NTGT];

// ---------------- helpers ----------------------------------------------------
__device__ __forceinline__ uint32_t smem_to_u32(const void* p) {
    uint32_t a;
    asm("{ .reg .u64 t; cvta.to.shared.u64 t, %1; cvt.u32.u64 %0, t; }" : "=r"(a) : "l"(p));
    return a;
}
__device__ __forceinline__ void cp_async16(uint32_t dst, const void* src) {
    asm volatile("cp.async.cg.shared.global [%0], [%1], 16;" :: "r"(dst), "l"(src) : "memory");
}
__device__ __forceinline__ void ldm4(uint32_t* r, uint32_t addr) {
    asm volatile("ldmatrix.sync.aligned.m8n8.x4.shared.b16 {%0,%1,%2,%3}, [%4];"
                 : "=r"(r[0]), "=r"(r[1]), "=r"(r[2]), "=r"(r[3]) : "r"(addr));
}
__device__ __forceinline__ void mma_f16(float* c, const uint32_t* a, const uint32_t* b) {
    asm volatile(
        "mma.sync.aligned.m16n8k16.row.col.f32.f16.f16.f32 "
        "{%0,%1,%2,%3}, {%4,%5,%6,%7}, {%8,%9}, {%0,%1,%2,%3};"
        : "+f"(c[0]), "+f"(c[1]), "+f"(c[2]), "+f"(c[3])
        : "r"(a[0]), "r"(a[1]), "r"(a[2]), "r"(a[3]), "r"(b[0]), "r"(b[1]));
}
__device__ __forceinline__ float fsqrt_ap(float x) {
    float r; asm("sqrt.approx.f32 %0, %1;" : "=f"(r) : "f"(x)); return r;
}
__device__ __forceinline__ float fex2_ap(float x) {
    float r; asm("ex2.approx.f32 %0, %1;" : "=f"(r) : "f"(x)); return r;
}

// ---------------- warp-MMA fp16 NT GEMM (single-pass hi x hi) ----------------
// C[r,c] = sum_k A[r,k]*B[c,k]; fp16 operands, fp32 accumulate.
// CTA 128x128, 8 warps (2x4), warp tile 64x32, BK=32, double-buffered cp.async,
// ldmatrix.x4 fragment loads. Fused deterministic row partial sums:
// EPI_BIAS emits sum(v^2) partials, EPI_COST emits sum(v) partials (32-col
// granularity, reduced by reduce_rows).
// DUAL=true: blockIdx.z in {0,1} selects operand set (merged proj launch).
#define EPI_NONE 0
#define EPI_BIAS 1
#define EPI_COST 2

#define BK 32
#define ROW_BYTES 80                        // 32 halves (64B) + 16B pad
#define TILE_BYTES (128 * ROW_BYTES)        // 10240
#define SMEM_DYN (2 * 2 * TILE_BYTES)       // 40960

template <int EPI, bool DUAL>
__global__ void __launch_bounds__(256, 2) tc_gemm(
    const __half* __restrict__ Ah, const __half* __restrict__ Bh,
    const float* __restrict__ bias,
    const __half* __restrict__ A2, const __half* __restrict__ B2,
    const float* __restrict__ bias2,
    const float* __restrict__ sqa, const float* __restrict__ sqb,
    const float* __restrict__ temp,
    float* __restrict__ C,
    __half* __restrict__ Chb, __half* __restrict__ Chb2,
    float* __restrict__ partial, float* __restrict__ partial2,
    int N, int Kdim, float oscale)
{
    extern __shared__ char dsm[];
    const uint32_t sm0 = smem_to_u32(dsm);
    const int tid = threadIdx.x;
    const int wid = tid >> 5, lane = tid & 31;
    const int warpRow = wid & 1;            // 2 row-warps (64 rows each)
    const int warpCol = wid >> 1;           // 4 col-warps (32 cols each)
    const int g  = lane >> 2;
    const int qp = lane & 3;
    const int rowBase = blockIdx.y * 128;
    const int colBase = blockIdx.x * 128;

    const __half* Ause = Ah;
    const __half* Buse = Bh;
    const float*  buse = bias;
    __half* chbuse = Chb;
    float*  partuse = partial;
    if (DUAL && blockIdx.z == 1) {
        Ause = A2; Buse = B2; buse = bias2; chbuse = Chb2; partuse = partial2;
    }

    const uint32_t offA = (uint32_t)((warpRow * 64 + (lane & 7) + ((lane >> 3) & 1) * 8) * ROW_BYTES
                                     + ((lane >> 4) & 1) * 16);
    const uint32_t offB = (uint32_t)(((lane & 7) + ((lane >> 4) & 1) * 8) * ROW_BYTES
                                     + ((lane >> 3) & 1) * 16);

    const __half* basep[2] = { Ause + (size_t)rowBase * Kdim, Buse + (size_t)colBase * Kdim };

    float acc[4][4][4];
#pragma unroll
    for (int mf = 0; mf < 4; mf++)
#pragma unroll
        for (int nf = 0; nf < 4; nf++)
#pragma unroll
            for (int e = 0; e < 4; e++) acc[mf][nf][e] = 0.f;

    const int KC = Kdim / BK;

    auto issue = [&](int ch, int buf) {
        uint32_t sbase = sm0 + (uint32_t)buf * (2u * TILE_BYTES);
        int kt = ch * BK;
#pragma unroll
        for (int j = 0; j < 4; j++) {
            int id  = j * 256 + tid;          // 0..1023
            int t   = id >> 9;                // tile 0..1
            int c   = id & 511;
            int row = c >> 2;
            int seg = c & 3;
            const void* src = basep[t] + (size_t)row * Kdim + kt + seg * 8;
            uint32_t dst = sbase + (uint32_t)t * TILE_BYTES + row * ROW_BYTES + seg * 16;
            cp_async16(dst, src);
        }
        asm volatile("cp.async.commit_group;" ::: "memory");
    };

    issue(0, 0);
#pragma unroll 1
    for (int ch = 0; ch < KC; ch++) {
        int buf = ch & 1;
        if (ch + 1 < KC) {
            issue(ch + 1, buf ^ 1);
            asm volatile("cp.async.wait_group 1;" ::: "memory");
        } else {
            asm volatile("cp.async.wait_group 0;" ::: "memory");
        }
        __syncthreads();

        uint32_t sb = sm0 + (uint32_t)buf * (2u * TILE_BYTES);
#pragma unroll
        for (int ks = 0; ks < 2; ks++) {
            const uint32_t kof = (uint32_t)(ks * 32);
            uint32_t bh[4][2];
#pragma unroll
            for (int p = 0; p < 2; p++) {
                uint32_t nboff = (uint32_t)((warpCol * 32 + p * 16) * ROW_BYTES);
                uint32_t rh[4];
                ldm4(rh, sb + TILE_BYTES + nboff + offB + kof);
                bh[p * 2][0] = rh[0]; bh[p * 2][1] = rh[1];
                bh[p * 2 + 1][0] = rh[2]; bh[p * 2 + 1][1] = rh[3];
            }
#pragma unroll
            for (int mf = 0; mf < 4; mf++) {
                uint32_t mof = (uint32_t)(mf * 16 * ROW_BYTES);
                uint32_t ah[4];
                ldm4(ah, sb + mof + offA + kof);
#pragma unroll
                for (int nf = 0; nf < 4; nf++) mma_f16(acc[mf][nf], ah, bh[nf]);
            }
        }
        __syncthreads();
    }

    // ---- epilogue (with fused deterministic row partial sums) ---------------
    // cost: exp(-sqrt(d2)/T) = ex2(-sqrt(d2) * log2(e)/T)
    const float cT = (EPI == EPI_COST) ? (1.44269504088896340736f / temp[0]) : 0.f;
    const int nchunk = N >> 5;
    const int chunkIdx = (colBase >> 5) + warpCol;
#pragma unroll
    for (int mf = 0; mf < 4; mf++) {
#pragma unroll
        for (int half = 0; half < 2; half++) {
            int r = rowBase + warpRow * 64 + mf * 16 + g + half * 8;
            float sa = (EPI == EPI_COST) ? sqa[r] : 0.f;
            float rs = 0.f;
#pragma unroll
            for (int nf = 0; nf < 4; nf++) {
                int c0 = colBase + warpCol * 32 + nf * 8 + qp * 2;
                float v0 = acc[mf][nf][half * 2 + 0];
                float v1 = acc[mf][nf][half * 2 + 1];
                if (EPI == EPI_COST) {
                    float d20 = sa + sqb[c0 + 0] - 2.0f * v0;
                    float d21 = sa + sqb[c0 + 1] - 2.0f * v1;
                    v0 = fex2_ap(-fsqrt_ap(fmaxf(d20, 0.0f)) * cT);
                    v1 = fex2_ap(-fsqrt_ap(fmaxf(d21, 0.0f)) * cT);
                    *(float2*)(C + (size_t)r * N + c0) = make_float2(v0, v1);
                    rs += v0 + v1;
                } else if (EPI == EPI_BIAS) {
                    v0 += buse[c0 + 0];
                    v1 += buse[c0 + 1];
                    unsigned short h0 = __half_as_ushort(__float2half_rn(v0));
                    unsigned short h1 = __half_as_ushort(__float2half_rn(v1));
                    *(uint32_t*)(chbuse + (size_t)r * N + c0) =
                        (uint32_t)h0 | ((uint32_t)h1 << 16);
                    rs += v0 * v0 + v1 * v1;
                } else {
                    *(float2*)(C + (size_t)r * N + c0) =
                        make_float2(v0 * oscale, v1 * oscale);
                }
            }
            if (EPI != EPI_NONE) {
                rs += __shfl_xor_sync(0xffffffffu, rs, 1);
                rs += __shfl_xor_sync(0xffffffffu, rs, 2);
                if (qp == 0) partuse[(size_t)r * nchunk + chunkIdx] = rs;
            }
        }
    }
}

// ---------------- small kernels ---------------------------------------------
// all four fp32->fp16 conversions in one launch (range dispatch, float4 units)
#define N4_SRC ((size_t)NSRC * DIM / 4)     // 1048576
#define N4_TGT ((size_t)NTGT * DIM / 4)     // 1048576
#define N4_W   ((size_t)DIM * DIM / 4)      // 262144
#define N4_ALL (N4_SRC + N4_TGT + 2 * N4_W) // 2621440
__global__ __launch_bounds__(256) void convert_all(
    const float* __restrict__ src, const float* __restrict__ tgt,
    const float* __restrict__ ws, const float* __restrict__ wt,
    __half* __restrict__ osrc, __half* __restrict__ otgt,
    __half* __restrict__ ows, __half* __restrict__ owt)
{
    size_t i = (size_t)blockIdx.x * 256 + threadIdx.x;
    if (i >= N4_ALL) return;
    const float* in;
    __half* oh;
    size_t j = i;
    if (j < N4_SRC) { in = src; oh = osrc; }
    else if ((j -= N4_SRC) < N4_TGT) { in = tgt; oh = otgt; }
    else if ((j -= N4_TGT) < N4_W) { in = ws; oh = ows; }
    else { j -= N4_W; in = wt; oh = owt; }
    float4 v = ((const float4*)in)[j];
    unsigned short h0 = __half_as_ushort(__float2half_rn(v.x));
    unsigned short h1 = __half_as_ushort(__float2half_rn(v.y));
    unsigned short h2 = __half_as_ushort(__float2half_rn(v.z));
    unsigned short h3 = __half_as_ushort(__float2half_rn(v.w));
    ((uint2*)oh)[j] = make_uint2((uint32_t)h0 | ((uint32_t)h1 << 16),
                                 (uint32_t)h2 | ((uint32_t)h3 << 16));
}

// target [NTGT][DIM] fp32 -> hi fp16 [DIM][NTGT]
__global__ void transpose_hi(const float* __restrict__ in,
                             __half* __restrict__ oh)
{
    __shared__ float t[32][33];
    int x  = blockIdx.x * 32 + threadIdx.x;
    int y0 = blockIdx.y * 32;
#pragma unroll
    for (int i = 0; i < 4; i++)
        t[threadIdx.y + i * 8][threadIdx.x] = in[(size_t)(y0 + threadIdx.y + i * 8) * DIM + x];
    __syncthreads();
    int ox  = y0 + threadIdx.x;
    int oy0 = blockIdx.x * 32;
#pragma unroll
    for (int i = 0; i < 4; i++) {
        float v = t[threadIdx.x][threadIdx.y + i * 8];
        size_t o = (size_t)(oy0 + threadIdx.y + i * 8) * NTGT + ox;
        oh[o] = __float2half_rn(v);
    }
}

// deterministic serial per-row reduce of 32-col partials
// rows [0,NSRC) from partA -> outA ; rows [NSRC, NSRC+NTGT) from partB -> outB
__global__ __launch_bounds__(256) void reduce_rows2(
    const float* __restrict__ partA, float* __restrict__ outA,
    const float* __restrict__ partB, float* __restrict__ outB, int nchunk)
{
    int row = blockIdx.x * blockDim.x + threadIdx.x;
    const float* p;
    float* o;
    int r = row;
    if (row < NSRC) { p = partA; o = outA; }
    else            { p = partB; o = outB; r = row - NSRC; }
    const float* pr = p + (size_t)r * nchunk;
    float s = 0.f;
    for (int i = 0; i < nchunk; i++) s += pr[i];
    o[r] = s;
}

__global__ __launch_bounds__(256) void reduce_rows(
    const float* __restrict__ part, float* __restrict__ out, int nchunk)
{
    int row = blockIdx.x * blockDim.x + threadIdx.x;
    const float* p = part + (size_t)row * nchunk;
    float s = 0.f;
    for (int i = 0; i < nchunk; i++) s += p[i];
    out[row] = s;
}

// normalize K rows in place (fp32) and emit fp16 hi of K * 2^12
#define KSCALE 4096.0f
__global__ __launch_bounds__(256) void normalize_hi(
    float* __restrict__ Kmat, const float* __restrict__ rowsum,
    __half* __restrict__ Kh)
{
    size_t idx = (size_t)blockIdx.x * 256 + threadIdx.x;   // float4 index
    size_t total4 = ((size_t)NSRC * NTGT) >> 2;
    if (idx >= total4) return;
    int row = (int)(idx >> 10);                            // 1024 float4 per row
    float inv = 1.0f / rowsum[row];
    float4* p = (float4*)Kmat + idx;
    float4 v = *p;
    v.x *= inv; v.y *= inv; v.z *= inv; v.w *= inv;
    *p = v;
    unsigned short h0 = __half_as_ushort(__float2half_rn(v.x * KSCALE));
    unsigned short h1 = __half_as_ushort(__float2half_rn(v.y * KSCALE));
    unsigned short h2 = __half_as_ushort(__float2half_rn(v.z * KSCALE));
    unsigned short h3 = __half_as_ushort(__float2half_rn(v.w * KSCALE));
    ((uint2*)Kh)[idx] = make_uint2((uint32_t)h0 | ((uint32_t)h1 << 16),
                                   (uint32_t)h2 | ((uint32_t)h3 << 16));
}

// ---------------- launch -----------------------------------------------------
extern "C" void kernel_launch(void* const* d_in, const int* in_sizes, int n_in,
                              void* d_out, int out_size)
{
    const float* source = (const float*)d_in[0];
    const float* target = (const float*)d_in[1];
    const float* W_src  = (const float*)d_in[2];
    const float* b_src  = (const float*)d_in[3];
    const float* W_tgt  = (const float*)d_in[4];
    const float* b_tgt  = (const float*)d_in[5];
    const float* temp   = (const float*)d_in[6];

    float* aligned = (float*)d_out;                       // [NSRC, DIM]
    float* Kout    = (float*)d_out + (size_t)NSRC * DIM;  // [NSRC, NTGT]

    float *sqs, *sqt, *rs, *sqps, *sqpt, *krsp;
    __half *srch, *tgth, *Wsh, *Wth, *sph, *tph, *tTh, *Kh;
    cudaGetSymbolAddress((void**)&sqs,  g_sqs);
    cudaGetSymbolAddress((void**)&sqt,  g_sqt);
    cudaGetSymbolAddress((void**)&rs,   g_rowsum);
    cudaGetSymbolAddress((void**)&sqps, g_sqpart_s);
    cudaGetSymbolAddress((void**)&sqpt, g_sqpart_t);
    cudaGetSymbolAddress((void**)&krsp, g_krspart);
    cudaGetSymbolAddress((void**)&srch, g_srch);
    cudaGetSymbolAddress((void**)&tgth, g_tgth);
    cudaGetSymbolAddress((void**)&Wsh,  g_Wsh);
    cudaGetSymbolAddress((void**)&Wth,  g_Wth);
    cudaGetSymbolAddress((void**)&sph,  g_sph);
    cudaGetSymbolAddress((void**)&tph,  g_tph);
    cudaGetSymbolAddress((void**)&tTh,  g_tTh);
    cudaGetSymbolAddress((void**)&Kh,   g_Kh);

    cudaFuncSetAttribute((const void*)tc_gemm<EPI_BIAS, true>,  cudaFuncAttributeMaxDynamicSharedMemorySize, SMEM_DYN);
    cudaFuncSetAttribute((const void*)tc_gemm<EPI_COST, false>, cudaFuncAttributeMaxDynamicSharedMemorySize, SMEM_DYN);
    cudaFuncSetAttribute((const void*)tc_gemm<EPI_NONE, false>, cudaFuncAttributeMaxDynamicSharedMemorySize, SMEM_DYN);

    // 1) convert all inputs to fp16 (single launch) + transposed target
    convert_all<<<(int)((N4_ALL + 255) / 256), 256>>>(
        source, target, W_src, W_tgt, srch, tgth, Wsh, Wth);
    transpose_hi<<<dim3(DIM / 32, NTGT / 32), dim3(32, 8)>>>(target, tTh);

    // 2) both projections in ONE launch (z=0: source, z=1: target);
    //    1-pass fp16, emit fp16 hi + fused sq-norm partials
    tc_gemm<EPI_BIAS, true><<<dim3(DIM / 128, NSRC / 128, 2), 256, SMEM_DYN>>>(
        srch, Wsh, b_src, tgth, Wth, b_tgt,
        nullptr, nullptr, nullptr,
        nullptr, sph, tph, sqps, sqpt, DIM, DIM, 1.f);

    // 3) reduce both sq-norm partial sets in one launch
    reduce_rows2<<<(NSRC + NTGT) / 256, 256>>>(sqps, sqs, sqpt, sqt, DIM / 32);

    // 4) K (unnormalized) = exp(-cdist/T): 1-pass fp16 + fused rowsum partials
    tc_gemm<EPI_COST, false><<<dim3(NTGT / 128, NSRC / 128), 256, SMEM_DYN>>>(
        sph, tph, nullptr, nullptr, nullptr, nullptr,
        sqs, sqt, temp,
        Kout, nullptr, nullptr, krsp, nullptr, NTGT, DIM, 1.f);

    // 5) reduce rowsum partials, normalize + scaled fp16 hi of K
    reduce_rows<<<NSRC / 256, 256>>>(krsp, rs, NTGT / 32);
    normalize_hi<<<(int)(((size_t)NSRC * NTGT / 4 + 255) / 256), 256>>>(Kout, rs, Kh);

    // 6) aligned = K @ target: 1-pass fp16 (Kh x target hi), scaled 2^-12
    tc_gemm<EPI_NONE, false><<<dim3(DIM / 128, NSRC / 128), 256, SMEM_DYN>>>(
        Kh, tTh, nullptr, nullptr, nullptr, nullptr,
        nullptr, nullptr, nullptr,
        aligned, nullptr, nullptr, nullptr, nullptr, DIM, NTGT, 1.0f / KSCALE);
}

// round 11
// speedup vs baseline: 3.7225x; 1.2210x over previous
#include <cuda_runtime.h>
#include <cuda_fp16.h>
#include <cstdint>
#include <cstddef>

#define NSRC 4096
#define NTGT 4096
#define DIM  1024

// ---------------- scratch (__device__ globals; no allocations allowed) -----
__device__ float g_sqs[NSRC];
__device__ float g_sqt[NTGT];
__device__ float g_rowsum[NSRC];
__device__ float g_sqpart_s[(size_t)NSRC * (DIM / 32)];
__device__ float g_sqpart_t[(size_t)NTGT * (DIM / 32)];
__device__ float g_krspart[(size_t)NSRC * (NTGT / 32)];

__device__ __half g_srch[(size_t)NSRC * DIM];
__device__ __half g_tgth[(size_t)NTGT * DIM];
__device__ __half g_Wsh[(size_t)DIM * DIM];
__device__ __half g_Wth[(size_t)DIM * DIM];
__device__ __half g_sph[(size_t)NSRC * DIM];
__device__ __half g_tph[(size_t)NTGT * DIM];
__device__ __half g_tTh[(size_t)DIM * NTGT];
__device__ __half g_Kh[(size_t)NSRC * NTGT];

// ---------------- helpers ----------------------------------------------------
__device__ __forceinline__ uint32_t smem_to_u32(const void* p) {
    uint32_t a;
    asm("{ .reg .u64 t; cvta.to.shared.u64 t, %1; cvt.u32.u64 %0, t; }" : "=r"(a) : "l"(p));
    return a;
}
__device__ __forceinline__ void cp_async16(uint32_t dst, const void* src) {
    asm volatile("cp.async.cg.shared.global [%0], [%1], 16;" :: "r"(dst), "l"(src) : "memory");
}
__device__ __forceinline__ void ldm4(uint32_t* r, uint32_t addr) {
    asm volatile("ldmatrix.sync.aligned.m8n8.x4.shared.b16 {%0,%1,%2,%3}, [%4];"
                 : "=r"(r[0]), "=r"(r[1]), "=r"(r[2]), "=r"(r[3]) : "r"(addr));
}
__device__ __forceinline__ void mma_f16(float* c, const uint32_t* a, const uint32_t* b) {
    asm volatile(
        "mma.sync.aligned.m16n8k16.row.col.f32.f16.f16.f32 "
        "{%0,%1,%2,%3}, {%4,%5,%6,%7}, {%8,%9}, {%0,%1,%2,%3};"
        : "+f"(c[0]), "+f"(c[1]), "+f"(c[2]), "+f"(c[3])
        : "r"(a[0]), "r"(a[1]), "r"(a[2]), "r"(a[3]), "r"(b[0]), "r"(b[1]));
}
__device__ __forceinline__ float fsqrt_ap(float x) {
    float r; asm("sqrt.approx.f32 %0, %1;" : "=f"(r) : "f"(x)); return r;
}
__device__ __forceinline__ float fex2_ap(float x) {
    float r; asm("ex2.approx.f32 %0, %1;" : "=f"(r) : "f"(x)); return r;
}

// ---------------- warp-MMA fp16 NT GEMM (single-pass hi x hi) ----------------
// C[r,c] = sum_k A[r,k]*B[c,k]; fp16 operands, fp32 accumulate.
// CTA 128x128, 8 warps (2x4), warp tile 64x32, BK=64, double-buffered cp.async,
// ldmatrix.x4 fragment loads. Fused deterministic row partial sums:
// EPI_BIAS emits sum(v^2) partials, EPI_COST emits sum(v) partials (32-col
// granularity). DUAL=true: blockIdx.z selects operand set (merged proj launch).
#define EPI_NONE 0
#define EPI_BIAS 1
#define EPI_COST 2

#define BK 64
#define ROW_BYTES 144                       // 64 halves (128B) + 16B pad
#define TILE_BYTES (128 * ROW_BYTES)        // 18432
#define SMEM_DYN (2 * 2 * TILE_BYTES)       // 73728

template <int EPI, bool DUAL>
__global__ void __launch_bounds__(256, 2) tc_gemm(
    const __half* __restrict__ Ah, const __half* __restrict__ Bh,
    const float* __restrict__ bias,
    const __half* __restrict__ A2, const __half* __restrict__ B2,
    const float* __restrict__ bias2,
    const float* __restrict__ sqa, const float* __restrict__ sqb,
    const float* __restrict__ temp,
    float* __restrict__ C,
    __half* __restrict__ Chb, __half* __restrict__ Chb2,
    float* __restrict__ partial, float* __restrict__ partial2,
    int N, int Kdim, float oscale)
{
    extern __shared__ char dsm[];
    const uint32_t sm0 = smem_to_u32(dsm);
    const int tid = threadIdx.x;
    const int wid = tid >> 5, lane = tid & 31;
    const int warpRow = wid & 1;            // 2 row-warps (64 rows each)
    const int warpCol = wid >> 1;           // 4 col-warps (32 cols each)
    const int g  = lane >> 2;
    const int qp = lane & 3;
    const int rowBase = blockIdx.y * 128;
    const int colBase = blockIdx.x * 128;

    const __half* Ause = Ah;
    const __half* Buse = Bh;
    const float*  buse = bias;
    __half* chbuse = Chb;
    float*  partuse = partial;
    if (DUAL && blockIdx.z == 1) {
        Ause = A2; Buse = B2; buse = bias2; chbuse = Chb2; partuse = partial2;
    }

    const uint32_t offA = (uint32_t)((warpRow * 64 + (lane & 7) + ((lane >> 3) & 1) * 8) * ROW_BYTES
                                     + ((lane >> 4) & 1) * 16);
    const uint32_t offB = (uint32_t)(((lane & 7) + ((lane >> 4) & 1) * 8) * ROW_BYTES
                                     + ((lane >> 3) & 1) * 16);

    const __half* basep[2] = { Ause + (size_t)rowBase * Kdim, Buse + (size_t)colBase * Kdim };

    float acc[4][4][4];
#pragma unroll
    for (int mf = 0; mf < 4; mf++)
#pragma unroll
        for (int nf = 0; nf < 4; nf++)
#pragma unroll
            for (int e = 0; e < 4; e++) acc[mf][nf][e] = 0.f;

    const int KC = Kdim / BK;               // 16

    auto issue = [&](int ch, int buf) {
        uint32_t sbase = sm0 + (uint32_t)buf * (2u * TILE_BYTES);
        int kt = ch * BK;
#pragma unroll
        for (int j = 0; j < 8; j++) {
            int id  = j * 256 + tid;          // 0..2047
            int t   = id >> 10;               // tile 0..1
            int c   = id & 1023;
            int row = c >> 3;                 // 0..127
            int seg = c & 7;                  // 0..7 (16B units)
            const void* src = basep[t] + (size_t)row * Kdim + kt + seg * 8;
            uint32_t dst = sbase + (uint32_t)t * TILE_BYTES + row * ROW_BYTES + seg * 16;
            cp_async16(dst, src);
        }
        asm volatile("cp.async.commit_group;" ::: "memory");
    };

    issue(0, 0);
#pragma unroll 1
    for (int ch = 0; ch < KC; ch++) {
        int buf = ch & 1;
        if (ch + 1 < KC) {
            issue(ch + 1, buf ^ 1);
            asm volatile("cp.async.wait_group 1;" ::: "memory");
        } else {
            asm volatile("cp.async.wait_group 0;" ::: "memory");
        }
        __syncthreads();

        uint32_t sb = sm0 + (uint32_t)buf * (2u * TILE_BYTES);
#pragma unroll
        for (int ks = 0; ks < 4; ks++) {
            const uint32_t kof = (uint32_t)(ks * 32);
            uint32_t bh[4][2];
#pragma unroll
            for (int p = 0; p < 2; p++) {
                uint32_t nboff = (uint32_t)((warpCol * 32 + p * 16) * ROW_BYTES);
                uint32_t rh[4];
                ldm4(rh, sb + TILE_BYTES + nboff + offB + kof);
                bh[p * 2][0] = rh[0]; bh[p * 2][1] = rh[1];
                bh[p * 2 + 1][0] = rh[2]; bh[p * 2 + 1][1] = rh[3];
            }
#pragma unroll
            for (int mf = 0; mf < 4; mf++) {
                uint32_t mof = (uint32_t)(mf * 16 * ROW_BYTES);
                uint32_t ah[4];
                ldm4(ah, sb + mof + offA + kof);
#pragma unroll
                for (int nf = 0; nf < 4; nf++) mma_f16(acc[mf][nf], ah, bh[nf]);
            }
        }
        __syncthreads();
    }

    // ---- epilogue (with fused deterministic row partial sums) ---------------
    // cost: exp(-sqrt(d2)/T) = ex2(-sqrt(d2) * log2(e)/T)
    const float cT = (EPI == EPI_COST) ? (1.44269504088896340736f / temp[0]) : 0.f;
    const int nchunk = N >> 5;
    const int chunkIdx = (colBase >> 5) + warpCol;
#pragma unroll
    for (int mf = 0; mf < 4; mf++) {
#pragma unroll
        for (int half = 0; half < 2; half++) {
            int r = rowBase + warpRow * 64 + mf * 16 + g + half * 8;
            float sa = (EPI == EPI_COST) ? sqa[r] : 0.f;
            float rs = 0.f;
#pragma unroll
            for (int nf = 0; nf < 4; nf++) {
                int c0 = colBase + warpCol * 32 + nf * 8 + qp * 2;
                float v0 = acc[mf][nf][half * 2 + 0];
                float v1 = acc[mf][nf][half * 2 + 1];
                if (EPI == EPI_COST) {
                    float d20 = sa + sqb[c0 + 0] - 2.0f * v0;
                    float d21 = sa + sqb[c0 + 1] - 2.0f * v1;
                    v0 = fex2_ap(-fsqrt_ap(fmaxf(d20, 0.0f)) * cT);
                    v1 = fex2_ap(-fsqrt_ap(fmaxf(d21, 0.0f)) * cT);
                    *(float2*)(C + (size_t)r * N + c0) = make_float2(v0, v1);
                    rs += v0 + v1;
                } else if (EPI == EPI_BIAS) {
                    v0 += buse[c0 + 0];
                    v1 += buse[c0 + 1];
                    unsigned short h0 = __half_as_ushort(__float2half_rn(v0));
                    unsigned short h1 = __half_as_ushort(__float2half_rn(v1));
                    *(uint32_t*)(chbuse + (size_t)r * N + c0) =
                        (uint32_t)h0 | ((uint32_t)h1 << 16);
                    rs += v0 * v0 + v1 * v1;
                } else {
                    *(float2*)(C + (size_t)r * N + c0) =
                        make_float2(v0 * oscale, v1 * oscale);
                }
            }
            if (EPI != EPI_NONE) {
                rs += __shfl_xor_sync(0xffffffffu, rs, 1);
                rs += __shfl_xor_sync(0xffffffffu, rs, 2);
                if (qp == 0) partuse[(size_t)r * nchunk + chunkIdx] = rs;
            }
        }
    }
}

// ---------------- small kernels ---------------------------------------------
// all four fp32->fp16 conversions in one launch (range dispatch, float4 units)
#define N4_SRC ((size_t)NSRC * DIM / 4)     // 1048576
#define N4_TGT ((size_t)NTGT * DIM / 4)     // 1048576
#define N4_W   ((size_t)DIM * DIM / 4)      // 262144
#define N4_ALL (N4_SRC + N4_TGT + 2 * N4_W) // 2621440
__global__ __launch_bounds__(256) void convert_all(
    const float* __restrict__ src, const float* __restrict__ tgt,
    const float* __restrict__ ws, const float* __restrict__ wt,
    __half* __restrict__ osrc, __half* __restrict__ otgt,
    __half* __restrict__ ows, __half* __restrict__ owt)
{
    size_t i = (size_t)blockIdx.x * 256 + threadIdx.x;
    if (i >= N4_ALL) return;
    const float* in;
    __half* oh;
    size_t j = i;
    if (j < N4_SRC) { in = src; oh = osrc; }
    else if ((j -= N4_SRC) < N4_TGT) { in = tgt; oh = otgt; }
    else if ((j -= N4_TGT) < N4_W) { in = ws; oh = ows; }
    else { j -= N4_W; in = wt; oh = owt; }
    float4 v = ((const float4*)in)[j];
    unsigned short h0 = __half_as_ushort(__float2half_rn(v.x));
    unsigned short h1 = __half_as_ushort(__float2half_rn(v.y));
    unsigned short h2 = __half_as_ushort(__float2half_rn(v.z));
    unsigned short h3 = __half_as_ushort(__float2half_rn(v.w));
    ((uint2*)oh)[j] = make_uint2((uint32_t)h0 | ((uint32_t)h1 << 16),
                                 (uint32_t)h2 | ((uint32_t)h3 << 16));
}

// target [NTGT][DIM] fp32 -> hi fp16 [DIM][NTGT]
__global__ void transpose_hi(const float* __restrict__ in,
                             __half* __restrict__ oh)
{
    __shared__ float t[32][33];
    int x  = blockIdx.x * 32 + threadIdx.x;
    int y0 = blockIdx.y * 32;
#pragma unroll
    for (int i = 0; i < 4; i++)
        t[threadIdx.y + i * 8][threadIdx.x] = in[(size_t)(y0 + threadIdx.y + i * 8) * DIM + x];
    __syncthreads();
    int ox  = y0 + threadIdx.x;
    int oy0 = blockIdx.x * 32;
#pragma unroll
    for (int i = 0; i < 4; i++) {
        float v = t[threadIdx.x][threadIdx.y + i * 8];
        size_t o = (size_t)(oy0 + threadIdx.y + i * 8) * NTGT + ox;
        oh[o] = __float2half_rn(v);
    }
}

// warp-per-row deterministic reduce (fixed shuffle tree order every run).
// rows [0,NSRC) from partA -> outA ; rows [NSRC, NSRC+NTGT) from partB -> outB
__global__ __launch_bounds__(256) void reduce_rows_warp2(
    const float* __restrict__ partA, float* __restrict__ outA,
    const float* __restrict__ partB, float* __restrict__ outB, int nchunk)
{
    int w = (int)((blockIdx.x * blockDim.x + threadIdx.x) >> 5);
    int lane = threadIdx.x & 31;
    const float* p;
    float* o;
    int r = w;
    if (w < NSRC) { p = partA; o = outA; }
    else          { p = partB; o = outB; r = w - NSRC; }
    const float* pr = p + (size_t)r * nchunk;
    float s = 0.f;
    for (int i = lane; i < nchunk; i += 32) s += pr[i];
#pragma unroll
    for (int st = 16; st > 0; st >>= 1) s += __shfl_xor_sync(0xffffffffu, s, st);
    if (lane == 0) o[r] = s;
}

__global__ __launch_bounds__(256) void reduce_rows_warp(
    const float* __restrict__ part, float* __restrict__ out, int nchunk)
{
    int w = (int)((blockIdx.x * blockDim.x + threadIdx.x) >> 5);
    int lane = threadIdx.x & 31;
    const float* pr = part + (size_t)w * nchunk;
    float s = 0.f;
    for (int i = lane; i < nchunk; i += 32) s += pr[i];
#pragma unroll
    for (int st = 16; st > 0; st >>= 1) s += __shfl_xor_sync(0xffffffffu, s, st);
    if (lane == 0) out[w] = s;
}

// normalize K rows in place (fp32) and emit fp16 hi of K * 2^12
#define KSCALE 4096.0f
__global__ __launch_bounds__(256) void normalize_hi(
    float* __restrict__ Kmat, const float* __restrict__ rowsum,
    __half* __restrict__ Kh)
{
    size_t idx = (size_t)blockIdx.x * 256 + threadIdx.x;   // float4 index
    size_t total4 = ((size_t)NSRC * NTGT) >> 2;
    if (idx >= total4) return;
    int row = (int)(idx >> 10);                            // 1024 float4 per row
    float inv = 1.0f / rowsum[row];
    float4* p = (float4*)Kmat + idx;
    float4 v = *p;
    v.x *= inv; v.y *= inv; v.z *= inv; v.w *= inv;
    *p = v;
    unsigned short h0 = __half_as_ushort(__float2half_rn(v.x * KSCALE));
    unsigned short h1 = __half_as_ushort(__float2half_rn(v.y * KSCALE));
    unsigned short h2 = __half_as_ushort(__float2half_rn(v.z * KSCALE));
    unsigned short h3 = __half_as_ushort(__float2half_rn(v.w * KSCALE));
    ((uint2*)Kh)[idx] = make_uint2((uint32_t)h0 | ((uint32_t)h1 << 16),
                                   (uint32_t)h2 | ((uint32_t)h3 << 16));
}

// ---------------- launch -----------------------------------------------------
extern "C" void kernel_launch(void* const* d_in, const int* in_sizes, int n_in,
                              void* d_out, int out_size)
{
    const float* source = (const float*)d_in[0];
    const float* target = (const float*)d_in[1];
    const float* W_src  = (const float*)d_in[2];
    const float* b_src  = (const float*)d_in[3];
    const float* W_tgt  = (const float*)d_in[4];
    const float* b_tgt  = (const float*)d_in[5];
    const float* temp   = (const float*)d_in[6];

    float* aligned = (float*)d_out;                       // [NSRC, DIM]
    float* Kout    = (float*)d_out + (size_t)NSRC * DIM;  // [NSRC, NTGT]

    float *sqs, *sqt, *rs, *sqps, *sqpt, *krsp;
    __half *srch, *tgth, *Wsh, *Wth, *sph, *tph, *tTh, *Kh;
    cudaGetSymbolAddress((void**)&sqs,  g_sqs);
    cudaGetSymbolAddress((void**)&sqt,  g_sqt);
    cudaGetSymbolAddress((void**)&rs,   g_rowsum);
    cudaGetSymbolAddress((void**)&sqps, g_sqpart_s);
    cudaGetSymbolAddress((void**)&sqpt, g_sqpart_t);
    cudaGetSymbolAddress((void**)&krsp, g_krspart);
    cudaGetSymbolAddress((void**)&srch, g_srch);
    cudaGetSymbolAddress((void**)&tgth, g_tgth);
    cudaGetSymbolAddress((void**)&Wsh,  g_Wsh);
    cudaGetSymbolAddress((void**)&Wth,  g_Wth);
    cudaGetSymbolAddress((void**)&sph,  g_sph);
    cudaGetSymbolAddress((void**)&tph,  g_tph);
    cudaGetSymbolAddress((void**)&tTh,  g_tTh);
    cudaGetSymbolAddress((void**)&Kh,   g_Kh);

    cudaFuncSetAttribute((const void*)tc_gemm<EPI_BIAS, true>,  cudaFuncAttributeMaxDynamicSharedMemorySize, SMEM_DYN);
    cudaFuncSetAttribute((const void*)tc_gemm<EPI_COST, false>, cudaFuncAttributeMaxDynamicSharedMemorySize, SMEM_DYN);
    cudaFuncSetAttribute((const void*)tc_gemm<EPI_NONE, false>, cudaFuncAttributeMaxDynamicSharedMemorySize, SMEM_DYN);

    // 1) convert all inputs to fp16 (single launch) + transposed target
    convert_all<<<(int)((N4_ALL + 255) / 256), 256>>>(
        source, target, W_src, W_tgt, srch, tgth, Wsh, Wth);
    transpose_hi<<<dim3(DIM / 32, NTGT / 32), dim3(32, 8)>>>(target, tTh);

    // 2) both projections in ONE launch (z=0: source, z=1: target);
    //    1-pass fp16, emit fp16 hi + fused sq-norm partials
    tc_gemm<EPI_BIAS, true><<<dim3(DIM / 128, NSRC / 128, 2), 256, SMEM_DYN>>>(
        srch, Wsh, b_src, tgth, Wth, b_tgt,
        nullptr, nullptr, nullptr,
        nullptr, sph, tph, sqps, sqpt, DIM, DIM, 1.f);

    // 3) reduce both sq-norm partial sets (warp per row, one launch)
    reduce_rows_warp2<<<(NSRC + NTGT) * 32 / 256, 256>>>(sqps, sqs, sqpt, sqt, DIM / 32);

    // 4) K (unnormalized) = exp(-cdist/T): 1-pass fp16 + fused rowsum partials
    tc_gemm<EPI_COST, false><<<dim3(NTGT / 128, NSRC / 128), 256, SMEM_DYN>>>(
        sph, tph, nullptr, nullptr, nullptr, nullptr,
        sqs, sqt, temp,
        Kout, nullptr, nullptr, krsp, nullptr, NTGT, DIM, 1.f);

    // 5) reduce rowsum partials (warp per row), normalize + scaled fp16 hi of K
    reduce_rows_warp<<<NSRC * 32 / 256, 256>>>(krsp, rs, NTGT / 32);
    normalize_hi<<<(int)(((size_t)NSRC * NTGT / 4 + 255) / 256), 256>>>(Kout, rs, Kh);

    // 6) aligned = K @ target: 1-pass fp16 (Kh x target hi), scaled 2^-12
    tc_gemm<EPI_NONE, false><<<dim3(DIM / 128, NSRC / 128), 256, SMEM_DYN>>>(
        Kh, tTh, nullptr, nullptr, nullptr, nullptr,
        nullptr, nullptr, nullptr,
        aligned, nullptr, nullptr, nullptr, nullptr, DIM, NTGT, 1.0f / KSCALE);
}

// round 12
// speedup vs baseline: 3.7299x; 1.0020x over previous
#include <cuda_runtime.h>
#include <cuda_fp16.h>
#include <cstdint>
#include <cstddef>

#define NSRC 4096
#define NTGT 4096
#define DIM  1024

// ---------------- scratch (__device__ globals; no allocations allowed) -----
__device__ float g_sqs[NSRC];
__device__ float g_sqt[NTGT];
__device__ float g_sqpart_s[(size_t)NSRC * (DIM / 32)];
__device__ float g_sqpart_t[(size_t)NTGT * (DIM / 32)];
__device__ float g_krspart[(size_t)NSRC * (NTGT / 32)];

__device__ __half g_srch[(size_t)NSRC * DIM];
__device__ __half g_tgth[(size_t)NTGT * DIM];
__device__ __half g_Wsh[(size_t)DIM * DIM];
__device__ __half g_Wth[(size_t)DIM * DIM];
__device__ __half g_sph[(size_t)NSRC * DIM];
__device__ __half g_tph[(size_t)NTGT * DIM];
__device__ __half g_tTh[(size_t)DIM * NTGT];
__device__ __half g_Kh[(size_t)NSRC * NTGT];

// ---------------- helpers ----------------------------------------------------
__device__ __forceinline__ uint32_t smem_to_u32(const void* p) {
    uint32_t a;
    asm("{ .reg .u64 t; cvta.to.shared.u64 t, %1; cvt.u32.u64 %0, t; }" : "=r"(a) : "l"(p));
    return a;
}
__device__ __forceinline__ void cp_async16(uint32_t dst, const void* src) {
    asm volatile("cp.async.cg.shared.global [%0], [%1], 16;" :: "r"(dst), "l"(src) : "memory");
}
__device__ __forceinline__ void ldm4(uint32_t* r, uint32_t addr) {
    asm volatile("ldmatrix.sync.aligned.m8n8.x4.shared.b16 {%0,%1,%2,%3}, [%4];"
                 : "=r"(r[0]), "=r"(r[1]), "=r"(r[2]), "=r"(r[3]) : "r"(addr));
}
__device__ __forceinline__ void mma_f16(float* c, const uint32_t* a, const uint32_t* b) {
    asm volatile(
        "mma.sync.aligned.m16n8k16.row.col.f32.f16.f16.f32 "
        "{%0,%1,%2,%3}, {%4,%5,%6,%7}, {%8,%9}, {%0,%1,%2,%3};"
        : "+f"(c[0]), "+f"(c[1]), "+f"(c[2]), "+f"(c[3])
        : "r"(a[0]), "r"(a[1]), "r"(a[2]), "r"(a[3]), "r"(b[0]), "r"(b[1]));
}
__device__ __forceinline__ float fsqrt_ap(float x) {
    float r; asm("sqrt.approx.f32 %0, %1;" : "=f"(r) : "f"(x)); return r;
}
__device__ __forceinline__ float fex2_ap(float x) {
    float r; asm("ex2.approx.f32 %0, %1;" : "=f"(r) : "f"(x)); return r;
}

// ---------------- warp-MMA fp16 NT GEMM (single-pass hi x hi) ----------------
// C[r,c] = sum_k A[r,k]*B[c,k]; fp16 operands, fp32 accumulate.
// CTA 128x128, 8 warps (2x4), warp tile 64x32, BK=64, double-buffered cp.async
// with SINGLE __syncthreads per chunk (issue next chunk post-sync: the sync
// already orders all warps past compute(ch-1), which last used that buffer).
// Fused deterministic row partial sums at 32-col granularity.
// DUAL=true: blockIdx.z selects operand set (merged proj launch).
#define EPI_NONE 0
#define EPI_BIAS 1
#define EPI_COST 2

#define BK 64
#define ROW_BYTES 144                       // 64 halves (128B) + 16B pad
#define TILE_BYTES (128 * ROW_BYTES)        // 18432
#define SMEM_DYN (2 * 2 * TILE_BYTES)       // 73728

template <int EPI, bool DUAL>
__global__ void __launch_bounds__(256, 2) tc_gemm(
    const __half* __restrict__ Ah, const __half* __restrict__ Bh,
    const float* __restrict__ bias,
    const __half* __restrict__ A2, const __half* __restrict__ B2,
    const float* __restrict__ bias2,
    const float* __restrict__ sqa, const float* __restrict__ sqb,
    const float* __restrict__ temp,
    float* __restrict__ C,
    __half* __restrict__ Chb, __half* __restrict__ Chb2,
    float* __restrict__ partial, float* __restrict__ partial2,
    int N, int Kdim, float oscale)
{
    extern __shared__ char dsm[];
    const uint32_t sm0 = smem_to_u32(dsm);
    const int tid = threadIdx.x;
    const int wid = tid >> 5, lane = tid & 31;
    const int warpRow = wid & 1;            // 2 row-warps (64 rows each)
    const int warpCol = wid >> 1;           // 4 col-warps (32 cols each)
    const int g  = lane >> 2;
    const int qp = lane & 3;
    const int rowBase = blockIdx.y * 128;
    const int colBase = blockIdx.x * 128;

    const __half* Ause = Ah;
    const __half* Buse = Bh;
    const float*  buse = bias;
    __half* chbuse = Chb;
    float*  partuse = partial;
    if (DUAL && blockIdx.z == 1) {
        Ause = A2; Buse = B2; buse = bias2; chbuse = Chb2; partuse = partial2;
    }

    const uint32_t offA = (uint32_t)((warpRow * 64 + (lane & 7) + ((lane >> 3) & 1) * 8) * ROW_BYTES
                                     + ((lane >> 4) & 1) * 16);
    const uint32_t offB = (uint32_t)(((lane & 7) + ((lane >> 4) & 1) * 8) * ROW_BYTES
                                     + ((lane >> 3) & 1) * 16);

    const __half* basep[2] = { Ause + (size_t)rowBase * Kdim, Buse + (size_t)colBase * Kdim };

    float acc[4][4][4];
#pragma unroll
    for (int mf = 0; mf < 4; mf++)
#pragma unroll
        for (int nf = 0; nf < 4; nf++)
#pragma unroll
            for (int e = 0; e < 4; e++) acc[mf][nf][e] = 0.f;

    const int KC = Kdim / BK;               // 16

    auto issue = [&](int ch, int buf) {
        uint32_t sbase = sm0 + (uint32_t)buf * (2u * TILE_BYTES);
        int kt = ch * BK;
#pragma unroll
        for (int j = 0; j < 8; j++) {
            int id  = j * 256 + tid;          // 0..2047
            int t   = id >> 10;               // tile 0..1
            int c   = id & 1023;
            int row = c >> 3;                 // 0..127
            int seg = c & 7;                  // 0..7 (16B units)
            const void* src = basep[t] + (size_t)row * Kdim + kt + seg * 8;
            uint32_t dst = sbase + (uint32_t)t * TILE_BYTES + row * ROW_BYTES + seg * 16;
            cp_async16(dst, src);
        }
        asm volatile("cp.async.commit_group;" ::: "memory");
    };

    issue(0, 0);
#pragma unroll 1
    for (int ch = 0; ch < KC; ch++) {
        int buf = ch & 1;
        // wait for the group feeding buffer `buf` (only group in flight here)
        asm volatile("cp.async.wait_group 0;" ::: "memory");
        __syncthreads();   // loads visible to all; all warps past compute(ch-1)
        if (ch + 1 < KC) issue(ch + 1, buf ^ 1);   // overlaps compute below

        uint32_t sb = sm0 + (uint32_t)buf * (2u * TILE_BYTES);
#pragma unroll
        for (int ks = 0; ks < 4; ks++) {
            const uint32_t kof = (uint32_t)(ks * 32);
            uint32_t bh[4][2];
#pragma unroll
            for (int p = 0; p < 2; p++) {
                uint32_t nboff = (uint32_t)((warpCol * 32 + p * 16) * ROW_BYTES);
                uint32_t rh[4];
                ldm4(rh, sb + TILE_BYTES + nboff + offB + kof);
                bh[p * 2][0] = rh[0]; bh[p * 2][1] = rh[1];
                bh[p * 2 + 1][0] = rh[2]; bh[p * 2 + 1][1] = rh[3];
            }
#pragma unroll
            for (int mf = 0; mf < 4; mf++) {
                uint32_t mof = (uint32_t)(mf * 16 * ROW_BYTES);
                uint32_t ah[4];
                ldm4(ah, sb + mof + offA + kof);
#pragma unroll
                for (int nf = 0; nf < 4; nf++) mma_f16(acc[mf][nf], ah, bh[nf]);
            }
        }
    }

    // ---- epilogue (with fused deterministic row partial sums) ---------------
    // cost: exp(-sqrt(d2)/T) = ex2(-sqrt(d2) * log2(e)/T)
    const float cT = (EPI == EPI_COST) ? (1.44269504088896340736f / temp[0]) : 0.f;
    const int nchunk = N >> 5;
    const int chunkIdx = (colBase >> 5) + warpCol;
#pragma unroll
    for (int mf = 0; mf < 4; mf++) {
#pragma unroll
        for (int half = 0; half < 2; half++) {
            int r = rowBase + warpRow * 64 + mf * 16 + g + half * 8;
            float sa = (EPI == EPI_COST) ? sqa[r] : 0.f;
            float rs = 0.f;
#pragma unroll
            for (int nf = 0; nf < 4; nf++) {
                int c0 = colBase + warpCol * 32 + nf * 8 + qp * 2;
                float v0 = acc[mf][nf][half * 2 + 0];
                float v1 = acc[mf][nf][half * 2 + 1];
                if (EPI == EPI_COST) {
                    float d20 = sa + sqb[c0 + 0] - 2.0f * v0;
                    float d21 = sa + sqb[c0 + 1] - 2.0f * v1;
                    v0 = fex2_ap(-fsqrt_ap(fmaxf(d20, 0.0f)) * cT);
                    v1 = fex2_ap(-fsqrt_ap(fmaxf(d21, 0.0f)) * cT);
                    *(float2*)(C + (size_t)r * N + c0) = make_float2(v0, v1);
                    rs += v0 + v1;
                } else if (EPI == EPI_BIAS) {
                    v0 += buse[c0 + 0];
                    v1 += buse[c0 + 1];
                    unsigned short h0 = __half_as_ushort(__float2half_rn(v0));
                    unsigned short h1 = __half_as_ushort(__float2half_rn(v1));
                    *(uint32_t*)(chbuse + (size_t)r * N + c0) =
                        (uint32_t)h0 | ((uint32_t)h1 << 16);
                    rs += v0 * v0 + v1 * v1;
                } else {
                    *(float2*)(C + (size_t)r * N + c0) =
                        make_float2(v0 * oscale, v1 * oscale);
                }
            }
            if (EPI != EPI_NONE) {
                rs += __shfl_xor_sync(0xffffffffu, rs, 1);
                rs += __shfl_xor_sync(0xffffffffu, rs, 2);
                if (qp == 0) partuse[(size_t)r * nchunk + chunkIdx] = rs;
            }
        }
    }
}

// ---------------- small kernels ---------------------------------------------
// all four fp32->fp16 conversions in one launch (range dispatch, float4 units)
#define N4_SRC ((size_t)NSRC * DIM / 4)     // 1048576
#define N4_TGT ((size_t)NTGT * DIM / 4)     // 1048576
#define N4_W   ((size_t)DIM * DIM / 4)      // 262144
#define N4_ALL (N4_SRC + N4_TGT + 2 * N4_W) // 2621440
__global__ __launch_bounds__(256) void convert_all(
    const float* __restrict__ src, const float* __restrict__ tgt,
    const float* __restrict__ ws, const float* __restrict__ wt,
    __half* __restrict__ osrc, __half* __restrict__ otgt,
    __half* __restrict__ ows, __half* __restrict__ owt)
{
    size_t i = (size_t)blockIdx.x * 256 + threadIdx.x;
    if (i >= N4_ALL) return;
    const float* in;
    __half* oh;
    size_t j = i;
    if (j < N4_SRC) { in = src; oh = osrc; }
    else if ((j -= N4_SRC) < N4_TGT) { in = tgt; oh = otgt; }
    else if ((j -= N4_TGT) < N4_W) { in = ws; oh = ows; }
    else { j -= N4_W; in = wt; oh = owt; }
    float4 v = ((const float4*)in)[j];
    unsigned short h0 = __half_as_ushort(__float2half_rn(v.x));
    unsigned short h1 = __half_as_ushort(__float2half_rn(v.y));
    unsigned short h2 = __half_as_ushort(__float2half_rn(v.z));
    unsigned short h3 = __half_as_ushort(__float2half_rn(v.w));
    ((uint2*)oh)[j] = make_uint2((uint32_t)h0 | ((uint32_t)h1 << 16),
                                 (uint32_t)h2 | ((uint32_t)h3 << 16));
}

// target [NTGT][DIM] fp32 -> hi fp16 [DIM][NTGT]
__global__ void transpose_hi(const float* __restrict__ in,
                             __half* __restrict__ oh)
{
    __shared__ float t[32][33];
    int x  = blockIdx.x * 32 + threadIdx.x;
    int y0 = blockIdx.y * 32;
#pragma unroll
    for (int i = 0; i < 4; i++)
        t[threadIdx.y + i * 8][threadIdx.x] = in[(size_t)(y0 + threadIdx.y + i * 8) * DIM + x];
    __syncthreads();
    int ox  = y0 + threadIdx.x;
    int oy0 = blockIdx.x * 32;
#pragma unroll
    for (int i = 0; i < 4; i++) {
        float v = t[threadIdx.x][threadIdx.y + i * 8];
        size_t o = (size_t)(oy0 + threadIdx.y + i * 8) * NTGT + ox;
        oh[o] = __float2half_rn(v);
    }
}

// warp-per-row deterministic reduce (fixed shuffle tree order every run).
// rows [0,NSRC) from partA -> outA ; rows [NSRC, NSRC+NTGT) from partB -> outB
__global__ __launch_bounds__(256) void reduce_rows_warp2(
    const float* __restrict__ partA, float* __restrict__ outA,
    const float* __restrict__ partB, float* __restrict__ outB, int nchunk)
{
    int w = (int)((blockIdx.x * blockDim.x + threadIdx.x) >> 5);
    int lane = threadIdx.x & 31;
    const float* p;
    float* o;
    int r = w;
    if (w < NSRC) { p = partA; o = outA; }
    else          { p = partB; o = outB; r = w - NSRC; }
    const float* pr = p + (size_t)r * nchunk;
    float s = 0.f;
    for (int i = lane; i < nchunk; i += 32) s += pr[i];
#pragma unroll
    for (int st = 16; st > 0; st >>= 1) s += __shfl_xor_sync(0xffffffffu, s, st);
    if (lane == 0) o[r] = s;
}

// block-per-row: deterministically reduce this row's 128 rowsum partials,
// then normalize the row in place (fp32) and emit fp16 hi of K*2^12.
#define KSCALE 4096.0f
__global__ __launch_bounds__(256) void normalize_fused(
    float* __restrict__ Kmat, const float* __restrict__ part,
    __half* __restrict__ Kh)
{
    const int row = blockIdx.x;
    const int tid = threadIdx.x;
    const int lane = tid & 31;
    __shared__ float sinv;
    if (tid < 32) {   // warp 0: deterministic fixed-order reduce of 128 partials
        const float* pr = part + (size_t)row * (NTGT / 32);
        float s = 0.f;
#pragma unroll
        for (int i = 0; i < 4; i++) s += pr[lane + i * 32];
#pragma unroll
        for (int st = 16; st > 0; st >>= 1) s += __shfl_xor_sync(0xffffffffu, s, st);
        if (lane == 0) sinv = 1.0f / s;
    }
    __syncthreads();
    const float inv = sinv;
    float4* prow = (float4*)(Kmat + (size_t)row * NTGT);
    uint2*  hrow = (uint2*)(Kh + (size_t)row * NTGT);
#pragma unroll
    for (int i = 0; i < 4; i++) {
        int idx = tid + i * 256;              // 0..1023 float4 per row
        float4 v = prow[idx];
        v.x *= inv; v.y *= inv; v.z *= inv; v.w *= inv;
        prow[idx] = v;
        unsigned short h0 = __half_as_ushort(__float2half_rn(v.x * KSCALE));
        unsigned short h1 = __half_as_ushort(__float2half_rn(v.y * KSCALE));
        unsigned short h2 = __half_as_ushort(__float2half_rn(v.z * KSCALE));
        unsigned short h3 = __half_as_ushort(__float2half_rn(v.w * KSCALE));
        hrow[idx] = make_uint2((uint32_t)h0 | ((uint32_t)h1 << 16),
                               (uint32_t)h2 | ((uint32_t)h3 << 16));
    }
}

// ---------------- launch -----------------------------------------------------
extern "C" void kernel_launch(void* const* d_in, const int* in_sizes, int n_in,
                              void* d_out, int out_size)
{
    const float* source = (const float*)d_in[0];
    const float* target = (const float*)d_in[1];
    const float* W_src  = (const float*)d_in[2];
    const float* b_src  = (const float*)d_in[3];
    const float* W_tgt  = (const float*)d_in[4];
    const float* b_tgt  = (const float*)d_in[5];
    const float* temp   = (const float*)d_in[6];

    float* aligned = (float*)d_out;                       // [NSRC, DIM]
    float* Kout    = (float*)d_out + (size_t)NSRC * DIM;  // [NSRC, NTGT]

    float *sqs, *sqt, *sqps, *sqpt, *krsp;
    __half *srch, *tgth, *Wsh, *Wth, *sph, *tph, *tTh, *Kh;
    cudaGetSymbolAddress((void**)&sqs,  g_sqs);
    cudaGetSymbolAddress((void**)&sqt,  g_sqt);
    cudaGetSymbolAddress((void**)&sqps, g_sqpart_s);
    cudaGetSymbolAddress((void**)&sqpt, g_sqpart_t);
    cudaGetSymbolAddress((void**)&krsp, g_krspart);
    cudaGetSymbolAddress((void**)&srch, g_srch);
    cudaGetSymbolAddress((void**)&tgth, g_tgth);
    cudaGetSymbolAddress((void**)&Wsh,  g_Wsh);
    cudaGetSymbolAddress((void**)&Wth,  g_Wth);
    cudaGetSymbolAddress((void**)&sph,  g_sph);
    cudaGetSymbolAddress((void**)&tph,  g_tph);
    cudaGetSymbolAddress((void**)&tTh,  g_tTh);
    cudaGetSymbolAddress((void**)&Kh,   g_Kh);

    cudaFuncSetAttribute((const void*)tc_gemm<EPI_BIAS, true>,  cudaFuncAttributeMaxDynamicSharedMemorySize, SMEM_DYN);
    cudaFuncSetAttribute((const void*)tc_gemm<EPI_COST, false>, cudaFuncAttributeMaxDynamicSharedMemorySize, SMEM_DYN);
    cudaFuncSetAttribute((const void*)tc_gemm<EPI_NONE, false>, cudaFuncAttributeMaxDynamicSharedMemorySize, SMEM_DYN);

    // 1) convert all inputs to fp16 (single launch) + transposed target
    convert_all<<<(int)((N4_ALL + 255) / 256), 256>>>(
        source, target, W_src, W_tgt, srch, tgth, Wsh, Wth);
    transpose_hi<<<dim3(DIM / 32, NTGT / 32), dim3(32, 8)>>>(target, tTh);

    // 2) both projections in ONE launch (z=0: source, z=1: target);
    //    1-pass fp16, emit fp16 hi + fused sq-norm partials
    tc_gemm<EPI_BIAS, true><<<dim3(DIM / 128, NSRC / 128, 2), 256, SMEM_DYN>>>(
        srch, Wsh, b_src, tgth, Wth, b_tgt,
        nullptr, nullptr, nullptr,
        nullptr, sph, tph, sqps, sqpt, DIM, DIM, 1.f);

    // 3) reduce both sq-norm partial sets (warp per row, one launch)
    reduce_rows_warp2<<<(NSRC + NTGT) * 32 / 256, 256>>>(sqps, sqs, sqpt, sqt, DIM / 32);

    // 4) K (unnormalized) = exp(-cdist/T): 1-pass fp16 + fused rowsum partials
    tc_gemm<EPI_COST, false><<<dim3(NTGT / 128, NSRC / 128), 256, SMEM_DYN>>>(
        sph, tph, nullptr, nullptr, nullptr, nullptr,
        sqs, sqt, temp,
        Kout, nullptr, nullptr, krsp, nullptr, NTGT, DIM, 1.f);

    // 5) fused: per-row rowsum reduce + normalize + scaled fp16 hi of K
    normalize_fused<<<NSRC, 256>>>(Kout, krsp, Kh);

    // 6) aligned = K @ target: 1-pass fp16 (Kh x target hi), scaled 2^-12
    tc_gemm<EPI_NONE, false><<<dim3(DIM / 128, NSRC / 128), 256, SMEM_DYN>>>(
        Kh, tTh, nullptr, nullptr, nullptr, nullptr,
        nullptr, nullptr, nullptr,
        aligned, nullptr, nullptr, nullptr, nullptr, DIM, NTGT, 1.0f / KSCALE);
}

// round 13
// speedup vs baseline: 3.7540x; 1.0065x over previous
#include <cuda_runtime.h>
#include <cuda_fp16.h>
#include <cstdint>
#include <cstddef>

#define NSRC 4096
#define NTGT 4096
#define DIM  1024

// ---------------- scratch (__device__ globals; no allocations allowed) -----
__device__ float g_sqs[NSRC];
__device__ float g_sqt[NTGT];
__device__ float g_sbavg[1];
__device__ float g_invrs[NSRC];
__device__ float g_sqpart_s[(size_t)NSRC * (DIM / 32)];
__device__ float g_sqpart_t[(size_t)NTGT * (DIM / 32)];
__device__ float g_krspart[(size_t)NSRC * (NTGT / 32)];

__device__ __half g_srch[(size_t)NSRC * DIM];
__device__ __half g_tgth[(size_t)NTGT * DIM];
__device__ __half g_Wsh[(size_t)DIM * DIM];
__device__ __half g_Wth[(size_t)DIM * DIM];
__device__ __half g_sph[(size_t)NSRC * DIM];
__device__ __half g_tph[(size_t)NTGT * DIM];
__device__ __half g_tTh[(size_t)DIM * NTGT];
__device__ __half g_Kh[(size_t)NSRC * NTGT];    // row-prescaled fp16 K (S_r cancels)

// ---------------- helpers ----------------------------------------------------
__device__ __forceinline__ uint32_t smem_to_u32(const void* p) {
    uint32_t a;
    asm("{ .reg .u64 t; cvta.to.shared.u64 t, %1; cvt.u32.u64 %0, t; }" : "=r"(a) : "l"(p));
    return a;
}
__device__ __forceinline__ void cp_async16(uint32_t dst, const void* src) {
    asm volatile("cp.async.cg.shared.global [%0], [%1], 16;" :: "r"(dst), "l"(src) : "memory");
}
__device__ __forceinline__ void ldm4(uint32_t* r, uint32_t addr) {
    asm volatile("ldmatrix.sync.aligned.m8n8.x4.shared.b16 {%0,%1,%2,%3}, [%4];"
                 : "=r"(r[0]), "=r"(r[1]), "=r"(r[2]), "=r"(r[3]) : "r"(addr));
}
__device__ __forceinline__ void mma_f16(float* c, const uint32_t* a, const uint32_t* b) {
    asm volatile(
        "mma.sync.aligned.m16n8k16.row.col.f32.f16.f16.f32 "
        "{%0,%1,%2,%3}, {%4,%5,%6,%7}, {%8,%9}, {%0,%1,%2,%3};"
        : "+f"(c[0]), "+f"(c[1]), "+f"(c[2]), "+f"(c[3])
        : "r"(a[0]), "r"(a[1]), "r"(a[2]), "r"(a[3]), "r"(b[0]), "r"(b[1]));
}
__device__ __forceinline__ float fsqrt_ap(float x) {
    float r; asm("sqrt.approx.f32 %0, %1;" : "=f"(r) : "f"(x)); return r;
}
__device__ __forceinline__ float fex2_ap(float x) {
    float r; asm("ex2.approx.f32 %0, %1;" : "=f"(r) : "f"(x)); return r;
}

// ---------------- warp-MMA fp16 NT GEMM (single-pass hi x hi) ----------------
// C[r,c] = sum_k A[r,k]*B[c,k]; fp16 operands, fp32 accumulate.
// CTA 128x128, 8 warps (2x4), warp tile 64x32, BK=64, double-buffered cp.async,
// single __syncthreads per chunk. Fused deterministic row partial sums.
// EPI_BIAS: +bias, emit fp16 hi + sum(v^2) partials (DUAL merges 2 problems).
// EPI_COST: v = ex2(e_r - d*cT) (row-prescaled kernel value), write fp16 ONLY
//           + sum(v) partials. e_r = rint(cT*sqrt(sqa[r]+sbavg)) is row-constant;
//           the 2^e_r prescale cancels in normalization.
// EPI_ROWS: out = v * rowscale[r]  (normalization fused into aligned GEMM).
#define EPI_ROWS 0
#define EPI_BIAS 1
#define EPI_COST 2

#define BK 64
#define ROW_BYTES 144                       // 64 halves (128B) + 16B pad
#define TILE_BYTES (128 * ROW_BYTES)        // 18432
#define SMEM_DYN (2 * 2 * TILE_BYTES)       // 73728

template <int EPI, bool DUAL>
__global__ void __launch_bounds__(256, 2) tc_gemm(
    const __half* __restrict__ Ah, const __half* __restrict__ Bh,
    const float* __restrict__ bias,
    const __half* __restrict__ A2, const __half* __restrict__ B2,
    const float* __restrict__ bias2,
    const float* __restrict__ sqa, const float* __restrict__ sqb,
    const float* __restrict__ temp, const float* __restrict__ sbavg,
    float* __restrict__ C,
    __half* __restrict__ Chb, __half* __restrict__ Chb2,
    float* __restrict__ partial, float* __restrict__ partial2,
    int N, int Kdim)
{
    extern __shared__ char dsm[];
    const uint32_t sm0 = smem_to_u32(dsm);
    const int tid = threadIdx.x;
    const int wid = tid >> 5, lane = tid & 31;
    const int warpRow = wid & 1;            // 2 row-warps (64 rows each)
    const int warpCol = wid >> 1;           // 4 col-warps (32 cols each)
    const int g  = lane >> 2;
    const int qp = lane & 3;
    const int rowBase = blockIdx.y * 128;
    const int colBase = blockIdx.x * 128;

    const __half* Ause = Ah;
    const __half* Buse = Bh;
    const float*  buse = bias;
    __half* chbuse = Chb;
    float*  partuse = partial;
    if (DUAL && blockIdx.z == 1) {
        Ause = A2; Buse = B2; buse = bias2; chbuse = Chb2; partuse = partial2;
    }

    const uint32_t offA = (uint32_t)((warpRow * 64 + (lane & 7) + ((lane >> 3) & 1) * 8) * ROW_BYTES
                                     + ((lane >> 4) & 1) * 16);
    const uint32_t offB = (uint32_t)(((lane & 7) + ((lane >> 4) & 1) * 8) * ROW_BYTES
                                     + ((lane >> 3) & 1) * 16);

    const __half* basep[2] = { Ause + (size_t)rowBase * Kdim, Buse + (size_t)colBase * Kdim };

    float acc[4][4][4];
#pragma unroll
    for (int mf = 0; mf < 4; mf++)
#pragma unroll
        for (int nf = 0; nf < 4; nf++)
#pragma unroll
            for (int e = 0; e < 4; e++) acc[mf][nf][e] = 0.f;

    const int KC = Kdim / BK;

    auto issue = [&](int ch, int buf) {
        uint32_t sbase = sm0 + (uint32_t)buf * (2u * TILE_BYTES);
        int kt = ch * BK;
#pragma unroll
        for (int j = 0; j < 8; j++) {
            int id  = j * 256 + tid;
            int t   = id >> 10;
            int c   = id & 1023;
            int row = c >> 3;
            int seg = c & 7;
            const void* src = basep[t] + (size_t)row * Kdim + kt + seg * 8;
            uint32_t dst = sbase + (uint32_t)t * TILE_BYTES + row * ROW_BYTES + seg * 16;
            cp_async16(dst, src);
        }
        asm volatile("cp.async.commit_group;" ::: "memory");
    };

    issue(0, 0);
#pragma unroll 1
    for (int ch = 0; ch < KC; ch++) {
        int buf = ch & 1;
        asm volatile("cp.async.wait_group 0;" ::: "memory");
        __syncthreads();
        if (ch + 1 < KC) issue(ch + 1, buf ^ 1);

        uint32_t sb = sm0 + (uint32_t)buf * (2u * TILE_BYTES);
#pragma unroll
        for (int ks = 0; ks < 4; ks++) {
            const uint32_t kof = (uint32_t)(ks * 32);
            uint32_t bh[4][2];
#pragma unroll
            for (int p = 0; p < 2; p++) {
                uint32_t nboff = (uint32_t)((warpCol * 32 + p * 16) * ROW_BYTES);
                uint32_t rh[4];
                ldm4(rh, sb + TILE_BYTES + nboff + offB + kof);
                bh[p * 2][0] = rh[0]; bh[p * 2][1] = rh[1];
                bh[p * 2 + 1][0] = rh[2]; bh[p * 2 + 1][1] = rh[3];
            }
#pragma unroll
            for (int mf = 0; mf < 4; mf++) {
                uint32_t mof = (uint32_t)(mf * 16 * ROW_BYTES);
                uint32_t ah[4];
                ldm4(ah, sb + mof + offA + kof);
#pragma unroll
                for (int nf = 0; nf < 4; nf++) mma_f16(acc[mf][nf], ah, bh[nf]);
            }
        }
    }

    // ---- epilogue ------------------------------------------------------------
    const float cT = (EPI == EPI_COST) ? (1.44269504088896340736f / temp[0]) : 0.f;
    const float sbav = (EPI == EPI_COST) ? sbavg[0] : 0.f;
    const int nchunk = N >> 5;
    const int chunkIdx = (colBase >> 5) + warpCol;
#pragma unroll
    for (int mf = 0; mf < 4; mf++) {
#pragma unroll
        for (int half = 0; half < 2; half++) {
            int r = rowBase + warpRow * 64 + mf * 16 + g + half * 8;
            float sa = 0.f, er = 0.f, rowsc = 0.f;
            if (EPI == EPI_COST) {
                sa = sqa[r];
                er = rintf(fsqrt_ap(sa + sbav) * cT);   // row-constant prescale exp
            } else if (EPI == EPI_ROWS) {
                rowsc = sqa[r];                          // invrs[r]
            }
            float rs = 0.f;
#pragma unroll
            for (int nf = 0; nf < 4; nf++) {
                int c0 = colBase + warpCol * 32 + nf * 8 + qp * 2;
                float v0 = acc[mf][nf][half * 2 + 0];
                float v1 = acc[mf][nf][half * 2 + 1];
                if (EPI == EPI_COST) {
                    float d20 = sa + sqb[c0 + 0] - 2.0f * v0;
                    float d21 = sa + sqb[c0 + 1] - 2.0f * v1;
                    v0 = fex2_ap(er - fsqrt_ap(fmaxf(d20, 0.0f)) * cT);
                    v1 = fex2_ap(er - fsqrt_ap(fmaxf(d21, 0.0f)) * cT);
                    unsigned short h0 = __half_as_ushort(__float2half_rn(v0));
                    unsigned short h1 = __half_as_ushort(__float2half_rn(v1));
                    *(uint32_t*)(chbuse + (size_t)r * N + c0) =
                        (uint32_t)h0 | ((uint32_t)h1 << 16);
                    rs += v0 + v1;
                } else if (EPI == EPI_BIAS) {
                    v0 += buse[c0 + 0];
                    v1 += buse[c0 + 1];
                    unsigned short h0 = __half_as_ushort(__float2half_rn(v0));
                    unsigned short h1 = __half_as_ushort(__float2half_rn(v1));
                    *(uint32_t*)(chbuse + (size_t)r * N + c0) =
                        (uint32_t)h0 | ((uint32_t)h1 << 16);
                    rs += v0 * v0 + v1 * v1;
                } else {   // EPI_ROWS
                    *(float2*)(C + (size_t)r * N + c0) =
                        make_float2(v0 * rowsc, v1 * rowsc);
                }
            }
            if (EPI != EPI_ROWS) {
                rs += __shfl_xor_sync(0xffffffffu, rs, 1);
                rs += __shfl_xor_sync(0xffffffffu, rs, 2);
                if (qp == 0) partuse[(size_t)r * nchunk + chunkIdx] = rs;
            }
        }
    }
}

// ---------------- small kernels ---------------------------------------------
#define N4_SRC ((size_t)NSRC * DIM / 4)
#define N4_TGT ((size_t)NTGT * DIM / 4)
#define N4_W   ((size_t)DIM * DIM / 4)
#define N4_ALL (N4_SRC + N4_TGT + 2 * N4_W)
__global__ __launch_bounds__(256) void convert_all(
    const float* __restrict__ src, const float* __restrict__ tgt,
    const float* __restrict__ ws, const float* __restrict__ wt,
    __half* __restrict__ osrc, __half* __restrict__ otgt,
    __half* __restrict__ ows, __half* __restrict__ owt)
{
    size_t i = (size_t)blockIdx.x * 256 + threadIdx.x;
    if (i >= N4_ALL) return;
    const float* in;
    __half* oh;
    size_t j = i;
    if (j < N4_SRC) { in = src; oh = osrc; }
    else if ((j -= N4_SRC) < N4_TGT) { in = tgt; oh = otgt; }
    else if ((j -= N4_TGT) < N4_W) { in = ws; oh = ows; }
    else { j -= N4_W; in = wt; oh = owt; }
    float4 v = ((const float4*)in)[j];
    unsigned short h0 = __half_as_ushort(__float2half_rn(v.x));
    unsigned short h1 = __half_as_ushort(__float2half_rn(v.y));
    unsigned short h2 = __half_as_ushort(__float2half_rn(v.z));
    unsigned short h3 = __half_as_ushort(__float2half_rn(v.w));
    ((uint2*)oh)[j] = make_uint2((uint32_t)h0 | ((uint32_t)h1 << 16),
                                 (uint32_t)h2 | ((uint32_t)h3 << 16));
}

__global__ void transpose_hi(const float* __restrict__ in,
                             __half* __restrict__ oh)
{
    __shared__ float t[32][33];
    int x  = blockIdx.x * 32 + threadIdx.x;
    int y0 = blockIdx.y * 32;
#pragma unroll
    for (int i = 0; i < 4; i++)
        t[threadIdx.y + i * 8][threadIdx.x] = in[(size_t)(y0 + threadIdx.y + i * 8) * DIM + x];
    __syncthreads();
    int ox  = y0 + threadIdx.x;
    int oy0 = blockIdx.x * 32;
#pragma unroll
    for (int i = 0; i < 4; i++) {
        float v = t[threadIdx.x][threadIdx.y + i * 8];
        size_t o = (size_t)(oy0 + threadIdx.y + i * 8) * NTGT + ox;
        oh[o] = __float2half_rn(v);
    }
}

// warp-per-row deterministic reduce (fixed shuffle tree order every run).
__global__ __launch_bounds__(256) void reduce_rows_warp2(
    const float* __restrict__ partA, float* __restrict__ outA,
    const float* __restrict__ partB, float* __restrict__ outB, int nchunk)
{
    int w = (int)((blockIdx.x * blockDim.x + threadIdx.x) >> 5);
    int lane = threadIdx.x & 31;
    const float* p;
    float* o;
    int r = w;
    if (w < NSRC) { p = partA; o = outA; }
    else          { p = partB; o = outB; r = w - NSRC; }
    const float* pr = p + (size_t)r * nchunk;
    float s = 0.f;
    for (int i = lane; i < nchunk; i += 32) s += pr[i];
#pragma unroll
    for (int st = 16; st > 0; st >>= 1) s += __shfl_xor_sync(0xffffffffu, s, st);
    if (lane == 0) o[r] = s;
}

// deterministic mean of a vector (1 block)
__global__ __launch_bounds__(256) void avg_vec(
    const float* __restrict__ in, float* __restrict__ out, int n)
{
    __shared__ float red[256];
    float s = 0.f;
    for (int i = threadIdx.x; i < n; i += 256) s += in[i];
    red[threadIdx.x] = s;
    __syncthreads();
#pragma unroll
    for (int st = 128; st > 0; st >>= 1) {
        if (threadIdx.x < st) red[threadIdx.x] += red[threadIdx.x + st];
        __syncthreads();
    }
    if (threadIdx.x == 0) out[0] = red[0] / (float)n;
}

// warp-per-row: reduce 128 rowsum partials -> write 1/rowsum (deterministic)
__global__ __launch_bounds__(256) void reduce_inv(
    const float* __restrict__ part, float* __restrict__ out, int nchunk)
{
    int w = (int)((blockIdx.x * blockDim.x + threadIdx.x) >> 5);
    int lane = threadIdx.x & 31;
    const float* pr = part + (size_t)w * nchunk;
    float s = 0.f;
    for (int i = lane; i < nchunk; i += 32) s += pr[i];
#pragma unroll
    for (int st = 16; st > 0; st >>= 1) s += __shfl_xor_sync(0xffffffffu, s, st);
    if (lane == 0) out[w] = 1.0f / s;
}

// fp32 K output: K[r,c] = h2f(Kh_s[r,c]) * invrs[r]  (prescale cancels)
__global__ __launch_bounds__(256) void k_out(
    const __half* __restrict__ Kh, const float* __restrict__ invrs,
    float* __restrict__ Kmat)
{
    size_t idx = (size_t)blockIdx.x * 256 + threadIdx.x;   // uint2 = 4 halves
    size_t total = ((size_t)NSRC * NTGT) >> 2;
    if (idx >= total) return;
    int row = (int)(idx >> 10);                            // 1024 uint2 per row
    float inv = invrs[row];
    uint2 h = ((const uint2*)Kh)[idx];
    float4 v;
    v.x = __half2float(__ushort_as_half((unsigned short)(h.x & 0xffff))) * inv;
    v.y = __half2float(__ushort_as_half((unsigned short)(h.x >> 16))) * inv;
    v.z = __half2float(__ushort_as_half((unsigned short)(h.y & 0xffff))) * inv;
    v.w = __half2float(__ushort_as_half((unsigned short)(h.y >> 16))) * inv;
    ((float4*)Kmat)[idx] = v;
}

// ---------------- launch -----------------------------------------------------
extern "C" void kernel_launch(void* const* d_in, const int* in_sizes, int n_in,
                              void* d_out, int out_size)
{
    const float* source = (const float*)d_in[0];
    const float* target = (const float*)d_in[1];
    const float* W_src  = (const float*)d_in[2];
    const float* b_src  = (const float*)d_in[3];
    const float* W_tgt  = (const float*)d_in[4];
    const float* b_tgt  = (const float*)d_in[5];
    const float* temp   = (const float*)d_in[6];

    float* aligned = (float*)d_out;                       // [NSRC, DIM]
    float* Kout    = (float*)d_out + (size_t)NSRC * DIM;  // [NSRC, NTGT]

    float *sqs, *sqt, *sbavg, *invrs, *sqps, *sqpt, *krsp;
    __half *srch, *tgth, *Wsh, *Wth, *sph, *tph, *tTh, *Kh;
    cudaGetSymbolAddress((void**)&sqs,   g_sqs);
    cudaGetSymbolAddress((void**)&sqt,   g_sqt);
    cudaGetSymbolAddress((void**)&sbavg, g_sbavg);
    cudaGetSymbolAddress((void**)&invrs, g_invrs);
    cudaGetSymbolAddress((void**)&sqps,  g_sqpart_s);
    cudaGetSymbolAddress((void**)&sqpt,  g_sqpart_t);
    cudaGetSymbolAddress((void**)&krsp,  g_krspart);
    cudaGetSymbolAddress((void**)&srch,  g_srch);
    cudaGetSymbolAddress((void**)&tgth,  g_tgth);
    cudaGetSymbolAddress((void**)&Wsh,   g_Wsh);
    cudaGetSymbolAddress((void**)&Wth,   g_Wth);
    cudaGetSymbolAddress((void**)&sph,   g_sph);
    cudaGetSymbolAddress((void**)&tph,   g_tph);
    cudaGetSymbolAddress((void**)&tTh,   g_tTh);
    cudaGetSymbolAddress((void**)&Kh,    g_Kh);

    cudaFuncSetAttribute((const void*)tc_gemm<EPI_BIAS, true>,  cudaFuncAttributeMaxDynamicSharedMemorySize, SMEM_DYN);
    cudaFuncSetAttribute((const void*)tc_gemm<EPI_COST, false>, cudaFuncAttributeMaxDynamicSharedMemorySize, SMEM_DYN);
    cudaFuncSetAttribute((const void*)tc_gemm<EPI_ROWS, false>, cudaFuncAttributeMaxDynamicSharedMemorySize, SMEM_DYN);

    // 1) convert all inputs to fp16 + transposed target
    convert_all<<<(int)((N4_ALL + 255) / 256), 256>>>(
        source, target, W_src, W_tgt, srch, tgth, Wsh, Wth);
    transpose_hi<<<dim3(DIM / 32, NTGT / 32), dim3(32, 8)>>>(target, tTh);

    // 2) both projections in ONE launch; emit fp16 hi + fused sq-norm partials
    tc_gemm<EPI_BIAS, true><<<dim3(DIM / 128, NSRC / 128, 2), 256, SMEM_DYN>>>(
        srch, Wsh, b_src, tgth, Wth, b_tgt,
        nullptr, nullptr, nullptr, nullptr,
        nullptr, sph, tph, sqps, sqpt, DIM, DIM);

    // 3) reduce sq-norm partials; mean of sqt for the row prescale
    reduce_rows_warp2<<<(NSRC + NTGT) * 32 / 256, 256>>>(sqps, sqs, sqpt, sqt, DIM / 32);
    avg_vec<<<1, 256>>>(sqt, sbavg, NTGT);

    // 4) cost GEMM: writes row-prescaled fp16 K ONLY + scaled rowsum partials
    tc_gemm<EPI_COST, false><<<dim3(NTGT / 128, NSRC / 128), 256, SMEM_DYN>>>(
        sph, tph, nullptr, nullptr, nullptr, nullptr,
        sqs, sqt, temp, sbavg,
        nullptr, Kh, nullptr, krsp, nullptr, NTGT, DIM);

    // 5) invrs[r] = 1 / scaled rowsum  (prescale cancels in all consumers)
    reduce_inv<<<NSRC * 32 / 256, 256>>>(krsp, invrs, NTGT / 32);

    // 6) aligned = (Kh_s @ target) * invrs[r]  (normalization fused)
    tc_gemm<EPI_ROWS, false><<<dim3(DIM / 128, NSRC / 128), 256, SMEM_DYN>>>(
        Kh, tTh, nullptr, nullptr, nullptr, nullptr,
        invrs, nullptr, nullptr, nullptr,
        aligned, nullptr, nullptr, nullptr, nullptr, DIM, NTGT);

    // 7) fp32 K output from fp16 prescaled values
    k_out<<<(int)(((size_t)NSRC * NTGT / 4 + 255) / 256), 256>>>(Kh, invrs, Kout);
}

// round 14
// speedup vs baseline: 3.9325x; 1.0475x over previous
#include <cuda_runtime.h>
#include <cuda_fp16.h>
#include <cstdint>
#include <cstddef>

#define NSRC 4096
#define NTGT 4096
#define DIM  1024

// ---------------- scratch (__device__ globals; no allocations allowed) -----
__device__ float g_sqs[NSRC];
__device__ float g_sqt[NTGT];
__device__ float g_sbavg[1];
__device__ float g_invrs[NSRC];
__device__ float g_sqpart_s[(size_t)NSRC * (DIM / 32)];
__device__ float g_sqpart_t[(size_t)NTGT * (DIM / 32)];
__device__ float g_krspart[(size_t)NSRC * (NTGT / 32)];

__device__ __half g_srch[(size_t)NSRC * DIM];
__device__ __half g_tgth[(size_t)NTGT * DIM];
__device__ __half g_Wsh[(size_t)DIM * DIM];
__device__ __half g_Wth[(size_t)DIM * DIM];
__device__ __half g_sph[(size_t)NSRC * DIM];
__device__ __half g_tph[(size_t)NTGT * DIM];
__device__ __half g_tTh[(size_t)DIM * NTGT];
__device__ __half g_Kh[(size_t)NSRC * NTGT];    // row-prescaled fp16 K (S_r cancels)

// ---------------- helpers ----------------------------------------------------
__device__ __forceinline__ uint32_t smem_to_u32(const void* p) {
    uint32_t a;
    asm("{ .reg .u64 t; cvta.to.shared.u64 t, %1; cvt.u32.u64 %0, t; }" : "=r"(a) : "l"(p));
    return a;
}
__device__ __forceinline__ void cp_async16(uint32_t dst, const void* src) {
    asm volatile("cp.async.cg.shared.global [%0], [%1], 16;" :: "r"(dst), "l"(src) : "memory");
}
__device__ __forceinline__ void ldm4(uint32_t* r, uint32_t addr) {
    asm volatile("ldmatrix.sync.aligned.m8n8.x4.shared.b16 {%0,%1,%2,%3}, [%4];"
                 : "=r"(r[0]), "=r"(r[1]), "=r"(r[2]), "=r"(r[3]) : "r"(addr));
}
__device__ __forceinline__ void mma_f16(float* c, const uint32_t* a, const uint32_t* b) {
    asm volatile(
        "mma.sync.aligned.m16n8k16.row.col.f32.f16.f16.f32 "
        "{%0,%1,%2,%3}, {%4,%5,%6,%7}, {%8,%9}, {%0,%1,%2,%3};"
        : "+f"(c[0]), "+f"(c[1]), "+f"(c[2]), "+f"(c[3])
        : "r"(a[0]), "r"(a[1]), "r"(a[2]), "r"(a[3]), "r"(b[0]), "r"(b[1]));
}
__device__ __forceinline__ float fsqrt_ap(float x) {
    float r; asm("sqrt.approx.f32 %0, %1;" : "=f"(r) : "f"(x)); return r;
}
__device__ __forceinline__ float fex2_ap(float x) {
    float r; asm("ex2.approx.f32 %0, %1;" : "=f"(r) : "f"(x)); return r;
}

// ---------------- warp-MMA fp16 NT GEMM (single-pass hi x hi) ----------------
// C[r,c] = sum_k A[r,k]*B[c,k]; fp16 operands, fp32 accumulate.
// CTA 128x128, 8 warps (2x4), warp tile 64x32, BK=64, double-buffered cp.async,
// single __syncthreads per chunk. Fused deterministic row partial sums.
// EPI_BIAS (DUAL): z=0/1 two merged projections; z=2 = AUX transpose slice
//   (target fp32 [NTGT][DIM] -> tTh fp16 [DIM][NTGT]), filling idle SM slots.
// EPI_COST: v = ex2(e_r - d*cT) row-prescaled fp16 K + sum(v) partials.
// EPI_ROWS: z=0 = aligned GEMM with fused normalization; z=1 = AUX k_out slice
//   (fp32 K = h2f(Kh)*invrs[r]), overlapping the GEMM's idle slots.
#define EPI_ROWS 0
#define EPI_BIAS 1
#define EPI_COST 2

#define BK 64
#define ROW_BYTES 144                       // 64 halves (128B) + 16B pad
#define TILE_BYTES (128 * ROW_BYTES)        // 18432
#define SMEM_DYN (2 * 2 * TILE_BYTES)       // 73728

template <int EPI, bool DUAL>
__global__ void __launch_bounds__(256, 2) tc_gemm(
    const __half* __restrict__ Ah, const __half* __restrict__ Bh,
    const float* __restrict__ bias,
    const __half* __restrict__ A2, const __half* __restrict__ B2,
    const float* __restrict__ bias2,
    const float* __restrict__ sqa, const float* __restrict__ sqb,
    const float* __restrict__ temp, const float* __restrict__ sbavg,
    float* __restrict__ C,
    __half* __restrict__ Chb, __half* __restrict__ Chb2,
    float* __restrict__ partial, float* __restrict__ partial2,
    const float* __restrict__ auxin, void* __restrict__ auxout,
    int N, int Kdim)
{
    extern __shared__ char dsm[];
    const int tid = threadIdx.x;

    // ---- AUX slice: transpose (proj launch, z==2) ---------------------------
    if (DUAL && blockIdx.z == 2) {
        float* tbuf = (float*)dsm;              // 32x33 tile
        __half* oh = (__half*)auxout;
        const int lx = tid & 31, ly = tid >> 5; // (32,8)
        const int base = (blockIdx.y * 8 + blockIdx.x) * 16;   // 16 tiles/block
        for (int t16 = 0; t16 < 16; t16++) {
            int tile = base + t16;              // 0..4095
            int bx = tile & 31;                 // DIM/32 tiles in x
            int by = tile >> 5;                 // NTGT/32 tiles in y
            int x  = bx * 32 + lx;
            int y0 = by * 32;
#pragma unroll
            for (int i = 0; i < 4; i++)
                tbuf[(ly + i * 8) * 33 + lx] =
                    auxin[(size_t)(y0 + ly + i * 8) * DIM + x];
            __syncthreads();
            int ox  = y0 + lx;
            int oy0 = bx * 32;
#pragma unroll
            for (int i = 0; i < 4; i++) {
                float v = tbuf[lx * 33 + ly + i * 8];
                oh[(size_t)(oy0 + ly + i * 8) * NTGT + ox] = __float2half_rn(v);
            }
            __syncthreads();
        }
        return;
    }

    // ---- AUX slice: fp32 K output (aligned launch, z==1) --------------------
    if (EPI == EPI_ROWS && blockIdx.z == 1) {
        const uint2* Khs = (const uint2*)Ah;    // prescaled fp16 K
        float* Kout = (float*)auxout;
        int bid = blockIdx.y * 8 + blockIdx.x;  // 0..255
        size_t basei = (size_t)bid * 16384;     // uint2 units (4M total / 256)
#pragma unroll 1
        for (int i = 0; i < 64; i++) {
            size_t idx = basei + (size_t)i * 256 + tid;
            int row = (int)(idx >> 10);         // 1024 uint2 per row
            float inv = sqa[row];               // invrs
            uint2 h = Khs[idx];
            float4 v;
            v.x = __half2float(__ushort_as_half((unsigned short)(h.x & 0xffff))) * inv;
            v.y = __half2float(__ushort_as_half((unsigned short)(h.x >> 16))) * inv;
            v.z = __half2float(__ushort_as_half((unsigned short)(h.y & 0xffff))) * inv;
            v.w = __half2float(__ushort_as_half((unsigned short)(h.y >> 16))) * inv;
            ((float4*)Kout)[idx] = v;
        }
        return;
    }

    const uint32_t sm0 = smem_to_u32(dsm);
    const int wid = tid >> 5, lane = tid & 31;
    const int warpRow = wid & 1;            // 2 row-warps (64 rows each)
    const int warpCol = wid >> 1;           // 4 col-warps (32 cols each)
    const int g  = lane >> 2;
    const int qp = lane & 3;
    const int rowBase = blockIdx.y * 128;
    const int colBase = blockIdx.x * 128;

    const __half* Ause = Ah;
    const __half* Buse = Bh;
    const float*  buse = bias;
    __half* chbuse = Chb;
    float*  partuse = partial;
    if (DUAL && blockIdx.z == 1) {
        Ause = A2; Buse = B2; buse = bias2; chbuse = Chb2; partuse = partial2;
    }

    const uint32_t offA = (uint32_t)((warpRow * 64 + (lane & 7) + ((lane >> 3) & 1) * 8) * ROW_BYTES
                                     + ((lane >> 4) & 1) * 16);
    const uint32_t offB = (uint32_t)(((lane & 7) + ((lane >> 4) & 1) * 8) * ROW_BYTES
                                     + ((lane >> 3) & 1) * 16);

    const __half* basep[2] = { Ause + (size_t)rowBase * Kdim, Buse + (size_t)colBase * Kdim };

    float acc[4][4][4];
#pragma unroll
    for (int mf = 0; mf < 4; mf++)
#pragma unroll
        for (int nf = 0; nf < 4; nf++)
#pragma unroll
            for (int e = 0; e < 4; e++) acc[mf][nf][e] = 0.f;

    const int KC = Kdim / BK;

    auto issue = [&](int ch, int buf) {
        uint32_t sbase = sm0 + (uint32_t)buf * (2u * TILE_BYTES);
        int kt = ch * BK;
#pragma unroll
        for (int j = 0; j < 8; j++) {
            int id  = j * 256 + tid;
            int t   = id >> 10;
            int c   = id & 1023;
            int row = c >> 3;
            int seg = c & 7;
            const void* src = basep[t] + (size_t)row * Kdim + kt + seg * 8;
            uint32_t dst = sbase + (uint32_t)t * TILE_BYTES + row * ROW_BYTES + seg * 16;
            cp_async16(dst, src);
        }
        asm volatile("cp.async.commit_group;" ::: "memory");
    };

    issue(0, 0);
#pragma unroll 1
    for (int ch = 0; ch < KC; ch++) {
        int buf = ch & 1;
        asm volatile("cp.async.wait_group 0;" ::: "memory");
        __syncthreads();
        if (ch + 1 < KC) issue(ch + 1, buf ^ 1);

        uint32_t sb = sm0 + (uint32_t)buf * (2u * TILE_BYTES);
#pragma unroll
        for (int ks = 0; ks < 4; ks++) {
            const uint32_t kof = (uint32_t)(ks * 32);
            uint32_t bh[4][2];
#pragma unroll
            for (int p = 0; p < 2; p++) {
                uint32_t nboff = (uint32_t)((warpCol * 32 + p * 16) * ROW_BYTES);
                uint32_t rh[4];
                ldm4(rh, sb + TILE_BYTES + nboff + offB + kof);
                bh[p * 2][0] = rh[0]; bh[p * 2][1] = rh[1];
                bh[p * 2 + 1][0] = rh[2]; bh[p * 2 + 1][1] = rh[3];
            }
#pragma unroll
            for (int mf = 0; mf < 4; mf++) {
                uint32_t mof = (uint32_t)(mf * 16 * ROW_BYTES);
                uint32_t ah[4];
                ldm4(ah, sb + mof + offA + kof);
#pragma unroll
                for (int nf = 0; nf < 4; nf++) mma_f16(acc[mf][nf], ah, bh[nf]);
            }
        }
    }

    // ---- epilogue ------------------------------------------------------------
    const float cT = (EPI == EPI_COST) ? (1.44269504088896340736f / temp[0]) : 0.f;
    const float sbav = (EPI == EPI_COST) ? sbavg[0] : 0.f;
    const int nchunk = N >> 5;
    const int chunkIdx = (colBase >> 5) + warpCol;
#pragma unroll
    for (int mf = 0; mf < 4; mf++) {
#pragma unroll
        for (int half = 0; half < 2; half++) {
            int r = rowBase + warpRow * 64 + mf * 16 + g + half * 8;
            float sa = 0.f, er = 0.f, rowsc = 0.f;
            if (EPI == EPI_COST) {
                sa = sqa[r];
                er = rintf(fsqrt_ap(sa + sbav) * cT);   // row-constant prescale exp
            } else if (EPI == EPI_ROWS) {
                rowsc = sqa[r];                          // invrs[r]
            }
            float rs = 0.f;
#pragma unroll
            for (int nf = 0; nf < 4; nf++) {
                int c0 = colBase + warpCol * 32 + nf * 8 + qp * 2;
                float v0 = acc[mf][nf][half * 2 + 0];
                float v1 = acc[mf][nf][half * 2 + 1];
                if (EPI == EPI_COST) {
                    float d20 = sa + sqb[c0 + 0] - 2.0f * v0;
                    float d21 = sa + sqb[c0 + 1] - 2.0f * v1;
                    v0 = fex2_ap(er - fsqrt_ap(fmaxf(d20, 0.0f)) * cT);
                    v1 = fex2_ap(er - fsqrt_ap(fmaxf(d21, 0.0f)) * cT);
                    unsigned short h0 = __half_as_ushort(__float2half_rn(v0));
                    unsigned short h1 = __half_as_ushort(__float2half_rn(v1));
                    *(uint32_t*)(chbuse + (size_t)r * N + c0) =
                        (uint32_t)h0 | ((uint32_t)h1 << 16);
                    rs += v0 + v1;
                } else if (EPI == EPI_BIAS) {
                    v0 += buse[c0 + 0];
                    v1 += buse[c0 + 1];
                    unsigned short h0 = __half_as_ushort(__float2half_rn(v0));
                    unsigned short h1 = __half_as_ushort(__float2half_rn(v1));
                    *(uint32_t*)(chbuse + (size_t)r * N + c0) =
                        (uint32_t)h0 | ((uint32_t)h1 << 16);
                    rs += v0 * v0 + v1 * v1;
                } else {   // EPI_ROWS
                    *(float2*)(C + (size_t)r * N + c0) =
                        make_float2(v0 * rowsc, v1 * rowsc);
                }
            }
            if (EPI != EPI_ROWS) {
                rs += __shfl_xor_sync(0xffffffffu, rs, 1);
                rs += __shfl_xor_sync(0xffffffffu, rs, 2);
                if (qp == 0) partuse[(size_t)r * nchunk + chunkIdx] = rs;
            }
        }
    }
}

// ---------------- small kernels ---------------------------------------------
#define N4_SRC ((size_t)NSRC * DIM / 4)
#define N4_TGT ((size_t)NTGT * DIM / 4)
#define N4_W   ((size_t)DIM * DIM / 4)
#define N4_ALL (N4_SRC + N4_TGT + 2 * N4_W)
__global__ __launch_bounds__(256) void convert_all(
    const float* __restrict__ src, const float* __restrict__ tgt,
    const float* __restrict__ ws, const float* __restrict__ wt,
    __half* __restrict__ osrc, __half* __restrict__ otgt,
    __half* __restrict__ ows, __half* __restrict__ owt)
{
    size_t i = (size_t)blockIdx.x * 256 + threadIdx.x;
    if (i >= N4_ALL) return;
    const float* in;
    __half* oh;
    size_t j = i;
    if (j < N4_SRC) { in = src; oh = osrc; }
    else if ((j -= N4_SRC) < N4_TGT) { in = tgt; oh = otgt; }
    else if ((j -= N4_TGT) < N4_W) { in = ws; oh = ows; }
    else { j -= N4_W; in = wt; oh = owt; }
    float4 v = ((const float4*)in)[j];
    unsigned short h0 = __half_as_ushort(__float2half_rn(v.x));
    unsigned short h1 = __half_as_ushort(__float2half_rn(v.y));
    unsigned short h2 = __half_as_ushort(__float2half_rn(v.z));
    unsigned short h3 = __half_as_ushort(__float2half_rn(v.w));
    ((uint2*)oh)[j] = make_uint2((uint32_t)h0 | ((uint32_t)h1 << 16),
                                 (uint32_t)h2 | ((uint32_t)h3 << 16));
}

// warp-per-row deterministic reduce (fixed shuffle tree order every run).
__global__ __launch_bounds__(256) void reduce_rows_warp2(
    const float* __restrict__ partA, float* __restrict__ outA,
    const float* __restrict__ partB, float* __restrict__ outB, int nchunk)
{
    int w = (int)((blockIdx.x * blockDim.x + threadIdx.x) >> 5);
    int lane = threadIdx.x & 31;
    const float* p;
    float* o;
    int r = w;
    if (w < NSRC) { p = partA; o = outA; }
    else          { p = partB; o = outB; r = w - NSRC; }
    const float* pr = p + (size_t)r * nchunk;
    float s = 0.f;
    for (int i = lane; i < nchunk; i += 32) s += pr[i];
#pragma unroll
    for (int st = 16; st > 0; st >>= 1) s += __shfl_xor_sync(0xffffffffu, s, st);
    if (lane == 0) o[r] = s;
}

// deterministic mean of a vector (1 block)
__global__ __launch_bounds__(256) void avg_vec(
    const float* __restrict__ in, float* __restrict__ out, int n)
{
    __shared__ float red[256];
    float s = 0.f;
    for (int i = threadIdx.x; i < n; i += 256) s += in[i];
    red[threadIdx.x] = s;
    __syncthreads();
#pragma unroll
    for (int st = 128; st > 0; st >>= 1) {
        if (threadIdx.x < st) red[threadIdx.x] += red[threadIdx.x + st];
        __syncthreads();
    }
    if (threadIdx.x == 0) out[0] = red[0] / (float)n;
}

// warp-per-row: reduce 128 rowsum partials -> write 1/rowsum (deterministic)
__global__ __launch_bounds__(256) void reduce_inv(
    const float* __restrict__ part, float* __restrict__ out, int nchunk)
{
    int w = (int)((blockIdx.x * blockDim.x + threadIdx.x) >> 5);
    int lane = threadIdx.x & 31;
    const float* pr = part + (size_t)w * nchunk;
    float s = 0.f;
    for (int i = lane; i < nchunk; i += 32) s += pr[i];
#pragma unroll
    for (int st = 16; st > 0; st >>= 1) s += __shfl_xor_sync(0xffffffffu, s, st);
    if (lane == 0) out[w] = 1.0f / s;
}

// ---------------- launch -----------------------------------------------------
extern "C" void kernel_launch(void* const* d_in, const int* in_sizes, int n_in,
                              void* d_out, int out_size)
{
    const float* source = (const float*)d_in[0];
    const float* target = (const float*)d_in[1];
    const float* W_src  = (const float*)d_in[2];
    const float* b_src  = (const float*)d_in[3];
    const float* W_tgt  = (const float*)d_in[4];
    const float* b_tgt  = (const float*)d_in[5];
    const float* temp   = (const float*)d_in[6];

    float* aligned = (float*)d_out;                       // [NSRC, DIM]
    float* Kout    = (float*)d_out + (size_t)NSRC * DIM;  // [NSRC, NTGT]

    float *sqs, *sqt, *sbavg, *invrs, *sqps, *sqpt, *krsp;
    __half *srch, *tgth, *Wsh, *Wth, *sph, *tph, *tTh, *Kh;
    cudaGetSymbolAddress((void**)&sqs,   g_sqs);
    cudaGetSymbolAddress((void**)&sqt,   g_sqt);
    cudaGetSymbolAddress((void**)&sbavg, g_sbavg);
    cudaGetSymbolAddress((void**)&invrs, g_invrs);
    cudaGetSymbolAddress((void**)&sqps,  g_sqpart_s);
    cudaGetSymbolAddress((void**)&sqpt,  g_sqpart_t);
    cudaGetSymbolAddress((void**)&krsp,  g_krspart);
    cudaGetSymbolAddress((void**)&srch,  g_srch);
    cudaGetSymbolAddress((void**)&tgth,  g_tgth);
    cudaGetSymbolAddress((void**)&Wsh,   g_Wsh);
    cudaGetSymbolAddress((void**)&Wth,   g_Wth);
    cudaGetSymbolAddress((void**)&sph,   g_sph);
    cudaGetSymbolAddress((void**)&tph,   g_tph);
    cudaGetSymbolAddress((void**)&tTh,   g_tTh);
    cudaGetSymbolAddress((void**)&Kh,    g_Kh);

    cudaFuncSetAttribute((const void*)tc_gemm<EPI_BIAS, true>,  cudaFuncAttributeMaxDynamicSharedMemorySize, SMEM_DYN);
    cudaFuncSetAttribute((const void*)tc_gemm<EPI_COST, false>, cudaFuncAttributeMaxDynamicSharedMemorySize, SMEM_DYN);
    cudaFuncSetAttribute((const void*)tc_gemm<EPI_ROWS, false>, cudaFuncAttributeMaxDynamicSharedMemorySize, SMEM_DYN);

    // 1) convert all inputs to fp16 (single launch)
    convert_all<<<(int)((N4_ALL + 255) / 256), 256>>>(
        source, target, W_src, W_tgt, srch, tgth, Wsh, Wth);

    // 2) projections (z=0,1) + transpose slice (z=2) in ONE launch
    tc_gemm<EPI_BIAS, true><<<dim3(DIM / 128, NSRC / 128, 3), 256, SMEM_DYN>>>(
        srch, Wsh, b_src, tgth, Wth, b_tgt,
        nullptr, nullptr, nullptr, nullptr,
        nullptr, sph, tph, sqps, sqpt,
        target, tTh, DIM, DIM);

    // 3) reduce sq-norm partials; mean of sqt for the row prescale
    reduce_rows_warp2<<<(NSRC + NTGT) * 32 / 256, 256>>>(sqps, sqs, sqpt, sqt, DIM / 32);
    avg_vec<<<1, 256>>>(sqt, sbavg, NTGT);

    // 4) cost GEMM: writes row-prescaled fp16 K + scaled rowsum partials
    tc_gemm<EPI_COST, false><<<dim3(NTGT / 128, NSRC / 128), 256, SMEM_DYN>>>(
        sph, tph, nullptr, nullptr, nullptr, nullptr,
        sqs, sqt, temp, sbavg,
        nullptr, Kh, nullptr, krsp, nullptr,
        nullptr, nullptr, NTGT, DIM);

    // 5) invrs[r] = 1 / scaled rowsum
    reduce_inv<<<NSRC * 32 / 256, 256>>>(krsp, invrs, NTGT / 32);

    // 6) aligned GEMM (z=0) + fp32 K output slice (z=1) in ONE launch
    tc_gemm<EPI_ROWS, false><<<dim3(DIM / 128, NSRC / 128, 2), 256, SMEM_DYN>>>(
        Kh, tTh, nullptr, nullptr, nullptr, nullptr,
        invrs, nullptr, nullptr, nullptr,
        aligned, nullptr, nullptr, nullptr, nullptr,
        nullptr, Kout, DIM, NTGT);
}